// round 1
// baseline (speedup 1.0000x reference)
#include <cuda_runtime.h>
#include <math.h>

#define BTOK 4096
#define CDIM 1024
#define HDIM 4096
#define NEXP 8
#define ERWKV 6
#define MAXS (2*BTOK)

// output layout (f32, tuple flattened in order)
#define OUT_VF   (BTOK*CDIM)
#define OUT_WIN  (2*BTOK*CDIM)
#define OUT_COST (OUT_WIN + 2*BTOK)
#define OUT_DIFF (OUT_COST + BTOK)
#define OUT_AFF  (OUT_DIFF + BTOK)

// ------------------------- scratch (static device memory) -------------------------
__device__ float g_xln[BTOK*CDIM];
__device__ float g_x2 [BTOK*CDIM];          // x + att_out (residual stream)
__device__ float g_h  [BTOK*CDIM];          // ln2(x2)
__device__ float g_rs [BTOK*CDIM];          // rwkv_state
__device__ float g_z  [BTOK*CDIM];          // h + prefix
__device__ float g_mid[(size_t)(MAXS+128)*HDIM]; // expert hidden (padded 128 rows)
__device__ float g_slot0[BTOK*CDIM];        // rank-0 expert output per token
__device__ float g_slot1[BTOK*CDIM];        // rank-1 expert output per token
__device__ int   g_win[2*BTOK];
__device__ float g_wt [2*BTOK];
__device__ int   g_cnt[NEXP];
__device__ int   g_off[NEXP+1];
__device__ int   g_cur[NEXP];
__device__ int   g_tok[MAXS];
__device__ float g_gate[MAXS];
__device__ int   g_rank[MAXS];
__device__ int   g_toff1[NEXP+1];
__device__ int   g_toff2[NEXP+1];
__device__ unsigned int g_ctr[2];

__device__ __forceinline__ float gelu_tanh(float x){
    float x3 = x*x*x;
    return 0.5f*x*(1.0f + tanhf(0.7978845608028654f*(x + 0.044715f*x3)));
}

// ------------------------- LN1 -------------------------
__global__ void k_ln1(const float* __restrict__ x, const float* __restrict__ g1,
                      const float* __restrict__ b1)
{
    const int t = blockIdx.x;
    const int tid = threadIdx.x;
    if (t == 0 && tid < NEXP) g_cnt[tid] = 0;   // reset routing counts each replay
    __shared__ float red[256];
    const float* xr = x + (size_t)t*CDIM;
    float v[4]; float s = 0.f;
#pragma unroll
    for (int q=0;q<4;q++){ v[q]=xr[tid+256*q]; s+=v[q]; }
    red[tid]=s; __syncthreads();
    for(int st=128;st>0;st>>=1){ if(tid<st) red[tid]+=red[tid+st]; __syncthreads(); }
    const float m = red[0]*(1.0f/CDIM);
    __syncthreads();
    float s2=0.f;
#pragma unroll
    for(int q=0;q<4;q++){ float d=v[q]-m; s2+=d*d; }
    red[tid]=s2; __syncthreads();
    for(int st=128;st>0;st>>=1){ if(tid<st) red[tid]+=red[tid+st]; __syncthreads(); }
    const float rstd = rsqrtf(red[0]*(1.0f/CDIM)+1e-5f);
#pragma unroll
    for(int q=0;q<4;q++){ int i=tid+256*q; g_xln[(size_t)t*CDIM+i]=(v[q]-m)*rstd*g1[i]+b1[i]; }
}

// ------------------------- LN2 + router -------------------------
__global__ void k_post1(const float* __restrict__ g2, const float* __restrict__ b2,
                        const float* __restrict__ w_conf, const float* __restrict__ w_diff,
                        const float* __restrict__ W_aff, const float* __restrict__ cap,
                        float* __restrict__ out)
{
    const int t = blockIdx.x;
    const int tid = threadIdx.x;
    __shared__ float red[256];
    __shared__ float sh[CDIM];
    __shared__ float sconf[NEXP], saff[NEXP];
    __shared__ float sdiff;
    const float* xr = g_x2 + (size_t)t*CDIM;
    float v[4]; float s=0.f;
#pragma unroll
    for(int q=0;q<4;q++){ v[q]=xr[tid+256*q]; s+=v[q]; }
    red[tid]=s; __syncthreads();
    for(int st=128;st>0;st>>=1){ if(tid<st) red[tid]+=red[tid+st]; __syncthreads(); }
    const float m=red[0]*(1.0f/CDIM);
    __syncthreads();
    float s2=0.f;
#pragma unroll
    for(int q=0;q<4;q++){ float d=v[q]-m; s2+=d*d; }
    red[tid]=s2; __syncthreads();
    for(int st=128;st>0;st>>=1){ if(tid<st) red[tid]+=red[tid+st]; __syncthreads(); }
    const float rstd=rsqrtf(red[0]*(1.0f/CDIM)+1e-5f);
#pragma unroll
    for(int q=0;q<4;q++){
        int i=tid+256*q;
        float hv=(v[q]-m)*rstd*g2[i]+b2[i];
        sh[i]=hv; g_h[(size_t)t*CDIM+i]=hv;
    }
    __syncthreads();
    const int w=tid>>5, lane=tid&31;
    float cd=0.f, ad=0.f, dd=0.f;
    for(int i=lane;i<CDIM;i+=32){
        float hv=sh[i];
        cd = fmaf(hv, w_conf[w*CDIM+i], cd);
        ad = fmaf(hv, W_aff[i*NEXP+w], ad);
        if(w==0) dd = fmaf(hv, w_diff[i], dd);
    }
#pragma unroll
    for(int o=16;o>0;o>>=1){
        cd += __shfl_down_sync(0xffffffffu, cd, o);
        ad += __shfl_down_sync(0xffffffffu, ad, o);
        dd += __shfl_down_sync(0xffffffffu, dd, o);
    }
    if(lane==0){ sconf[w]=cd; saff[w]=ad; if(w==0) sdiff=dd; }
    __syncthreads();
    if(tid<NEXP) out[OUT_AFF + t*NEXP + tid] = saff[tid];
    if(tid==0){
        // softplus (jax: max(x,0)+log1p(exp(-|x|)))
        float diff = fmaxf(sdiff,0.f) + log1pf(expf(-fabsf(sdiff)));
        float b0=-INFINITY, b1v=-INFINITY; int e0=0,e1=0;
#pragma unroll
        for(int e=0;e<NEXP;e++){
            float conf = 1.0f/(1.0f+expf(-sconf[e]));
            float bid = fmaf(conf, cap[e], saff[e]);
            if(bid>b0){ b1v=b0;e1=e0;b0=bid;e0=e; }
            else if(bid>b1v){ b1v=bid;e1=e; }
        }
        float ex = expf(b1v-b0);           // <= 1, stable
        float w0 = 1.0f/(1.0f+ex);
        float w1 = ex/(1.0f+ex);
        out[OUT_WIN + 2*t]   = (float)e0;
        out[OUT_WIN + 2*t+1] = (float)e1;
        out[OUT_COST + t] = (b0*w0 + b1v*w1)*diff;
        out[OUT_DIFF + t] = diff;
        g_win[2*t]=e0; g_win[2*t+1]=e1;
        g_wt[2*t]=w0;  g_wt[2*t+1]=w1;
        atomicAdd(&g_cnt[e0],1);
        atomicAdd(&g_cnt[e1],1);
    }
}

// ------------------------- routing setup/fill -------------------------
__global__ void k_route_setup(){
    if(threadIdx.x==0){
        int o=0;
        for(int e=0;e<NEXP;e++){ g_off[e]=o; o+=g_cnt[e]; }
        g_off[NEXP]=o;
        int t1=0,t2=0;
        for(int e=0;e<NEXP;e++){
            g_cur[e]=g_off[e];
            int mt=(g_cnt[e]+127)>>7;
            int nt1=(e<ERWKV)?(HDIM>>7):(CDIM>>7);
            g_toff1[e]=t1; t1+=mt*nt1;
            g_toff2[e]=t2; t2+=mt*(CDIM>>7);
        }
        g_toff1[NEXP]=t1; g_toff2[NEXP]=t2;
        g_ctr[0]=0u; g_ctr[1]=0u;
    }
}

__global__ void k_route_fill(){
    int t = blockIdx.x*blockDim.x + threadIdx.x;
    if(t<BTOK){
#pragma unroll
        for(int r=0;r<2;r++){
            int e=g_win[2*t+r];
            int p=atomicAdd(&g_cur[e],1);
            g_tok[p]=t; g_gate[p]=g_wt[2*t+r]; g_rank[p]=r;
        }
    }
}

// ------------------------- dense SGEMM core (128x128x8, 8x8/thread) -------------------------
__device__ __forceinline__ void gemm128_dense(const float* __restrict__ A,
    const float* __restrict__ B, const float* __restrict__ D,
    float* __restrict__ Cc, int K, int N)
{
    __shared__ float As[8][128];
    __shared__ float Bs[8][128];
    const int tid=threadIdx.x;
    const int tx=tid&15, ty=tid>>4;
    const int mb=blockIdx.y*128, nb=blockIdx.x*128;
    const int ar=tid>>1, akq=(tid&1)*4;
    const int bkr=tid>>5, bn=(tid&31)*4;
    float acc[8][8];
#pragma unroll
    for(int i=0;i<8;i++)
#pragma unroll
        for(int j=0;j<8;j++) acc[i][j]=0.f;
    const float* Ap=A+(size_t)(mb+ar)*K+akq;
    const float* Bp=B+(size_t)bkr*N+nb+bn;
    for(int k0=0;k0<K;k0+=8){
        float4 av=*(const float4*)(Ap+k0);
        float4 bv=*(const float4*)(Bp+(size_t)k0*N);
        As[akq+0][ar]=av.x; As[akq+1][ar]=av.y; As[akq+2][ar]=av.z; As[akq+3][ar]=av.w;
        *(float4*)(&Bs[bkr][bn])=bv;
        __syncthreads();
#pragma unroll
        for(int kk=0;kk<8;kk++){
            float a[8],b[8];
#pragma unroll
            for(int i=0;i<8;i++) a[i]=As[kk][ty*8+i];
#pragma unroll
            for(int j=0;j<8;j++) b[j]=Bs[kk][tx*8+j];
#pragma unroll
            for(int i=0;i<8;i++)
#pragma unroll
                for(int j=0;j<8;j++) acc[i][j]=fmaf(a[i],b[j],acc[i][j]);
        }
        __syncthreads();
    }
#pragma unroll
    for(int i=0;i<8;i++){
        const int r=mb+ty*8+i;
#pragma unroll
        for(int j=0;j<8;j++){
            const int c=nb+tx*8+j;
            float vv=acc[i][j];
            if(D) vv+=D[(size_t)r*N+c];
            Cc[(size_t)r*N+c]=vv;
        }
    }
}

__global__ __launch_bounds__(256,2) void k_gemm_att(const float* __restrict__ x, const float* __restrict__ Wa){
    gemm128_dense(g_xln, Wa, x, g_x2, CDIM, CDIM);              // x2 = x + xln@Wa
}
__global__ __launch_bounds__(256,2) void k_gemm_rs(const float* __restrict__ Ws){
    gemm128_dense(g_xln, Ws, nullptr, g_rs, CDIM, CDIM);        // rs = xln@Ws
}
__global__ __launch_bounds__(256,2) void k_gemm_z1(const float* __restrict__ Wbh){
    gemm128_dense(g_h, Wbh, g_h, g_z, CDIM, CDIM);              // z = h + h@Wbh
}
__global__ __launch_bounds__(256,2) void k_gemm_z2(const float* __restrict__ Wbs){
    gemm128_dense(g_rs, Wbs, g_z, g_z, CDIM, CDIM);             // z += rs@Wbs
}

// ------------------------- routed grouped GEMM (persistent, atomic tiles) -------------------------
__global__ __launch_bounds__(256,2)
void k_gemm_routed(int stage, const float* __restrict__ Wk, const float* __restrict__ Wv,
                   const float* __restrict__ W1, const float* __restrict__ W2)
{
    __shared__ float As[8][128];
    __shared__ float Bs[8][128];
    __shared__ int s_idx;
    const int tid=threadIdx.x;
    const int tx=tid&15, ty=tid>>4;
    const int ar=tid>>1, akq=(tid&1)*4;
    const int bkr=tid>>5, bn=(tid&31)*4;
    const int* toff = (stage==0)? g_toff1 : g_toff2;
    const int total = toff[NEXP];
    for(;;){
        if(tid==0) s_idx=(int)atomicAdd(&g_ctr[stage],1u);
        __syncthreads();
        const int idx=s_idx;
        if(idx>=total) return;
        int e=0;
#pragma unroll
        for(int q=1;q<NEXP;q++) if(idx>=toff[q]) e=q;
        const int local=idx-toff[e];
        const int base=g_off[e];
        const int ne=g_off[e+1]-base;
        const bool rwkv=(e<ERWKV);
        int Nn,K;
        const float* Bsrc;
        if(stage==0){
            Nn = rwkv? HDIM:CDIM; K=CDIM;
            Bsrc = rwkv? (Wk+(size_t)e*CDIM*HDIM) : (W1+(size_t)(e-ERWKV)*CDIM*CDIM);
        } else {
            Nn=CDIM; K = rwkv? HDIM:CDIM;
            Bsrc = rwkv? (Wv+(size_t)e*HDIM*CDIM) : (W2+(size_t)(e-ERWKV)*CDIM*CDIM);
        }
        const int ntl = Nn>>7;
        const int mb=(local/ntl)*128;
        const int nb=(local%ntl)*128;
        float acc[8][8];
#pragma unroll
        for(int i=0;i<8;i++)
#pragma unroll
            for(int j=0;j<8;j++) acc[i][j]=0.f;
        const float* Bp=Bsrc+(size_t)bkr*Nn+nb+bn;
        if(stage==0){
            const int mrow=mb+ar;
            const bool valid = (mrow<ne);
            const int tokr = valid? g_tok[base+mrow] : 0;
            const float* Asrc = rwkv? g_h : g_z;
            const float* Ap = Asrc + (size_t)tokr*CDIM + akq;
            for(int k0=0;k0<K;k0+=8){
                float4 av = valid? *(const float4*)(Ap+k0) : make_float4(0.f,0.f,0.f,0.f);
                float4 bv = *(const float4*)(Bp+(size_t)k0*Nn);
                As[akq+0][ar]=av.x; As[akq+1][ar]=av.y; As[akq+2][ar]=av.z; As[akq+3][ar]=av.w;
                *(float4*)(&Bs[bkr][bn])=bv;
                __syncthreads();
#pragma unroll
                for(int kk=0;kk<8;kk++){
                    float a[8],b[8];
#pragma unroll
                    for(int i=0;i<8;i++) a[i]=As[kk][ty*8+i];
#pragma unroll
                    for(int j=0;j<8;j++) b[j]=Bs[kk][tx*8+j];
#pragma unroll
                    for(int i=0;i<8;i++)
#pragma unroll
                        for(int j=0;j<8;j++) acc[i][j]=fmaf(a[i],b[j],acc[i][j]);
                }
                __syncthreads();
            }
#pragma unroll
            for(int i=0;i<8;i++){
                const int mr2=mb+ty*8+i;
                if(mr2<ne){
                    float* dst=g_mid+(size_t)(base+mr2)*HDIM+nb+tx*8;
#pragma unroll
                    for(int j=0;j<8;j++){
                        float vv=acc[i][j];
                        if(rwkv){ vv=fmaxf(vv,0.f); vv=vv*vv; }
                        else      vv=gelu_tanh(vv);
                        dst[j]=vv;
                    }
                }
            }
        } else {
            const float* Ap=g_mid+(size_t)(base+mb+ar)*HDIM+akq;
            for(int k0=0;k0<K;k0+=8){
                float4 av=*(const float4*)(Ap+k0);
                float4 bv=*(const float4*)(Bp+(size_t)k0*Nn);
                As[akq+0][ar]=av.x; As[akq+1][ar]=av.y; As[akq+2][ar]=av.z; As[akq+3][ar]=av.w;
                *(float4*)(&Bs[bkr][bn])=bv;
                __syncthreads();
#pragma unroll
                for(int kk=0;kk<8;kk++){
                    float a[8],b[8];
#pragma unroll
                    for(int i=0;i<8;i++) a[i]=As[kk][ty*8+i];
#pragma unroll
                    for(int j=0;j<8;j++) b[j]=Bs[kk][tx*8+j];
#pragma unroll
                    for(int i=0;i<8;i++)
#pragma unroll
                        for(int j=0;j<8;j++) acc[i][j]=fmaf(a[i],b[j],acc[i][j]);
                }
                __syncthreads();
            }
#pragma unroll
            for(int i=0;i<8;i++){
                const int mr2=mb+ty*8+i;
                if(mr2<ne){
                    const int slot=base+mr2;
                    const int tt=g_tok[slot];
                    const float gt=g_gate[slot];
                    float* dst = (g_rank[slot]==0? g_slot0 : g_slot1) + (size_t)tt*CDIM + nb + tx*8;
#pragma unroll
                    for(int j=0;j<8;j++) dst[j]=gt*acc[i][j];
                }
            }
        }
    }
}

// ------------------------- epilogue: combine + passthrough -------------------------
__global__ void k_final(const float* __restrict__ vf, float* __restrict__ out){
    const int i=blockIdx.x*256+threadIdx.x;
    out[i]        = g_x2[i] + g_slot0[i] + g_slot1[i];
    out[OUT_VF+i] = vf[i];
}

// ------------------------- launch -------------------------
extern "C" void kernel_launch(void* const* d_in, const int* in_sizes, int n_in,
                              void* d_out, int out_size)
{
    const float* x     =(const float*)d_in[0];
    const float* vf    =(const float*)d_in[1];
    const float* cap   =(const float*)d_in[2];
    const float* ln1g  =(const float*)d_in[3];
    const float* ln1b  =(const float*)d_in[4];
    const float* ln2g  =(const float*)d_in[5];
    const float* ln2b  =(const float*)d_in[6];
    const float* Wa    =(const float*)d_in[7];
    const float* Ws    =(const float*)d_in[8];
    const float* wconf =(const float*)d_in[9];
    const float* wdiff =(const float*)d_in[10];
    const float* Waff  =(const float*)d_in[11];
    const float* Wbh   =(const float*)d_in[12];
    const float* Wbs   =(const float*)d_in[13];
    const float* Wk    =(const float*)d_in[14];
    const float* Wv    =(const float*)d_in[15];
    const float* W1    =(const float*)d_in[16];
    const float* W2    =(const float*)d_in[17];
    float* out=(float*)d_out;

    k_ln1<<<BTOK,256>>>(x,ln1g,ln1b);
    dim3 gd(CDIM/128, BTOK/128);
    k_gemm_att<<<gd,256>>>(x,Wa);
    k_gemm_rs <<<gd,256>>>(Ws);
    k_post1<<<BTOK,256>>>(ln2g,ln2b,wconf,wdiff,Waff,cap,out);
    k_route_setup<<<1,32>>>();
    k_route_fill<<<(BTOK+255)/256,256>>>();
    k_gemm_z1<<<gd,256>>>(Wbh);
    k_gemm_z2<<<gd,256>>>(Wbs);
    k_gemm_routed<<<304,256>>>(0,Wk,Wv,W1,W2);
    k_gemm_routed<<<304,256>>>(1,Wk,Wv,W1,W2);
    k_final<<<BTOK*CDIM/256,256>>>(vf,out);
}

// round 2
// speedup vs baseline: 1.0002x; 1.0002x over previous
#include <cuda_runtime.h>
#include <math.h>

#define BTOK 4096
#define CDIM 1024
#define HDIM 4096
#define NEXP 8
#define ERWKV 6
#define MAXS (2*BTOK)

// output layout (f32, tuple flattened in order)
#define OUT_VF   (BTOK*CDIM)
#define OUT_WIN  (2*BTOK*CDIM)
#define OUT_COST (OUT_WIN + 2*BTOK)
#define OUT_DIFF (OUT_COST + BTOK)
#define OUT_AFF  (OUT_DIFF + BTOK)

// ------------------------- scratch (static device memory) -------------------------
__device__ float g_xln[BTOK*CDIM];
__device__ float g_x2 [BTOK*CDIM];          // x + att_out (residual stream)
__device__ float g_h  [BTOK*CDIM];          // ln2(x2)
__device__ float g_rs [BTOK*CDIM];          // rwkv_state
__device__ float g_z  [BTOK*CDIM];          // h + prefix
__device__ float g_mid[(size_t)(MAXS+128)*HDIM]; // expert hidden (padded 128 rows)
__device__ float g_slot0[BTOK*CDIM];        // rank-0 expert output per token
__device__ float g_slot1[BTOK*CDIM];        // rank-1 expert output per token
__device__ int   g_win[2*BTOK];
__device__ float g_wt [2*BTOK];
__device__ int   g_cnt[NEXP];
__device__ int   g_off[NEXP+1];
__device__ int   g_cur[NEXP];
__device__ int   g_tok[MAXS];
__device__ float g_gate[MAXS];
__device__ int   g_rank[MAXS];
__device__ int   g_toff1[NEXP+1];
__device__ int   g_toff2[NEXP+1];
__device__ unsigned int g_ctr[2];

__device__ __forceinline__ float gelu_tanh(float x){
    float x3 = x*x*x;
    return 0.5f*x*(1.0f + tanhf(0.7978845608028654f*(x + 0.044715f*x3)));
}

// ------------------------- LN1 -------------------------
__global__ void k_ln1(const float* __restrict__ x, const float* __restrict__ g1,
                      const float* __restrict__ b1)
{
    const int t = blockIdx.x;
    const int tid = threadIdx.x;
    if (t == 0 && tid < NEXP) g_cnt[tid] = 0;   // reset routing counts each replay
    __shared__ float red[256];
    const float* xr = x + (size_t)t*CDIM;
    float v[4]; float s = 0.f;
#pragma unroll
    for (int q=0;q<4;q++){ v[q]=xr[tid+256*q]; s+=v[q]; }
    red[tid]=s; __syncthreads();
    for(int st=128;st>0;st>>=1){ if(tid<st) red[tid]+=red[tid+st]; __syncthreads(); }
    const float m = red[0]*(1.0f/CDIM);
    __syncthreads();
    float s2=0.f;
#pragma unroll
    for(int q=0;q<4;q++){ float d=v[q]-m; s2+=d*d; }
    red[tid]=s2; __syncthreads();
    for(int st=128;st>0;st>>=1){ if(tid<st) red[tid]+=red[tid+st]; __syncthreads(); }
    const float rstd = rsqrtf(red[0]*(1.0f/CDIM)+1e-5f);
#pragma unroll
    for(int q=0;q<4;q++){ int i=tid+256*q; g_xln[(size_t)t*CDIM+i]=(v[q]-m)*rstd*g1[i]+b1[i]; }
}

// ------------------------- LN2 + router -------------------------
__global__ void k_post1(const float* __restrict__ g2, const float* __restrict__ b2,
                        const float* __restrict__ w_conf, const float* __restrict__ w_diff,
                        const float* __restrict__ W_aff, const float* __restrict__ cap,
                        float* __restrict__ out)
{
    const int t = blockIdx.x;
    const int tid = threadIdx.x;
    __shared__ float red[256];
    __shared__ float sh[CDIM];
    __shared__ float sconf[NEXP], saff[NEXP];
    __shared__ float sdiff;
    const float* xr = g_x2 + (size_t)t*CDIM;
    float v[4]; float s=0.f;
#pragma unroll
    for(int q=0;q<4;q++){ v[q]=xr[tid+256*q]; s+=v[q]; }
    red[tid]=s; __syncthreads();
    for(int st=128;st>0;st>>=1){ if(tid<st) red[tid]+=red[tid+st]; __syncthreads(); }
    const float m=red[0]*(1.0f/CDIM);
    __syncthreads();
    float s2=0.f;
#pragma unroll
    for(int q=0;q<4;q++){ float d=v[q]-m; s2+=d*d; }
    red[tid]=s2; __syncthreads();
    for(int st=128;st>0;st>>=1){ if(tid<st) red[tid]+=red[tid+st]; __syncthreads(); }
    const float rstd=rsqrtf(red[0]*(1.0f/CDIM)+1e-5f);
#pragma unroll
    for(int q=0;q<4;q++){
        int i=tid+256*q;
        float hv=(v[q]-m)*rstd*g2[i]+b2[i];
        sh[i]=hv; g_h[(size_t)t*CDIM+i]=hv;
    }
    __syncthreads();
    const int w=tid>>5, lane=tid&31;
    float cd=0.f, ad=0.f, dd=0.f;
    for(int i=lane;i<CDIM;i+=32){
        float hv=sh[i];
        cd = fmaf(hv, w_conf[w*CDIM+i], cd);
        ad = fmaf(hv, W_aff[i*NEXP+w], ad);
        if(w==0) dd = fmaf(hv, w_diff[i], dd);
    }
#pragma unroll
    for(int o=16;o>0;o>>=1){
        cd += __shfl_down_sync(0xffffffffu, cd, o);
        ad += __shfl_down_sync(0xffffffffu, ad, o);
        dd += __shfl_down_sync(0xffffffffu, dd, o);
    }
    if(lane==0){ sconf[w]=cd; saff[w]=ad; if(w==0) sdiff=dd; }
    __syncthreads();
    if(tid<NEXP) out[OUT_AFF + t*NEXP + tid] = saff[tid];
    if(tid==0){
        // softplus (jax: max(x,0)+log1p(exp(-|x|)))
        float diff = fmaxf(sdiff,0.f) + log1pf(expf(-fabsf(sdiff)));
        float b0=-INFINITY, b1v=-INFINITY; int e0=0,e1=0;
#pragma unroll
        for(int e=0;e<NEXP;e++){
            float conf = 1.0f/(1.0f+expf(-sconf[e]));
            float bid = fmaf(conf, cap[e], saff[e]);
            if(bid>b0){ b1v=b0;e1=e0;b0=bid;e0=e; }
            else if(bid>b1v){ b1v=bid;e1=e; }
        }
        float ex = expf(b1v-b0);           // <= 1, stable
        float w0 = 1.0f/(1.0f+ex);
        float w1 = ex/(1.0f+ex);
        out[OUT_WIN + 2*t]   = (float)e0;
        out[OUT_WIN + 2*t+1] = (float)e1;
        out[OUT_COST + t] = (b0*w0 + b1v*w1)*diff;
        out[OUT_DIFF + t] = diff;
        g_win[2*t]=e0; g_win[2*t+1]=e1;
        g_wt[2*t]=w0;  g_wt[2*t+1]=w1;
        atomicAdd(&g_cnt[e0],1);
        atomicAdd(&g_cnt[e1],1);
    }
}

// ------------------------- routing setup/fill -------------------------
__global__ void k_route_setup(){
    if(threadIdx.x==0){
        int o=0;
        for(int e=0;e<NEXP;e++){ g_off[e]=o; o+=g_cnt[e]; }
        g_off[NEXP]=o;
        int t1=0,t2=0;
        for(int e=0;e<NEXP;e++){
            g_cur[e]=g_off[e];
            int mt=(g_cnt[e]+127)>>7;
            int nt1=(e<ERWKV)?(HDIM>>7):(CDIM>>7);
            g_toff1[e]=t1; t1+=mt*nt1;
            g_toff2[e]=t2; t2+=mt*(CDIM>>7);
        }
        g_toff1[NEXP]=t1; g_toff2[NEXP]=t2;
        g_ctr[0]=0u; g_ctr[1]=0u;
    }
}

__global__ void k_route_fill(){
    int t = blockIdx.x*blockDim.x + threadIdx.x;
    if(t<BTOK){
#pragma unroll
        for(int r=0;r<2;r++){
            int e=g_win[2*t+r];
            int p=atomicAdd(&g_cur[e],1);
            g_tok[p]=t; g_gate[p]=g_wt[2*t+r]; g_rank[p]=r;
        }
    }
}

// ------------------------- dense SGEMM core (128x128x8, 8x8/thread) -------------------------
__device__ __forceinline__ void gemm128_dense(const float* __restrict__ A,
    const float* __restrict__ B, const float* __restrict__ D,
    float* __restrict__ Cc, int K, int N)
{
    __shared__ float As[8][128];
    __shared__ float Bs[8][128];
    const int tid=threadIdx.x;
    const int tx=tid&15, ty=tid>>4;
    const int mb=blockIdx.y*128, nb=blockIdx.x*128;
    const int ar=tid>>1, akq=(tid&1)*4;
    const int bkr=tid>>5, bn=(tid&31)*4;
    float acc[8][8];
#pragma unroll
    for(int i=0;i<8;i++)
#pragma unroll
        for(int j=0;j<8;j++) acc[i][j]=0.f;
    const float* Ap=A+(size_t)(mb+ar)*K+akq;
    const float* Bp=B+(size_t)bkr*N+nb+bn;
    for(int k0=0;k0<K;k0+=8){
        float4 av=*(const float4*)(Ap+k0);
        float4 bv=*(const float4*)(Bp+(size_t)k0*N);
        As[akq+0][ar]=av.x; As[akq+1][ar]=av.y; As[akq+2][ar]=av.z; As[akq+3][ar]=av.w;
        *(float4*)(&Bs[bkr][bn])=bv;
        __syncthreads();
#pragma unroll
        for(int kk=0;kk<8;kk++){
            float a[8],b[8];
#pragma unroll
            for(int i=0;i<8;i++) a[i]=As[kk][ty*8+i];
#pragma unroll
            for(int j=0;j<8;j++) b[j]=Bs[kk][tx*8+j];
#pragma unroll
            for(int i=0;i<8;i++)
#pragma unroll
                for(int j=0;j<8;j++) acc[i][j]=fmaf(a[i],b[j],acc[i][j]);
        }
        __syncthreads();
    }
#pragma unroll
    for(int i=0;i<8;i++){
        const int r=mb+ty*8+i;
#pragma unroll
        for(int j=0;j<8;j++){
            const int c=nb+tx*8+j;
            float vv=acc[i][j];
            if(D) vv+=D[(size_t)r*N+c];
            Cc[(size_t)r*N+c]=vv;
        }
    }
}

__global__ __launch_bounds__(256,2) void k_gemm_att(const float* __restrict__ x, const float* __restrict__ Wa){
    gemm128_dense(g_xln, Wa, x, g_x2, CDIM, CDIM);              // x2 = x + xln@Wa
}
__global__ __launch_bounds__(256,2) void k_gemm_rs(const float* __restrict__ Ws){
    gemm128_dense(g_xln, Ws, nullptr, g_rs, CDIM, CDIM);        // rs = xln@Ws
}
__global__ __launch_bounds__(256,2) void k_gemm_z1(const float* __restrict__ Wbh){
    gemm128_dense(g_h, Wbh, g_h, g_z, CDIM, CDIM);              // z = h + h@Wbh
}
__global__ __launch_bounds__(256,2) void k_gemm_z2(const float* __restrict__ Wbs){
    gemm128_dense(g_rs, Wbs, g_z, g_z, CDIM, CDIM);             // z += rs@Wbs
}

// ------------------------- routed grouped GEMM (persistent, atomic tiles) -------------------------
__global__ __launch_bounds__(256,2)
void k_gemm_routed(int stage, const float* __restrict__ Wk, const float* __restrict__ Wv,
                   const float* __restrict__ W1, const float* __restrict__ W2)
{
    __shared__ float As[8][128];
    __shared__ float Bs[8][128];
    __shared__ int s_idx;
    const int tid=threadIdx.x;
    const int tx=tid&15, ty=tid>>4;
    const int ar=tid>>1, akq=(tid&1)*4;
    const int bkr=tid>>5, bn=(tid&31)*4;
    const int* toff = (stage==0)? g_toff1 : g_toff2;
    const int total = toff[NEXP];
    for(;;){
        if(tid==0) s_idx=(int)atomicAdd(&g_ctr[stage],1u);
        __syncthreads();
        const int idx=s_idx;
        if(idx>=total) return;
        int e=0;
#pragma unroll
        for(int q=1;q<NEXP;q++) if(idx>=toff[q]) e=q;
        const int local=idx-toff[e];
        const int base=g_off[e];
        const int ne=g_off[e+1]-base;
        const bool rwkv=(e<ERWKV);
        int Nn,K;
        const float* Bsrc;
        if(stage==0){
            Nn = rwkv? HDIM:CDIM; K=CDIM;
            Bsrc = rwkv? (Wk+(size_t)e*CDIM*HDIM) : (W1+(size_t)(e-ERWKV)*CDIM*CDIM);
        } else {
            Nn=CDIM; K = rwkv? HDIM:CDIM;
            Bsrc = rwkv? (Wv+(size_t)e*HDIM*CDIM) : (W2+(size_t)(e-ERWKV)*CDIM*CDIM);
        }
        const int ntl = Nn>>7;
        const int mb=(local/ntl)*128;
        const int nb=(local%ntl)*128;
        float acc[8][8];
#pragma unroll
        for(int i=0;i<8;i++)
#pragma unroll
            for(int j=0;j<8;j++) acc[i][j]=0.f;
        const float* Bp=Bsrc+(size_t)bkr*Nn+nb+bn;
        if(stage==0){
            const int mrow=mb+ar;
            const bool valid = (mrow<ne);
            const int tokr = valid? g_tok[base+mrow] : 0;
            const float* Asrc = rwkv? g_h : g_z;
            const float* Ap = Asrc + (size_t)tokr*CDIM + akq;
            for(int k0=0;k0<K;k0+=8){
                float4 av = valid? *(const float4*)(Ap+k0) : make_float4(0.f,0.f,0.f,0.f);
                float4 bv = *(const float4*)(Bp+(size_t)k0*Nn);
                As[akq+0][ar]=av.x; As[akq+1][ar]=av.y; As[akq+2][ar]=av.z; As[akq+3][ar]=av.w;
                *(float4*)(&Bs[bkr][bn])=bv;
                __syncthreads();
#pragma unroll
                for(int kk=0;kk<8;kk++){
                    float a[8],b[8];
#pragma unroll
                    for(int i=0;i<8;i++) a[i]=As[kk][ty*8+i];
#pragma unroll
                    for(int j=0;j<8;j++) b[j]=Bs[kk][tx*8+j];
#pragma unroll
                    for(int i=0;i<8;i++)
#pragma unroll
                        for(int j=0;j<8;j++) acc[i][j]=fmaf(a[i],b[j],acc[i][j]);
                }
                __syncthreads();
            }
#pragma unroll
            for(int i=0;i<8;i++){
                const int mr2=mb+ty*8+i;
                if(mr2<ne){
                    float* dst=g_mid+(size_t)(base+mr2)*HDIM+nb+tx*8;
#pragma unroll
                    for(int j=0;j<8;j++){
                        float vv=acc[i][j];
                        if(rwkv){ vv=fmaxf(vv,0.f); vv=vv*vv; }
                        else      vv=gelu_tanh(vv);
                        dst[j]=vv;
                    }
                }
            }
        } else {
            const float* Ap=g_mid+(size_t)(base+mb+ar)*HDIM+akq;
            for(int k0=0;k0<K;k0+=8){
                float4 av=*(const float4*)(Ap+k0);
                float4 bv=*(const float4*)(Bp+(size_t)k0*Nn);
                As[akq+0][ar]=av.x; As[akq+1][ar]=av.y; As[akq+2][ar]=av.z; As[akq+3][ar]=av.w;
                *(float4*)(&Bs[bkr][bn])=bv;
                __syncthreads();
#pragma unroll
                for(int kk=0;kk<8;kk++){
                    float a[8],b[8];
#pragma unroll
                    for(int i=0;i<8;i++) a[i]=As[kk][ty*8+i];
#pragma unroll
                    for(int j=0;j<8;j++) b[j]=Bs[kk][tx*8+j];
#pragma unroll
                    for(int i=0;i<8;i++)
#pragma unroll
                        for(int j=0;j<8;j++) acc[i][j]=fmaf(a[i],b[j],acc[i][j]);
                }
                __syncthreads();
            }
#pragma unroll
            for(int i=0;i<8;i++){
                const int mr2=mb+ty*8+i;
                if(mr2<ne){
                    const int slot=base+mr2;
                    const int tt=g_tok[slot];
                    const float gt=g_gate[slot];
                    float* dst = (g_rank[slot]==0? g_slot0 : g_slot1) + (size_t)tt*CDIM + nb + tx*8;
#pragma unroll
                    for(int j=0;j<8;j++) dst[j]=gt*acc[i][j];
                }
            }
        }
    }
}

// ------------------------- epilogue: combine + passthrough -------------------------
__global__ void k_final(const float* __restrict__ vf, float* __restrict__ out){
    const int i=blockIdx.x*256+threadIdx.x;
    out[i]        = g_x2[i] + g_slot0[i] + g_slot1[i];
    out[OUT_VF+i] = vf[i];
}

// ------------------------- launch -------------------------
extern "C" void kernel_launch(void* const* d_in, const int* in_sizes, int n_in,
                              void* d_out, int out_size)
{
    const float* x     =(const float*)d_in[0];
    const float* vf    =(const float*)d_in[1];
    const float* cap   =(const float*)d_in[2];
    const float* ln1g  =(const float*)d_in[3];
    const float* ln1b  =(const float*)d_in[4];
    const float* ln2g  =(const float*)d_in[5];
    const float* ln2b  =(const float*)d_in[6];
    const float* Wa    =(const float*)d_in[7];
    const float* Ws    =(const float*)d_in[8];
    const float* wconf =(const float*)d_in[9];
    const float* wdiff =(const float*)d_in[10];
    const float* Waff  =(const float*)d_in[11];
    const float* Wbh   =(const float*)d_in[12];
    const float* Wbs   =(const float*)d_in[13];
    const float* Wk    =(const float*)d_in[14];
    const float* Wv    =(const float*)d_in[15];
    const float* W1    =(const float*)d_in[16];
    const float* W2    =(const float*)d_in[17];
    float* out=(float*)d_out;

    k_ln1<<<BTOK,256>>>(x,ln1g,ln1b);
    dim3 gd(CDIM/128, BTOK/128);
    k_gemm_att<<<gd,256>>>(x,Wa);
    k_gemm_rs <<<gd,256>>>(Ws);
    k_post1<<<BTOK,256>>>(ln2g,ln2b,wconf,wdiff,Waff,cap,out);
    k_route_setup<<<1,32>>>();
    k_route_fill<<<(BTOK+255)/256,256>>>();
    k_gemm_z1<<<gd,256>>>(Wbh);
    k_gemm_z2<<<gd,256>>>(Wbs);
    k_gemm_routed<<<304,256>>>(0,Wk,Wv,W1,W2);
    k_gemm_routed<<<304,256>>>(1,Wk,Wv,W1,W2);
    k_final<<<BTOK*CDIM/256,256>>>(vf,out);
}

// round 7
// speedup vs baseline: 1.4336x; 1.4333x over previous
#include <cuda_runtime.h>
#include <cuda_bf16.h>
#include <mma.h>
#include <math.h>
#include <stdint.h>

using namespace nvcuda;

#define BTOK 4096
#define CDIM 1024
#define HDIM 4096
#define NEXP 8
#define ERWKV 6
#define MAXS (2*BTOK)
#define MIDROWS (MAXS+128)

#define OUT_VF   (BTOK*CDIM)
#define OUT_WIN  (2*BTOK*CDIM)
#define OUT_COST (OUT_WIN + 2*BTOK)
#define OUT_DIFF (OUT_COST + BTOK)
#define OUT_AFF  (OUT_DIFF + BTOK)

// ---------------- SMEM layout ----------------
// 4 buffers (Ah, Al, Bh, Bl), each 128 rows x 72 bf16 (144B row: 128B data + 16B pad)
#define ROWE   72                     // elements per row
#define BUFE   (128*ROWE)             // 9216 elements per buffer
#define BUFB   (BUFE*2)               // 18432 bytes
#define SM_AOFF  (4*BUFB)             // 73728: 128 * 8B A-row offsets
#define SMEM_BYTES (SM_AOFF + 1024)   // 74752
// epilogue f32 scratch 128x132 (67584 B) overlaps buffers (used after compute)

// ---------------- scratch (static device memory) ----------------
__device__ __nv_bfloat16 g_xln_h[BTOK*CDIM], g_xln_l[BTOK*CDIM];
__device__ float g_x2[BTOK*CDIM];
__device__ __nv_bfloat16 g_hr_h[(size_t)BTOK*2*CDIM], g_hr_l[(size_t)BTOK*2*CDIM]; // [tok][0:1024)=h, [1024:2048)=rs
__device__ __nv_bfloat16 g_z_h[BTOK*CDIM], g_z_l[BTOK*CDIM];
__device__ __nv_bfloat16 g_mid_h[(size_t)MIDROWS*HDIM], g_mid_l[(size_t)MIDROWS*HDIM];
__device__ float g_slot0[BTOK*CDIM], g_slot1[BTOK*CDIM];

// transposed + split weights ([N][K] K-major)
__device__ __nv_bfloat16 g_WaT_h[CDIM*CDIM], g_WaT_l[CDIM*CDIM];
__device__ __nv_bfloat16 g_WsT_h[CDIM*CDIM], g_WsT_l[CDIM*CDIM];
__device__ __nv_bfloat16 g_WbT_h[(size_t)CDIM*2*CDIM], g_WbT_l[(size_t)CDIM*2*CDIM]; // [1024][2048] = [Wbh^T | Wbs^T]
__device__ __nv_bfloat16 g_WkT_h[(size_t)ERWKV*HDIM*CDIM], g_WkT_l[(size_t)ERWKV*HDIM*CDIM];
__device__ __nv_bfloat16 g_WvT_h[(size_t)ERWKV*CDIM*HDIM], g_WvT_l[(size_t)ERWKV*CDIM*HDIM];
__device__ __nv_bfloat16 g_W1T_h[2*CDIM*CDIM], g_W1T_l[2*CDIM*CDIM];
__device__ __nv_bfloat16 g_W2T_h[2*CDIM*CDIM], g_W2T_l[2*CDIM*CDIM];

// routing
__device__ int   g_win[2*BTOK];
__device__ float g_wt [2*BTOK];
__device__ int   g_cnt[NEXP];
__device__ int   g_off[NEXP+1];
__device__ int   g_cur[NEXP];
__device__ int   g_tok[MAXS];
__device__ float g_gate[MAXS];
__device__ int   g_rank[MAXS];
__device__ int   g_toff[2][NEXP+1];
__device__ unsigned int g_ctr[2];

__device__ __forceinline__ float gelu_tanh(float x){
    float x3 = x*x*x;
    return 0.5f*x*(1.0f + tanhf(0.7978845608028654f*(x + 0.044715f*x3)));
}
__device__ __forceinline__ void split_store(__nv_bfloat16* ph, __nv_bfloat16* pl, size_t o, float v){
    __nv_bfloat16 hi = __float2bfloat16(v);
    ph[o] = hi;
    pl[o] = __float2bfloat16(v - __bfloat162float(hi));
}

// ---------------- weight transpose+split: src[K][N] f32 -> dst[N][dstride] bf16 hi/lo ----------------
__global__ void k_transpose(const float* __restrict__ src, __nv_bfloat16* __restrict__ dh,
                            __nv_bfloat16* __restrict__ dl, int K, int N, int dstride, int coloff,
                            long long sBatch, long long dBatch)
{
    __shared__ float t[32][33];
    const int bz = blockIdx.z;
    src += (long long)bz*sBatch;
    dh  += (long long)bz*dBatch;
    dl  += (long long)bz*dBatch;
    const int k0 = blockIdx.y*32, n0 = blockIdx.x*32;
    const int tx = threadIdx.x, ty = threadIdx.y;
#pragma unroll
    for (int j=0;j<4;j++) t[ty+8*j][tx] = src[(size_t)(k0+ty+8*j)*N + n0+tx];
    __syncthreads();
#pragma unroll
    for (int j=0;j<4;j++){
        float v = t[tx][ty+8*j];
        size_t o = (size_t)(n0+ty+8*j)*dstride + coloff + k0 + tx;
        __nv_bfloat16 hi = __float2bfloat16(v);
        dh[o]=hi; dl[o]=__float2bfloat16(v - __bfloat162float(hi));
    }
}

// ---------------- LN1 (writes split xln) ----------------
__global__ void k_ln1(const float* __restrict__ x, const float* __restrict__ g1,
                      const float* __restrict__ b1)
{
    const int t = blockIdx.x;
    const int tid = threadIdx.x;
    if (t == 0 && tid < NEXP) g_cnt[tid] = 0;
    __shared__ float red[256];
    const float* xr = x + (size_t)t*CDIM;
    float v[4]; float s = 0.f;
#pragma unroll
    for (int q=0;q<4;q++){ v[q]=xr[tid+256*q]; s+=v[q]; }
    red[tid]=s; __syncthreads();
    for(int st=128;st>0;st>>=1){ if(tid<st) red[tid]+=red[tid+st]; __syncthreads(); }
    const float m = red[0]*(1.0f/CDIM);
    __syncthreads();
    float s2=0.f;
#pragma unroll
    for(int q=0;q<4;q++){ float d=v[q]-m; s2+=d*d; }
    red[tid]=s2; __syncthreads();
    for(int st=128;st>0;st>>=1){ if(tid<st) red[tid]+=red[tid+st]; __syncthreads(); }
    const float rstd = rsqrtf(red[0]*(1.0f/CDIM)+1e-5f);
#pragma unroll
    for(int q=0;q<4;q++){
        int i=tid+256*q;
        float xv=(v[q]-m)*rstd*g1[i]+b1[i];
        split_store(g_xln_h, g_xln_l, (size_t)t*CDIM+i, xv);
    }
}

// ---------------- LN2 + router (writes split h into g_hr[:,0:1024)) ----------------
__global__ void k_post1(const float* __restrict__ g2, const float* __restrict__ b2,
                        const float* __restrict__ w_conf, const float* __restrict__ w_diff,
                        const float* __restrict__ W_aff, const float* __restrict__ cap,
                        float* __restrict__ out)
{
    const int t = blockIdx.x;
    const int tid = threadIdx.x;
    __shared__ float red[256];
    __shared__ float sh[CDIM];
    __shared__ float sconf[NEXP], saff[NEXP];
    __shared__ float sdiff;
    const float* xr = g_x2 + (size_t)t*CDIM;
    float v[4]; float s=0.f;
#pragma unroll
    for(int q=0;q<4;q++){ v[q]=xr[tid+256*q]; s+=v[q]; }
    red[tid]=s; __syncthreads();
    for(int st=128;st>0;st>>=1){ if(tid<st) red[tid]+=red[tid+st]; __syncthreads(); }
    const float m=red[0]*(1.0f/CDIM);
    __syncthreads();
    float s2=0.f;
#pragma unroll
    for(int q=0;q<4;q++){ float d=v[q]-m; s2+=d*d; }
    red[tid]=s2; __syncthreads();
    for(int st=128;st>0;st>>=1){ if(tid<st) red[tid]+=red[tid+st]; __syncthreads(); }
    const float rstd=rsqrtf(red[0]*(1.0f/CDIM)+1e-5f);
#pragma unroll
    for(int q=0;q<4;q++){
        int i=tid+256*q;
        float hv=(v[q]-m)*rstd*g2[i]+b2[i];
        sh[i]=hv;
        split_store(g_hr_h, g_hr_l, (size_t)t*2*CDIM+i, hv);
    }
    __syncthreads();
    const int w=tid>>5, lane=tid&31;
    float cd=0.f, ad=0.f, dd=0.f;
    for(int i=lane;i<CDIM;i+=32){
        float hv=sh[i];
        cd = fmaf(hv, w_conf[w*CDIM+i], cd);
        ad = fmaf(hv, W_aff[i*NEXP+w], ad);
        if(w==0) dd = fmaf(hv, w_diff[i], dd);
    }
#pragma unroll
    for(int o=16;o>0;o>>=1){
        cd += __shfl_down_sync(0xffffffffu, cd, o);
        ad += __shfl_down_sync(0xffffffffu, ad, o);
        dd += __shfl_down_sync(0xffffffffu, dd, o);
    }
    if(lane==0){ sconf[w]=cd; saff[w]=ad; if(w==0) sdiff=dd; }
    __syncthreads();
    if(tid<NEXP) out[OUT_AFF + t*NEXP + tid] = saff[tid];
    if(tid==0){
        float diff = fmaxf(sdiff,0.f) + log1pf(expf(-fabsf(sdiff)));
        float b0=-INFINITY, b1v=-INFINITY; int e0=0,e1=0;
#pragma unroll
        for(int e=0;e<NEXP;e++){
            float conf = 1.0f/(1.0f+expf(-sconf[e]));
            float bid = fmaf(conf, cap[e], saff[e]);
            if(bid>b0){ b1v=b0;e1=e0;b0=bid;e0=e; }
            else if(bid>b1v){ b1v=bid;e1=e; }
        }
        float ex = expf(b1v-b0);
        float w0 = 1.0f/(1.0f+ex);
        float w1 = ex/(1.0f+ex);
        out[OUT_WIN + 2*t]   = (float)e0;
        out[OUT_WIN + 2*t+1] = (float)e1;
        out[OUT_COST + t] = (b0*w0 + b1v*w1)*diff;
        out[OUT_DIFF + t] = diff;
        g_win[2*t]=e0; g_win[2*t+1]=e1;
        g_wt[2*t]=w0;  g_wt[2*t+1]=w1;
        atomicAdd(&g_cnt[e0],1);
        atomicAdd(&g_cnt[e1],1);
    }
}

// ---------------- routing setup/fill ----------------
__global__ void k_route_setup(){
    if(threadIdx.x==0){
        int o=0;
        for(int e=0;e<NEXP;e++){ g_off[e]=o; o+=g_cnt[e]; }
        g_off[NEXP]=o;
        int t1=0,t2=0;
        for(int e=0;e<NEXP;e++){
            g_cur[e]=g_off[e];
            int mt=(g_cnt[e]+127)>>7;
            int nt1=(e<ERWKV)?(HDIM>>7):(CDIM>>7);
            g_toff[0][e]=t1; t1+=mt*nt1;
            g_toff[1][e]=t2; t2+=mt*(CDIM>>7);
        }
        g_toff[0][NEXP]=t1; g_toff[1][NEXP]=t2;
        g_ctr[0]=0u; g_ctr[1]=0u;
    }
}
__global__ void k_route_fill(){
    int t = blockIdx.x*blockDim.x + threadIdx.x;
    if(t<BTOK){
#pragma unroll
        for(int r=0;r<2;r++){
            int e=g_win[2*t+r];
            int p=atomicAdd(&g_cur[e],1);
            g_tok[p]=t; g_gate[p]=g_wt[2*t+r]; g_rank[p]=r;
        }
    }
}

// ---------------- wmma tile core (128x128 tile, Kc=64 chunks, synchronous loads) ----------------
// EPI: 0=X2(residual add, f32), 1=RS(split to hr[:,1024:]), 2=Z(h + D, split),
//      3=MID(activation, split), 4=OUT(gate scatter)
// amode: 0 direct rows (mb+r), 1 gather via g_tok[base+row], 2 slot rows (base+mb+r)
template<int EPI>
__device__ void tc_tile(char* smem,
    const __nv_bfloat16* __restrict__ Ah, const __nv_bfloat16* __restrict__ Al,
    int astride, int amode,
    const __nv_bfloat16* __restrict__ Bh, const __nv_bfloat16* __restrict__ Bl, int K,
    int mb, int nb, int base, int ne, int rwkv,
    const float* __restrict__ xsrc)
{
    const int tid = threadIdx.x;
    __nv_bfloat16* sbuf = (__nv_bfloat16*)smem;   // 4 buffers of BUFE elements
    long long* s_aoff = (long long*)(smem + SM_AOFF);
    if (tid < 128){
        int r = tid;
        long long off;
        if (amode==0)      off = (long long)(mb+r)*astride;
        else if (amode==1){ int row=mb+r; int tk = (row<ne)? g_tok[base+row] : g_tok[base]; off=(long long)tk*astride; }
        else               off = (long long)(base+mb+r)*astride;
        s_aoff[r] = off;
    }
    __syncthreads();

    const int wid = tid>>5;
    const int m0w = (wid&3)*32;        // 4 warps in M
    const int n0w = (wid>>2)*64;       // 2 warps in N

    wmma::fragment<wmma::accumulator,16,16,16,float> acc[2][4];
#pragma unroll
    for (int i=0;i<2;i++)
#pragma unroll
        for (int j=0;j<4;j++) wmma::fill_fragment(acc[i][j], 0.0f);

    const int nch = K >> 6;
    const int b = tid >> 6, p = tid & 63;
    const __nv_bfloat16* sel = (b==0)?Ah:(b==1)?Al:(b==2)?Bh:Bl;

    for (int c=0; c<nch; c++){
        const int c0 = c << 6;
        // synchronous load: 4 buffers x 128 rows x 128B
        {
#pragma unroll
            for (int rr=0; rr<2; rr++){
                const int r = p*2+rr;
                const __nv_bfloat16* src = (b<2) ? (sel + s_aoff[r] + c0)
                                                 : (sel + (long long)(nb + r)*K + c0);
                __nv_bfloat16* drow = sbuf + b*BUFE + r*ROWE;
#pragma unroll
                for (int i=0;i<8;i++){
                    *(uint4*)(drow + i*8) = *(const uint4*)(src + i*8);
                }
            }
        }
        __syncthreads();

        const __nv_bfloat16* sAh = sbuf;
        const __nv_bfloat16* sAl = sbuf + BUFE;
        const __nv_bfloat16* sBh = sbuf + 2*BUFE;
        const __nv_bfloat16* sBl = sbuf + 3*BUFE;
#pragma unroll
        for (int kk=0; kk<4; kk++){
            const int k0 = kk*16;
            wmma::fragment<wmma::matrix_a,16,16,16,__nv_bfloat16,wmma::row_major> a_h[2], a_l[2];
#pragma unroll
            for (int mf=0; mf<2; mf++){
                wmma::load_matrix_sync(a_h[mf], sAh + (m0w+mf*16)*ROWE + k0, ROWE);
                wmma::load_matrix_sync(a_l[mf], sAl + (m0w+mf*16)*ROWE + k0, ROWE);
            }
#pragma unroll
            for (int nf=0; nf<4; nf++){
                wmma::fragment<wmma::matrix_b,16,16,16,__nv_bfloat16,wmma::col_major> b_h, b_l;
                wmma::load_matrix_sync(b_h, sBh + (n0w+nf*16)*ROWE + k0, ROWE);
                wmma::load_matrix_sync(b_l, sBl + (n0w+nf*16)*ROWE + k0, ROWE);
#pragma unroll
                for (int mf=0; mf<2; mf++){
                    wmma::mma_sync(acc[mf][nf], a_h[mf], b_h, acc[mf][nf]);
                    wmma::mma_sync(acc[mf][nf], a_h[mf], b_l, acc[mf][nf]);
                    wmma::mma_sync(acc[mf][nf], a_l[mf], b_h, acc[mf][nf]);
                }
            }
        }
        __syncthreads();
    }

    // epilogue: accum -> padded SMEM (128x132 f32) -> coalesced global
    float* eps = (float*)smem;
#pragma unroll
    for (int mf=0; mf<2; mf++)
#pragma unroll
        for (int nf=0; nf<4; nf++)
            wmma::store_matrix_sync(eps + (m0w+mf*16)*132 + n0w + nf*16, acc[mf][nf], 132, wmma::mem_row_major);
    __syncthreads();
    for (int i=tid; i<16384; i+=256){
        const int row = i>>7, col = i&127;
        const float v = eps[row*132+col];
        if (EPI==0){
            size_t o = (size_t)(mb+row)*CDIM + nb + col;
            g_x2[o] = xsrc[o] + v;
        } else if (EPI==1){
            size_t o = (size_t)(mb+row)*2*CDIM + CDIM + nb + col;
            split_store(g_hr_h, g_hr_l, o, v);
        } else if (EPI==2){
            size_t ho = (size_t)(mb+row)*2*CDIM + nb + col;
            float hrec = __bfloat162float(g_hr_h[ho]) + __bfloat162float(g_hr_l[ho]);
            split_store(g_z_h, g_z_l, (size_t)(mb+row)*CDIM + nb + col, hrec + v);
        } else if (EPI==3){
            int r2 = mb+row;
            if (r2 < ne){
                float a;
                if (rwkv){ a = fmaxf(v,0.f); a = a*a; }
                else       a = gelu_tanh(v);
                split_store(g_mid_h, g_mid_l, (size_t)(base+r2)*HDIM + nb + col, a);
            }
        } else {
            int r2 = mb+row;
            if (r2 < ne){
                int slot = base + r2;
                int tt = g_tok[slot];
                float gt = g_gate[slot];
                float* dst = g_rank[slot] ? g_slot1 : g_slot0;
                dst[(size_t)tt*CDIM + nb + col] = gt*v;
            }
        }
    }
    __syncthreads();
}

// ---------------- dense GEMM kernels ----------------
template<int EPI>
__global__ __launch_bounds__(256) void k_dense(
    const __nv_bfloat16* __restrict__ Ah, const __nv_bfloat16* __restrict__ Al, int astride,
    const __nv_bfloat16* __restrict__ Bh, const __nv_bfloat16* __restrict__ Bl, int K,
    const float* __restrict__ xsrc)
{
    extern __shared__ char smem[];
    tc_tile<EPI>(smem, Ah, Al, astride, 0, Bh, Bl, K,
                 blockIdx.y*128, blockIdx.x*128, 0, 1<<30, 0, xsrc);
}

// ---------------- routed persistent grouped GEMM ----------------
template<int STAGE>
__global__ __launch_bounds__(256) void k_routed()
{
    extern __shared__ char smem[];
    __shared__ int s_idx;
    const int total = g_toff[STAGE][NEXP];
    for(;;){
        if (threadIdx.x==0) s_idx = (int)atomicAdd(&g_ctr[STAGE], 1u);
        __syncthreads();
        const int idx = s_idx;
        if (idx >= total) break;
        int e = 0;
#pragma unroll
        for (int q=1;q<NEXP;q++) if (idx >= g_toff[STAGE][q]) e = q;
        const int local = idx - g_toff[STAGE][e];
        const int base = g_off[e];
        const int ne = g_off[e+1]-base;
        const bool rwkv = (e < ERWKV);
        const int ntl = (STAGE==0) ? (rwkv ? (HDIM>>7) : (CDIM>>7)) : (CDIM>>7);
        const int mb = (local/ntl)*128;
        const int nb = (local%ntl)*128;
        if (STAGE==0){
            const __nv_bfloat16* Ah = rwkv ? g_hr_h : g_z_h;
            const __nv_bfloat16* Al = rwkv ? g_hr_l : g_z_l;
            const int astride = rwkv ? 2*CDIM : CDIM;
            const __nv_bfloat16* Bh = rwkv ? (g_WkT_h + (size_t)e*HDIM*CDIM) : (g_W1T_h + (size_t)(e-ERWKV)*CDIM*CDIM);
            const __nv_bfloat16* Bl = rwkv ? (g_WkT_l + (size_t)e*HDIM*CDIM) : (g_W1T_l + (size_t)(e-ERWKV)*CDIM*CDIM);
            tc_tile<3>(smem, Ah, Al, astride, 1, Bh, Bl, CDIM,
                       mb, nb, base, ne, rwkv?1:0, nullptr);
        } else {
            const int K = rwkv ? HDIM : CDIM;
            const __nv_bfloat16* Bh = rwkv ? (g_WvT_h + (size_t)e*CDIM*HDIM) : (g_W2T_h + (size_t)(e-ERWKV)*CDIM*CDIM);
            const __nv_bfloat16* Bl = rwkv ? (g_WvT_l + (size_t)e*CDIM*HDIM) : (g_W2T_l + (size_t)(e-ERWKV)*CDIM*CDIM);
            tc_tile<4>(smem, g_mid_h, g_mid_l, HDIM, 2, Bh, Bl, K,
                       mb, nb, base, ne, 0, nullptr);
        }
    }
}

// ---------------- epilogue combine ----------------
__global__ void k_final(const float* __restrict__ vf, float* __restrict__ out){
    const int i = blockIdx.x*256 + threadIdx.x;
    out[i]        = g_x2[i] + g_slot0[i] + g_slot1[i];
    out[OUT_VF+i] = vf[i];
}

// ---------------- launch ----------------
extern "C" void kernel_launch(void* const* d_in, const int* in_sizes, int n_in,
                              void* d_out, int out_size)
{
    const float* x     =(const float*)d_in[0];
    const float* vf    =(const float*)d_in[1];
    const float* cap   =(const float*)d_in[2];
    const float* ln1g  =(const float*)d_in[3];
    const float* ln1b  =(const float*)d_in[4];
    const float* ln2g  =(const float*)d_in[5];
    const float* ln2b  =(const float*)d_in[6];
    const float* Wa    =(const float*)d_in[7];
    const float* Ws    =(const float*)d_in[8];
    const float* wconf =(const float*)d_in[9];
    const float* wdiff =(const float*)d_in[10];
    const float* Waff  =(const float*)d_in[11];
    const float* Wbh   =(const float*)d_in[12];
    const float* Wbs   =(const float*)d_in[13];
    const float* Wk    =(const float*)d_in[14];
    const float* Wv    =(const float*)d_in[15];
    const float* W1    =(const float*)d_in[16];
    const float* W2    =(const float*)d_in[17];
    float* out=(float*)d_out;

    // CRITICAL: resolve __device__ symbols to REAL device addresses.
    // (Passing the symbol name from host code passes the host-side shadow
    //  array, which GB300's ATS happily dereferences as zeros.)
    void *p_xln_h, *p_xln_l, *p_hr_h, *p_hr_l, *p_z_h, *p_z_l;
    void *p_WaT_h, *p_WaT_l, *p_WsT_h, *p_WsT_l, *p_WbT_h, *p_WbT_l;
    void *p_WkT_h, *p_WkT_l, *p_WvT_h, *p_WvT_l, *p_W1T_h, *p_W1T_l, *p_W2T_h, *p_W2T_l;
    cudaGetSymbolAddress(&p_xln_h, g_xln_h); cudaGetSymbolAddress(&p_xln_l, g_xln_l);
    cudaGetSymbolAddress(&p_hr_h,  g_hr_h);  cudaGetSymbolAddress(&p_hr_l,  g_hr_l);
    cudaGetSymbolAddress(&p_z_h,   g_z_h);   cudaGetSymbolAddress(&p_z_l,   g_z_l);
    cudaGetSymbolAddress(&p_WaT_h, g_WaT_h); cudaGetSymbolAddress(&p_WaT_l, g_WaT_l);
    cudaGetSymbolAddress(&p_WsT_h, g_WsT_h); cudaGetSymbolAddress(&p_WsT_l, g_WsT_l);
    cudaGetSymbolAddress(&p_WbT_h, g_WbT_h); cudaGetSymbolAddress(&p_WbT_l, g_WbT_l);
    cudaGetSymbolAddress(&p_WkT_h, g_WkT_h); cudaGetSymbolAddress(&p_WkT_l, g_WkT_l);
    cudaGetSymbolAddress(&p_WvT_h, g_WvT_h); cudaGetSymbolAddress(&p_WvT_l, g_WvT_l);
    cudaGetSymbolAddress(&p_W1T_h, g_W1T_h); cudaGetSymbolAddress(&p_W1T_l, g_W1T_l);
    cudaGetSymbolAddress(&p_W2T_h, g_W2T_h); cudaGetSymbolAddress(&p_W2T_l, g_W2T_l);

    cudaFuncSetAttribute(k_dense<0>, cudaFuncAttributeMaxDynamicSharedMemorySize, SMEM_BYTES);
    cudaFuncSetAttribute(k_dense<1>, cudaFuncAttributeMaxDynamicSharedMemorySize, SMEM_BYTES);
    cudaFuncSetAttribute(k_dense<2>, cudaFuncAttributeMaxDynamicSharedMemorySize, SMEM_BYTES);
    cudaFuncSetAttribute(k_routed<0>, cudaFuncAttributeMaxDynamicSharedMemorySize, SMEM_BYTES);
    cudaFuncSetAttribute(k_routed<1>, cudaFuncAttributeMaxDynamicSharedMemorySize, SMEM_BYTES);

    dim3 tb(32,8);
    // weight transpose + split (destinations are RESOLVED device pointers)
    k_transpose<<<dim3(32,32,1), tb>>>(Wa,  (__nv_bfloat16*)p_WaT_h, (__nv_bfloat16*)p_WaT_l, CDIM, CDIM, CDIM, 0, 0, 0);
    k_transpose<<<dim3(32,32,1), tb>>>(Ws,  (__nv_bfloat16*)p_WsT_h, (__nv_bfloat16*)p_WsT_l, CDIM, CDIM, CDIM, 0, 0, 0);
    k_transpose<<<dim3(32,32,1), tb>>>(Wbh, (__nv_bfloat16*)p_WbT_h, (__nv_bfloat16*)p_WbT_l, CDIM, CDIM, 2*CDIM, 0,    0, 0);
    k_transpose<<<dim3(32,32,1), tb>>>(Wbs, (__nv_bfloat16*)p_WbT_h, (__nv_bfloat16*)p_WbT_l, CDIM, CDIM, 2*CDIM, CDIM, 0, 0);
    k_transpose<<<dim3(128,32,ERWKV), tb>>>(Wk, (__nv_bfloat16*)p_WkT_h, (__nv_bfloat16*)p_WkT_l, CDIM, HDIM, CDIM, 0,
                                            (long long)CDIM*HDIM, (long long)HDIM*CDIM);
    k_transpose<<<dim3(32,128,ERWKV), tb>>>(Wv, (__nv_bfloat16*)p_WvT_h, (__nv_bfloat16*)p_WvT_l, HDIM, CDIM, HDIM, 0,
                                            (long long)HDIM*CDIM, (long long)CDIM*HDIM);
    k_transpose<<<dim3(32,32,2), tb>>>(W1, (__nv_bfloat16*)p_W1T_h, (__nv_bfloat16*)p_W1T_l, CDIM, CDIM, CDIM, 0,
                                       (long long)CDIM*CDIM, (long long)CDIM*CDIM);
    k_transpose<<<dim3(32,32,2), tb>>>(W2, (__nv_bfloat16*)p_W2T_h, (__nv_bfloat16*)p_W2T_l, CDIM, CDIM, CDIM, 0,
                                       (long long)CDIM*CDIM, (long long)CDIM*CDIM);

    k_ln1<<<BTOK,256>>>(x, ln1g, ln1b);

    dim3 gd(CDIM/128, BTOK/128);
    k_dense<0><<<gd,256,SMEM_BYTES>>>((__nv_bfloat16*)p_xln_h, (__nv_bfloat16*)p_xln_l, CDIM,
                                      (__nv_bfloat16*)p_WaT_h, (__nv_bfloat16*)p_WaT_l, CDIM, x);
    k_dense<1><<<gd,256,SMEM_BYTES>>>((__nv_bfloat16*)p_xln_h, (__nv_bfloat16*)p_xln_l, CDIM,
                                      (__nv_bfloat16*)p_WsT_h, (__nv_bfloat16*)p_WsT_l, CDIM, nullptr);

    k_post1<<<BTOK,256>>>(ln2g, ln2b, wconf, wdiff, Waff, cap, out);
    k_route_setup<<<1,32>>>();
    k_route_fill<<<(BTOK+255)/256,256>>>();

    k_dense<2><<<gd,256,SMEM_BYTES>>>((__nv_bfloat16*)p_hr_h, (__nv_bfloat16*)p_hr_l, 2*CDIM,
                                      (__nv_bfloat16*)p_WbT_h, (__nv_bfloat16*)p_WbT_l, 2*CDIM, nullptr);

    k_routed<0><<<148,256,SMEM_BYTES>>>();
    k_routed<1><<<148,256,SMEM_BYTES>>>();

    k_final<<<BTOK*CDIM/256,256>>>(vf, out);
}

// round 8
// speedup vs baseline: 1.6950x; 1.1823x over previous
#include <cuda_runtime.h>
#include <cuda_bf16.h>
#include <mma.h>
#include <math.h>
#include <stdint.h>

using namespace nvcuda;

#define BTOK 4096
#define CDIM 1024
#define HDIM 4096
#define NEXP 8
#define ERWKV 6
#define MAXS (2*BTOK)
#define MIDROWS (MAXS+128)

#define OUT_VF   (BTOK*CDIM)
#define OUT_WIN  (2*BTOK*CDIM)
#define OUT_COST (OUT_WIN + 2*BTOK)
#define OUT_DIFF (OUT_COST + BTOK)
#define OUT_AFF  (OUT_DIFF + BTOK)

// ---------------- SMEM layout ----------------
// stage s (0,1): 4 buffers (Ah, Al, Bh, Bl), each 128 rows x 72 bf16 (144B row)
#define ROWE   72                      // elements per row
#define BUFE   (128*ROWE)              // 9216 elements per buffer
#define BUFB   (BUFE*2)                // 18432 bytes
#define STAGEB (4*BUFB)                // 73728 bytes per stage
#define SM_AOFF  (2*STAGEB)            // 147456: 128 * 8B A-row offsets
#define SMEM_BYTES (SM_AOFF + 1024)    // 148480
// epilogue f32 scratch 128x132 (67584 B) overlaps stage 0 (used after compute)

// ---------------- scratch (static device memory) ----------------
__device__ __nv_bfloat16 g_xln_h[BTOK*CDIM], g_xln_l[BTOK*CDIM];
__device__ float g_x2[BTOK*CDIM];
__device__ __nv_bfloat16 g_hr_h[(size_t)BTOK*2*CDIM], g_hr_l[(size_t)BTOK*2*CDIM]; // [tok][0:1024)=h, [1024:2048)=rs
__device__ __nv_bfloat16 g_z_h[BTOK*CDIM], g_z_l[BTOK*CDIM];
__device__ __nv_bfloat16 g_mid_h[(size_t)MIDROWS*HDIM], g_mid_l[(size_t)MIDROWS*HDIM];
__device__ float g_slot0[BTOK*CDIM], g_slot1[BTOK*CDIM];

// transposed + split weights ([N][K] K-major)
__device__ __nv_bfloat16 g_WaT_h[CDIM*CDIM], g_WaT_l[CDIM*CDIM];
__device__ __nv_bfloat16 g_WsT_h[CDIM*CDIM], g_WsT_l[CDIM*CDIM];
__device__ __nv_bfloat16 g_WbT_h[(size_t)CDIM*2*CDIM], g_WbT_l[(size_t)CDIM*2*CDIM]; // [1024][2048] = [Wbh^T | Wbs^T]
__device__ __nv_bfloat16 g_WkT_h[(size_t)ERWKV*HDIM*CDIM], g_WkT_l[(size_t)ERWKV*HDIM*CDIM];
__device__ __nv_bfloat16 g_WvT_h[(size_t)ERWKV*CDIM*HDIM], g_WvT_l[(size_t)ERWKV*CDIM*HDIM];
__device__ __nv_bfloat16 g_W1T_h[2*CDIM*CDIM], g_W1T_l[2*CDIM*CDIM];
__device__ __nv_bfloat16 g_W2T_h[2*CDIM*CDIM], g_W2T_l[2*CDIM*CDIM];

// routing
__device__ int   g_win[2*BTOK];
__device__ float g_wt [2*BTOK];
__device__ int   g_cnt[NEXP];
__device__ int   g_off[NEXP+1];
__device__ int   g_cur[NEXP];
__device__ int   g_tok[MAXS];
__device__ float g_gate[MAXS];
__device__ int   g_rank[MAXS];
__device__ int   g_toff[2][NEXP+1];
__device__ unsigned int g_ctr[2];

// ---------------- helpers ----------------
__device__ __forceinline__ uint32_t smem_to_u32(const void* p) {
    uint32_t a;
    asm("{ .reg .u64 t; cvta.to.shared.u64 t, %1; cvt.u32.u64 %0, t; }" : "=r"(a) : "l"(p));
    return a;
}
#define CP_ASYNC16(dst, src) \
    asm volatile("cp.async.cg.shared.global [%0], [%1], 16;" :: "r"(dst), "l"(src) : "memory")
#define CP_COMMIT() asm volatile("cp.async.commit_group;" ::: "memory")
#define CP_WAIT(n)  asm volatile("cp.async.wait_group %0;" :: "n"(n) : "memory")

__device__ __forceinline__ float gelu_tanh(float x){
    float x3 = x*x*x;
    return 0.5f*x*(1.0f + tanhf(0.7978845608028654f*(x + 0.044715f*x3)));
}
__device__ __forceinline__ void split_store(__nv_bfloat16* ph, __nv_bfloat16* pl, size_t o, float v){
    __nv_bfloat16 hi = __float2bfloat16(v);
    ph[o] = hi;
    pl[o] = __float2bfloat16(v - __bfloat162float(hi));
}

// ---------------- weight transpose+split: src[K][N] f32 -> dst[N][dstride] bf16 hi/lo ----------------
__global__ void k_transpose(const float* __restrict__ src, __nv_bfloat16* __restrict__ dh,
                            __nv_bfloat16* __restrict__ dl, int K, int N, int dstride, int coloff,
                            long long sBatch, long long dBatch)
{
    __shared__ float t[32][33];
    const int bz = blockIdx.z;
    src += (long long)bz*sBatch;
    dh  += (long long)bz*dBatch;
    dl  += (long long)bz*dBatch;
    const int k0 = blockIdx.y*32, n0 = blockIdx.x*32;
    const int tx = threadIdx.x, ty = threadIdx.y;
#pragma unroll
    for (int j=0;j<4;j++) t[ty+8*j][tx] = src[(size_t)(k0+ty+8*j)*N + n0+tx];
    __syncthreads();
#pragma unroll
    for (int j=0;j<4;j++){
        float v = t[tx][ty+8*j];
        size_t o = (size_t)(n0+ty+8*j)*dstride + coloff + k0 + tx;
        __nv_bfloat16 hi = __float2bfloat16(v);
        dh[o]=hi; dl[o]=__float2bfloat16(v - __bfloat162float(hi));
    }
}

// ---------------- LN1 (writes split xln) ----------------
__global__ void k_ln1(const float* __restrict__ x, const float* __restrict__ g1,
                      const float* __restrict__ b1)
{
    const int t = blockIdx.x;
    const int tid = threadIdx.x;
    if (t == 0 && tid < NEXP) g_cnt[tid] = 0;
    __shared__ float red[256];
    const float* xr = x + (size_t)t*CDIM;
    float v[4]; float s = 0.f;
#pragma unroll
    for (int q=0;q<4;q++){ v[q]=xr[tid+256*q]; s+=v[q]; }
    red[tid]=s; __syncthreads();
    for(int st=128;st>0;st>>=1){ if(tid<st) red[tid]+=red[tid+st]; __syncthreads(); }
    const float m = red[0]*(1.0f/CDIM);
    __syncthreads();
    float s2=0.f;
#pragma unroll
    for(int q=0;q<4;q++){ float d=v[q]-m; s2+=d*d; }
    red[tid]=s2; __syncthreads();
    for(int st=128;st>0;st>>=1){ if(tid<st) red[tid]+=red[tid+st]; __syncthreads(); }
    const float rstd = rsqrtf(red[0]*(1.0f/CDIM)+1e-5f);
#pragma unroll
    for(int q=0;q<4;q++){
        int i=tid+256*q;
        float xv=(v[q]-m)*rstd*g1[i]+b1[i];
        split_store(g_xln_h, g_xln_l, (size_t)t*CDIM+i, xv);
    }
}

// ---------------- LN2 + router (writes split h into g_hr[:,0:1024)) ----------------
__global__ void k_post1(const float* __restrict__ g2, const float* __restrict__ b2,
                        const float* __restrict__ w_conf, const float* __restrict__ w_diff,
                        const float* __restrict__ W_aff, const float* __restrict__ cap,
                        float* __restrict__ out)
{
    const int t = blockIdx.x;
    const int tid = threadIdx.x;
    __shared__ float red[256];
    __shared__ float sh[CDIM];
    __shared__ float sconf[NEXP], saff[NEXP];
    __shared__ float sdiff;
    const float* xr = g_x2 + (size_t)t*CDIM;
    float v[4]; float s=0.f;
#pragma unroll
    for(int q=0;q<4;q++){ v[q]=xr[tid+256*q]; s+=v[q]; }
    red[tid]=s; __syncthreads();
    for(int st=128;st>0;st>>=1){ if(tid<st) red[tid]+=red[tid+st]; __syncthreads(); }
    const float m=red[0]*(1.0f/CDIM);
    __syncthreads();
    float s2=0.f;
#pragma unroll
    for(int q=0;q<4;q++){ float d=v[q]-m; s2+=d*d; }
    red[tid]=s2; __syncthreads();
    for(int st=128;st>0;st>>=1){ if(tid<st) red[tid]+=red[tid+st]; __syncthreads(); }
    const float rstd=rsqrtf(red[0]*(1.0f/CDIM)+1e-5f);
#pragma unroll
    for(int q=0;q<4;q++){
        int i=tid+256*q;
        float hv=(v[q]-m)*rstd*g2[i]+b2[i];
        sh[i]=hv;
        split_store(g_hr_h, g_hr_l, (size_t)t*2*CDIM+i, hv);
    }
    __syncthreads();
    const int w=tid>>5, lane=tid&31;
    float cd=0.f, ad=0.f, dd=0.f;
    for(int i=lane;i<CDIM;i+=32){
        float hv=sh[i];
        cd = fmaf(hv, w_conf[w*CDIM+i], cd);
        ad = fmaf(hv, W_aff[i*NEXP+w], ad);
        if(w==0) dd = fmaf(hv, w_diff[i], dd);
    }
#pragma unroll
    for(int o=16;o>0;o>>=1){
        cd += __shfl_down_sync(0xffffffffu, cd, o);
        ad += __shfl_down_sync(0xffffffffu, ad, o);
        dd += __shfl_down_sync(0xffffffffu, dd, o);
    }
    if(lane==0){ sconf[w]=cd; saff[w]=ad; if(w==0) sdiff=dd; }
    __syncthreads();
    if(tid<NEXP) out[OUT_AFF + t*NEXP + tid] = saff[tid];
    if(tid==0){
        float diff = fmaxf(sdiff,0.f) + log1pf(expf(-fabsf(sdiff)));
        float b0=-INFINITY, b1v=-INFINITY; int e0=0,e1=0;
#pragma unroll
        for(int e=0;e<NEXP;e++){
            float conf = 1.0f/(1.0f+expf(-sconf[e]));
            float bid = fmaf(conf, cap[e], saff[e]);
            if(bid>b0){ b1v=b0;e1=e0;b0=bid;e0=e; }
            else if(bid>b1v){ b1v=bid;e1=e; }
        }
        float ex = expf(b1v-b0);
        float w0 = 1.0f/(1.0f+ex);
        float w1 = ex/(1.0f+ex);
        out[OUT_WIN + 2*t]   = (float)e0;
        out[OUT_WIN + 2*t+1] = (float)e1;
        out[OUT_COST + t] = (b0*w0 + b1v*w1)*diff;
        out[OUT_DIFF + t] = diff;
        g_win[2*t]=e0; g_win[2*t+1]=e1;
        g_wt[2*t]=w0;  g_wt[2*t+1]=w1;
        atomicAdd(&g_cnt[e0],1);
        atomicAdd(&g_cnt[e1],1);
    }
}

// ---------------- routing setup/fill ----------------
__global__ void k_route_setup(){
    if(threadIdx.x==0){
        int o=0;
        for(int e=0;e<NEXP;e++){ g_off[e]=o; o+=g_cnt[e]; }
        g_off[NEXP]=o;
        int t1=0,t2=0;
        for(int e=0;e<NEXP;e++){
            g_cur[e]=g_off[e];
            int mt=(g_cnt[e]+127)>>7;
            int nt1=(e<ERWKV)?(HDIM>>7):(CDIM>>7);
            g_toff[0][e]=t1; t1+=mt*nt1;
            g_toff[1][e]=t2; t2+=mt*(CDIM>>7);
        }
        g_toff[0][NEXP]=t1; g_toff[1][NEXP]=t2;
        g_ctr[0]=0u; g_ctr[1]=0u;
    }
}
__global__ void k_route_fill(){
    int t = blockIdx.x*blockDim.x + threadIdx.x;
    if(t<BTOK){
#pragma unroll
        for(int r=0;r<2;r++){
            int e=g_win[2*t+r];
            int p=atomicAdd(&g_cur[e],1);
            g_tok[p]=t; g_gate[p]=g_wt[2*t+r]; g_rank[p]=r;
        }
    }
}

// ---------------- async chunk loader: 4 buffers x 128 rows x 128B into stage s ----------------
__device__ __forceinline__ void issue_chunk(uint32_t su, const long long* s_aoff,
    const __nv_bfloat16* __restrict__ Ah, const __nv_bfloat16* __restrict__ Al,
    const __nv_bfloat16* __restrict__ Bh, const __nv_bfloat16* __restrict__ Bl,
    int K, int nb, int s, int c0)
{
    const int tid = threadIdx.x;
    const int b = tid >> 6, p = tid & 63;
    const __nv_bfloat16* sel = (b==0)?Ah:(b==1)?Al:(b==2)?Bh:Bl;
    const uint32_t dstb = su + (uint32_t)s*STAGEB + (uint32_t)b*BUFB;
#pragma unroll
    for (int rr=0; rr<2; rr++){
        const int r = p*2+rr;
        const __nv_bfloat16* src = (b<2) ? (sel + s_aoff[r] + c0)
                                         : (sel + (long long)(nb + r)*K + c0);
        const uint32_t drow = dstb + (uint32_t)r*144u;
#pragma unroll
        for (int i=0;i<8;i++){
            CP_ASYNC16(drow + i*16, src + i*8);
        }
    }
    CP_COMMIT();
}

// ---------------- wmma tile core (128x128 tile, Kc=64 chunks, cp.async double-buffered) ----------------
// EPI: 0=X2(residual add, f32), 1=RS(split to hr[:,1024:]), 2=Z(h + D, split),
//      3=MID(activation, split), 4=OUT(gate scatter)
// amode: 0 direct rows (mb+r), 1 gather via g_tok[base+row], 2 slot rows (base+mb+r)
template<int EPI>
__device__ void tc_tile(char* smem, uint32_t su,
    const __nv_bfloat16* __restrict__ Ah, const __nv_bfloat16* __restrict__ Al,
    int astride, int amode,
    const __nv_bfloat16* __restrict__ Bh, const __nv_bfloat16* __restrict__ Bl, int K,
    int mb, int nb, int base, int ne, int rwkv,
    const float* __restrict__ xsrc)
{
    const int tid = threadIdx.x;
    __nv_bfloat16* sbuf = (__nv_bfloat16*)smem;
    long long* s_aoff = (long long*)(smem + SM_AOFF);
    if (tid < 128){
        int r = tid;
        long long off;
        if (amode==0)      off = (long long)(mb+r)*astride;
        else if (amode==1){ int row=mb+r; int tk = (row<ne)? g_tok[base+row] : g_tok[base]; off=(long long)tk*astride; }
        else               off = (long long)(base+mb+r)*astride;
        s_aoff[r] = off;
    }
    __syncthreads();

    const int wid = tid>>5;
    const int m0w = (wid&3)*32;        // 4 warps in M
    const int n0w = (wid>>2)*64;       // 2 warps in N

    wmma::fragment<wmma::accumulator,16,16,16,float> acc[2][4];
#pragma unroll
    for (int i=0;i<2;i++)
#pragma unroll
        for (int j=0;j<4;j++) wmma::fill_fragment(acc[i][j], 0.0f);

    const int nch = K >> 6;
    issue_chunk(su, s_aoff, Ah, Al, Bh, Bl, K, nb, 0, 0);

    for (int c=0; c<nch; c++){
        const int s = c & 1;
        if (c+1 < nch){
            issue_chunk(su, s_aoff, Ah, Al, Bh, Bl, K, nb, (c+1)&1, (c+1)<<6);
            CP_WAIT(1);
        } else {
            CP_WAIT(0);
        }
        __syncthreads();

        const __nv_bfloat16* sAh = sbuf + s*(STAGEB/2);
        const __nv_bfloat16* sAl = sAh + BUFE;
        const __nv_bfloat16* sBh = sAh + 2*BUFE;
        const __nv_bfloat16* sBl = sAh + 3*BUFE;
#pragma unroll
        for (int kk=0; kk<4; kk++){
            const int k0 = kk*16;
            wmma::fragment<wmma::matrix_a,16,16,16,__nv_bfloat16,wmma::row_major> a_h[2], a_l[2];
#pragma unroll
            for (int mf=0; mf<2; mf++){
                wmma::load_matrix_sync(a_h[mf], sAh + (m0w+mf*16)*ROWE + k0, ROWE);
                wmma::load_matrix_sync(a_l[mf], sAl + (m0w+mf*16)*ROWE + k0, ROWE);
            }
#pragma unroll
            for (int nf=0; nf<4; nf++){
                wmma::fragment<wmma::matrix_b,16,16,16,__nv_bfloat16,wmma::col_major> b_h, b_l;
                wmma::load_matrix_sync(b_h, sBh + (n0w+nf*16)*ROWE + k0, ROWE);
                wmma::load_matrix_sync(b_l, sBl + (n0w+nf*16)*ROWE + k0, ROWE);
#pragma unroll
                for (int mf=0; mf<2; mf++){
                    wmma::mma_sync(acc[mf][nf], a_h[mf], b_h, acc[mf][nf]);
                    wmma::mma_sync(acc[mf][nf], a_h[mf], b_l, acc[mf][nf]);
                    wmma::mma_sync(acc[mf][nf], a_l[mf], b_h, acc[mf][nf]);
                }
            }
        }
        __syncthreads();
    }

    // epilogue: accum -> padded SMEM (128x132 f32) -> coalesced global
    float* eps = (float*)smem;
#pragma unroll
    for (int mf=0; mf<2; mf++)
#pragma unroll
        for (int nf=0; nf<4; nf++)
            wmma::store_matrix_sync(eps + (m0w+mf*16)*132 + n0w + nf*16, acc[mf][nf], 132, wmma::mem_row_major);
    __syncthreads();
    for (int i=tid; i<16384; i+=256){
        const int row = i>>7, col = i&127;
        const float v = eps[row*132+col];
        if (EPI==0){
            size_t o = (size_t)(mb+row)*CDIM + nb + col;
            g_x2[o] = xsrc[o] + v;
        } else if (EPI==1){
            size_t o = (size_t)(mb+row)*2*CDIM + CDIM + nb + col;
            split_store(g_hr_h, g_hr_l, o, v);
        } else if (EPI==2){
            size_t ho = (size_t)(mb+row)*2*CDIM + nb + col;
            float hrec = __bfloat162float(g_hr_h[ho]) + __bfloat162float(g_hr_l[ho]);
            split_store(g_z_h, g_z_l, (size_t)(mb+row)*CDIM + nb + col, hrec + v);
        } else if (EPI==3){
            int r2 = mb+row;
            if (r2 < ne){
                float a;
                if (rwkv){ a = fmaxf(v,0.f); a = a*a; }
                else       a = gelu_tanh(v);
                split_store(g_mid_h, g_mid_l, (size_t)(base+r2)*HDIM + nb + col, a);
            }
        } else {
            int r2 = mb+row;
            if (r2 < ne){
                int slot = base + r2;
                int tt = g_tok[slot];
                float gt = g_gate[slot];
                float* dst = g_rank[slot] ? g_slot1 : g_slot0;
                dst[(size_t)tt*CDIM + nb + col] = gt*v;
            }
        }
    }
    __syncthreads();
}

// ---------------- dense GEMM kernels ----------------
template<int EPI>
__global__ __launch_bounds__(256) void k_dense(
    const __nv_bfloat16* __restrict__ Ah, const __nv_bfloat16* __restrict__ Al, int astride,
    const __nv_bfloat16* __restrict__ Bh, const __nv_bfloat16* __restrict__ Bl, int K,
    const float* __restrict__ xsrc)
{
    extern __shared__ char smem[];
    uint32_t su = smem_to_u32(smem);
    tc_tile<EPI>(smem, su, Ah, Al, astride, 0, Bh, Bl, K,
                 blockIdx.y*128, blockIdx.x*128, 0, 1<<30, 0, xsrc);
}

// ---------------- routed persistent grouped GEMM ----------------
template<int STAGE>
__global__ __launch_bounds__(256) void k_routed(
    const __nv_bfloat16* __restrict__ hr_h, const __nv_bfloat16* __restrict__ hr_l,
    const __nv_bfloat16* __restrict__ z_h,  const __nv_bfloat16* __restrict__ z_l,
    const __nv_bfloat16* __restrict__ mid_h,const __nv_bfloat16* __restrict__ mid_l,
    const __nv_bfloat16* __restrict__ WkT_h,const __nv_bfloat16* __restrict__ WkT_l,
    const __nv_bfloat16* __restrict__ WvT_h,const __nv_bfloat16* __restrict__ WvT_l,
    const __nv_bfloat16* __restrict__ W1T_h,const __nv_bfloat16* __restrict__ W1T_l,
    const __nv_bfloat16* __restrict__ W2T_h,const __nv_bfloat16* __restrict__ W2T_l)
{
    extern __shared__ char smem[];
    __shared__ int s_idx;
    uint32_t su = smem_to_u32(smem);
    const int total = g_toff[STAGE][NEXP];
    for(;;){
        if (threadIdx.x==0) s_idx = (int)atomicAdd(&g_ctr[STAGE], 1u);
        __syncthreads();
        const int idx = s_idx;
        if (idx >= total) break;
        int e = 0;
#pragma unroll
        for (int q=1;q<NEXP;q++) if (idx >= g_toff[STAGE][q]) e = q;
        const int local = idx - g_toff[STAGE][e];
        const int base = g_off[e];
        const int ne = g_off[e+1]-base;
        const bool rwkv = (e < ERWKV);
        const int ntl = (STAGE==0) ? (rwkv ? (HDIM>>7) : (CDIM>>7)) : (CDIM>>7);
        const int mb = (local/ntl)*128;
        const int nb = (local%ntl)*128;
        if (STAGE==0){
            const __nv_bfloat16* Ah = rwkv ? hr_h : z_h;
            const __nv_bfloat16* Al = rwkv ? hr_l : z_l;
            const int astride = rwkv ? 2*CDIM : CDIM;
            const __nv_bfloat16* Bh = rwkv ? (WkT_h + (size_t)e*HDIM*CDIM) : (W1T_h + (size_t)(e-ERWKV)*CDIM*CDIM);
            const __nv_bfloat16* Bl = rwkv ? (WkT_l + (size_t)e*HDIM*CDIM) : (W1T_l + (size_t)(e-ERWKV)*CDIM*CDIM);
            tc_tile<3>(smem, su, Ah, Al, astride, 1, Bh, Bl, CDIM,
                       mb, nb, base, ne, rwkv?1:0, nullptr);
        } else {
            const int K = rwkv ? HDIM : CDIM;
            const __nv_bfloat16* Bh = rwkv ? (WvT_h + (size_t)e*CDIM*HDIM) : (W2T_h + (size_t)(e-ERWKV)*CDIM*CDIM);
            const __nv_bfloat16* Bl = rwkv ? (WvT_l + (size_t)e*CDIM*HDIM) : (W2T_l + (size_t)(e-ERWKV)*CDIM*CDIM);
            tc_tile<4>(smem, su, mid_h, mid_l, HDIM, 2, Bh, Bl, K,
                       mb, nb, base, ne, 0, nullptr);
        }
    }
}

// ---------------- epilogue combine ----------------
__global__ void k_final(const float* __restrict__ vf, float* __restrict__ out){
    const int i = blockIdx.x*256 + threadIdx.x;
    out[i]        = g_x2[i] + g_slot0[i] + g_slot1[i];
    out[OUT_VF+i] = vf[i];
}

// ---------------- launch ----------------
extern "C" void kernel_launch(void* const* d_in, const int* in_sizes, int n_in,
                              void* d_out, int out_size)
{
    const float* x     =(const float*)d_in[0];
    const float* vf    =(const float*)d_in[1];
    const float* cap   =(const float*)d_in[2];
    const float* ln1g  =(const float*)d_in[3];
    const float* ln1b  =(const float*)d_in[4];
    const float* ln2g  =(const float*)d_in[5];
    const float* ln2b  =(const float*)d_in[6];
    const float* Wa    =(const float*)d_in[7];
    const float* Ws    =(const float*)d_in[8];
    const float* wconf =(const float*)d_in[9];
    const float* wdiff =(const float*)d_in[10];
    const float* Waff  =(const float*)d_in[11];
    const float* Wbh   =(const float*)d_in[12];
    const float* Wbs   =(const float*)d_in[13];
    const float* Wk    =(const float*)d_in[14];
    const float* Wv    =(const float*)d_in[15];
    const float* W1    =(const float*)d_in[16];
    const float* W2    =(const float*)d_in[17];
    float* out=(float*)d_out;

    // resolve __device__ symbols to REAL device addresses (host-shadow trap on GB300 ATS)
    void *p_xln_h, *p_xln_l, *p_hr_h, *p_hr_l, *p_z_h, *p_z_l, *p_mid_h, *p_mid_l;
    void *p_WaT_h, *p_WaT_l, *p_WsT_h, *p_WsT_l, *p_WbT_h, *p_WbT_l;
    void *p_WkT_h, *p_WkT_l, *p_WvT_h, *p_WvT_l, *p_W1T_h, *p_W1T_l, *p_W2T_h, *p_W2T_l;
    cudaGetSymbolAddress(&p_xln_h, g_xln_h); cudaGetSymbolAddress(&p_xln_l, g_xln_l);
    cudaGetSymbolAddress(&p_hr_h,  g_hr_h);  cudaGetSymbolAddress(&p_hr_l,  g_hr_l);
    cudaGetSymbolAddress(&p_z_h,   g_z_h);   cudaGetSymbolAddress(&p_z_l,   g_z_l);
    cudaGetSymbolAddress(&p_mid_h, g_mid_h); cudaGetSymbolAddress(&p_mid_l, g_mid_l);
    cudaGetSymbolAddress(&p_WaT_h, g_WaT_h); cudaGetSymbolAddress(&p_WaT_l, g_WaT_l);
    cudaGetSymbolAddress(&p_WsT_h, g_WsT_h); cudaGetSymbolAddress(&p_WsT_l, g_WsT_l);
    cudaGetSymbolAddress(&p_WbT_h, g_WbT_h); cudaGetSymbolAddress(&p_WbT_l, g_WbT_l);
    cudaGetSymbolAddress(&p_WkT_h, g_WkT_h); cudaGetSymbolAddress(&p_WkT_l, g_WkT_l);
    cudaGetSymbolAddress(&p_WvT_h, g_WvT_h); cudaGetSymbolAddress(&p_WvT_l, g_WvT_l);
    cudaGetSymbolAddress(&p_W1T_h, g_W1T_h); cudaGetSymbolAddress(&p_W1T_l, g_W1T_l);
    cudaGetSymbolAddress(&p_W2T_h, g_W2T_h); cudaGetSymbolAddress(&p_W2T_l, g_W2T_l);

    cudaFuncSetAttribute(k_dense<0>, cudaFuncAttributeMaxDynamicSharedMemorySize, SMEM_BYTES);
    cudaFuncSetAttribute(k_dense<1>, cudaFuncAttributeMaxDynamicSharedMemorySize, SMEM_BYTES);
    cudaFuncSetAttribute(k_dense<2>, cudaFuncAttributeMaxDynamicSharedMemorySize, SMEM_BYTES);
    cudaFuncSetAttribute(k_routed<0>, cudaFuncAttributeMaxDynamicSharedMemorySize, SMEM_BYTES);
    cudaFuncSetAttribute(k_routed<1>, cudaFuncAttributeMaxDynamicSharedMemorySize, SMEM_BYTES);

    dim3 tb(32,8);
    k_transpose<<<dim3(32,32,1), tb>>>(Wa,  (__nv_bfloat16*)p_WaT_h, (__nv_bfloat16*)p_WaT_l, CDIM, CDIM, CDIM, 0, 0, 0);
    k_transpose<<<dim3(32,32,1), tb>>>(Ws,  (__nv_bfloat16*)p_WsT_h, (__nv_bfloat16*)p_WsT_l, CDIM, CDIM, CDIM, 0, 0, 0);
    k_transpose<<<dim3(32,32,1), tb>>>(Wbh, (__nv_bfloat16*)p_WbT_h, (__nv_bfloat16*)p_WbT_l, CDIM, CDIM, 2*CDIM, 0,    0, 0);
    k_transpose<<<dim3(32,32,1), tb>>>(Wbs, (__nv_bfloat16*)p_WbT_h, (__nv_bfloat16*)p_WbT_l, CDIM, CDIM, 2*CDIM, CDIM, 0, 0);
    k_transpose<<<dim3(128,32,ERWKV), tb>>>(Wk, (__nv_bfloat16*)p_WkT_h, (__nv_bfloat16*)p_WkT_l, CDIM, HDIM, CDIM, 0,
                                            (long long)CDIM*HDIM, (long long)HDIM*CDIM);
    k_transpose<<<dim3(32,128,ERWKV), tb>>>(Wv, (__nv_bfloat16*)p_WvT_h, (__nv_bfloat16*)p_WvT_l, HDIM, CDIM, HDIM, 0,
                                            (long long)HDIM*CDIM, (long long)CDIM*HDIM);
    k_transpose<<<dim3(32,32,2), tb>>>(W1, (__nv_bfloat16*)p_W1T_h, (__nv_bfloat16*)p_W1T_l, CDIM, CDIM, CDIM, 0,
                                       (long long)CDIM*CDIM, (long long)CDIM*CDIM);
    k_transpose<<<dim3(32,32,2), tb>>>(W2, (__nv_bfloat16*)p_W2T_h, (__nv_bfloat16*)p_W2T_l, CDIM, CDIM, CDIM, 0,
                                       (long long)CDIM*CDIM, (long long)CDIM*CDIM);

    k_ln1<<<BTOK,256>>>(x, ln1g, ln1b);

    dim3 gd(CDIM/128, BTOK/128);
    k_dense<0><<<gd,256,SMEM_BYTES>>>((__nv_bfloat16*)p_xln_h, (__nv_bfloat16*)p_xln_l, CDIM,
                                      (__nv_bfloat16*)p_WaT_h, (__nv_bfloat16*)p_WaT_l, CDIM, x);
    k_dense<1><<<gd,256,SMEM_BYTES>>>((__nv_bfloat16*)p_xln_h, (__nv_bfloat16*)p_xln_l, CDIM,
                                      (__nv_bfloat16*)p_WsT_h, (__nv_bfloat16*)p_WsT_l, CDIM, nullptr);

    k_post1<<<BTOK,256>>>(ln2g, ln2b, wconf, wdiff, Waff, cap, out);
    k_route_setup<<<1,32>>>();
    k_route_fill<<<(BTOK+255)/256,256>>>();

    k_dense<2><<<gd,256,SMEM_BYTES>>>((__nv_bfloat16*)p_hr_h, (__nv_bfloat16*)p_hr_l, 2*CDIM,
                                      (__nv_bfloat16*)p_WbT_h, (__nv_bfloat16*)p_WbT_l, 2*CDIM, nullptr);

    k_routed<0><<<148,256,SMEM_BYTES>>>((__nv_bfloat16*)p_hr_h,(__nv_bfloat16*)p_hr_l,
        (__nv_bfloat16*)p_z_h,(__nv_bfloat16*)p_z_l,(__nv_bfloat16*)p_mid_h,(__nv_bfloat16*)p_mid_l,
        (__nv_bfloat16*)p_WkT_h,(__nv_bfloat16*)p_WkT_l,(__nv_bfloat16*)p_WvT_h,(__nv_bfloat16*)p_WvT_l,
        (__nv_bfloat16*)p_W1T_h,(__nv_bfloat16*)p_W1T_l,(__nv_bfloat16*)p_W2T_h,(__nv_bfloat16*)p_W2T_l);
    k_routed<1><<<148,256,SMEM_BYTES>>>((__nv_bfloat16*)p_hr_h,(__nv_bfloat16*)p_hr_l,
        (__nv_bfloat16*)p_z_h,(__nv_bfloat16*)p_z_l,(__nv_bfloat16*)p_mid_h,(__nv_bfloat16*)p_mid_l,
        (__nv_bfloat16*)p_WkT_h,(__nv_bfloat16*)p_WkT_l,(__nv_bfloat16*)p_WvT_h,(__nv_bfloat16*)p_WvT_l,
        (__nv_bfloat16*)p_W1T_h,(__nv_bfloat16*)p_W1T_l,(__nv_bfloat16*)p_W2T_h,(__nv_bfloat16*)p_W2T_l);

    k_final<<<BTOK*CDIM/256,256>>>(vf, out);
}

// round 9
// speedup vs baseline: 1.7770x; 1.0484x over previous
#include <cuda_runtime.h>
#include <cuda_bf16.h>
#include <mma.h>
#include <math.h>
#include <stdint.h>

using namespace nvcuda;

#define BTOK 4096
#define CDIM 1024
#define HDIM 4096
#define NEXP 8
#define ERWKV 6
#define MAXS (2*BTOK)
#define MIDROWS (MAXS+256)

#define OUT_VF   (BTOK*CDIM)
#define OUT_WIN  (2*BTOK*CDIM)
#define OUT_COST (OUT_WIN + 2*BTOK)
#define OUT_DIFF (OUT_COST + BTOK)
#define OUT_AFF  (OUT_DIFF + BTOK)

// ---------------- SMEM layout ----------------
// stage: Ah(256 rows), Al(256), Bh(128), Bl(128); row = 64 bf16 data + 8 pad = 144B
#define ROWE   72
#define ABUFE  (256*ROWE)              // 18432 elements
#define BBUFE  (128*ROWE)              // 9216 elements
#define STAGEB ((2*ABUFE + 2*BBUFE)*2) // 110592 bytes
#define SM_AOFF  (2*STAGEB)            // 221184: 256 * 8B A-row offsets
#define SMEM_BYTES (SM_AOFF + 2048)    // 223232
// epilogue f32 scratch 256x132 (135168 B) overlaps stages (used after compute)

// ---------------- scratch (static device memory) ----------------
__device__ __nv_bfloat16 g_xln_h[BTOK*CDIM], g_xln_l[BTOK*CDIM];
__device__ float g_x2[BTOK*CDIM];
__device__ __nv_bfloat16 g_hr_h[(size_t)BTOK*2*CDIM], g_hr_l[(size_t)BTOK*2*CDIM]; // [tok][0:1024)=h, [1024:2048)=rs
__device__ __nv_bfloat16 g_z_h[BTOK*CDIM], g_z_l[BTOK*CDIM];
__device__ __nv_bfloat16 g_mid_h[(size_t)MIDROWS*HDIM], g_mid_l[(size_t)MIDROWS*HDIM];
__device__ float g_slot0[BTOK*CDIM], g_slot1[BTOK*CDIM];

// transposed + split weights ([N][K] K-major)
__device__ __nv_bfloat16 g_WaT_h[CDIM*CDIM], g_WaT_l[CDIM*CDIM];
__device__ __nv_bfloat16 g_WsT_h[CDIM*CDIM], g_WsT_l[CDIM*CDIM];
__device__ __nv_bfloat16 g_WbT_h[(size_t)CDIM*2*CDIM], g_WbT_l[(size_t)CDIM*2*CDIM];
__device__ __nv_bfloat16 g_WkT_h[(size_t)ERWKV*HDIM*CDIM], g_WkT_l[(size_t)ERWKV*HDIM*CDIM];
__device__ __nv_bfloat16 g_WvT_h[(size_t)ERWKV*CDIM*HDIM], g_WvT_l[(size_t)ERWKV*CDIM*HDIM];
__device__ __nv_bfloat16 g_W1T_h[2*CDIM*CDIM], g_W1T_l[2*CDIM*CDIM];
__device__ __nv_bfloat16 g_W2T_h[2*CDIM*CDIM], g_W2T_l[2*CDIM*CDIM];

// routing
__device__ int   g_win[2*BTOK];
__device__ float g_wt [2*BTOK];
__device__ int   g_cnt[NEXP];
__device__ int   g_off[NEXP+1];
__device__ int   g_cur[NEXP];
__device__ int   g_tok[MAXS];
__device__ float g_gate[MAXS];
__device__ int   g_rank[MAXS];
__device__ int   g_toff[2][NEXP+1];
__device__ unsigned int g_ctr[2];

// ---------------- helpers ----------------
__device__ __forceinline__ uint32_t smem_to_u32(const void* p) {
    uint32_t a;
    asm("{ .reg .u64 t; cvta.to.shared.u64 t, %1; cvt.u32.u64 %0, t; }" : "=r"(a) : "l"(p));
    return a;
}
#define CP_ASYNC16(dst, src) \
    asm volatile("cp.async.cg.shared.global [%0], [%1], 16;" :: "r"(dst), "l"(src) : "memory")
#define CP_COMMIT() asm volatile("cp.async.commit_group;" ::: "memory")
#define CP_WAIT(n)  asm volatile("cp.async.wait_group %0;" :: "n"(n) : "memory")

__device__ __forceinline__ float gelu_tanh(float x){
    float x3 = x*x*x;
    return 0.5f*x*(1.0f + tanhf(0.7978845608028654f*(x + 0.044715f*x3)));
}
__device__ __forceinline__ void split_store(__nv_bfloat16* ph, __nv_bfloat16* pl, size_t o, float v){
    __nv_bfloat16 hi = __float2bfloat16(v);
    ph[o] = hi;
    pl[o] = __float2bfloat16(v - __bfloat162float(hi));
}

// ---------------- weight transpose+split ----------------
__global__ void k_transpose(const float* __restrict__ src, __nv_bfloat16* __restrict__ dh,
                            __nv_bfloat16* __restrict__ dl, int K, int N, int dstride, int coloff,
                            long long sBatch, long long dBatch)
{
    __shared__ float t[32][33];
    const int bz = blockIdx.z;
    src += (long long)bz*sBatch;
    dh  += (long long)bz*dBatch;
    dl  += (long long)bz*dBatch;
    const int k0 = blockIdx.y*32, n0 = blockIdx.x*32;
    const int tx = threadIdx.x, ty = threadIdx.y;
#pragma unroll
    for (int j=0;j<4;j++) t[ty+8*j][tx] = src[(size_t)(k0+ty+8*j)*N + n0+tx];
    __syncthreads();
#pragma unroll
    for (int j=0;j<4;j++){
        float v = t[tx][ty+8*j];
        size_t o = (size_t)(n0+ty+8*j)*dstride + coloff + k0 + tx;
        __nv_bfloat16 hi = __float2bfloat16(v);
        dh[o]=hi; dl[o]=__float2bfloat16(v - __bfloat162float(hi));
    }
}

// ---------------- LN1 ----------------
__global__ void k_ln1(const float* __restrict__ x, const float* __restrict__ g1,
                      const float* __restrict__ b1)
{
    const int t = blockIdx.x;
    const int tid = threadIdx.x;
    if (t == 0 && tid < NEXP) g_cnt[tid] = 0;
    __shared__ float red[256];
    const float* xr = x + (size_t)t*CDIM;
    float v[4]; float s = 0.f;
#pragma unroll
    for (int q=0;q<4;q++){ v[q]=xr[tid+256*q]; s+=v[q]; }
    red[tid]=s; __syncthreads();
    for(int st=128;st>0;st>>=1){ if(tid<st) red[tid]+=red[tid+st]; __syncthreads(); }
    const float m = red[0]*(1.0f/CDIM);
    __syncthreads();
    float s2=0.f;
#pragma unroll
    for(int q=0;q<4;q++){ float d=v[q]-m; s2+=d*d; }
    red[tid]=s2; __syncthreads();
    for(int st=128;st>0;st>>=1){ if(tid<st) red[tid]+=red[tid+st]; __syncthreads(); }
    const float rstd = rsqrtf(red[0]*(1.0f/CDIM)+1e-5f);
#pragma unroll
    for(int q=0;q<4;q++){
        int i=tid+256*q;
        float xv=(v[q]-m)*rstd*g1[i]+b1[i];
        split_store(g_xln_h, g_xln_l, (size_t)t*CDIM+i, xv);
    }
}

// ---------------- LN2 + router ----------------
__global__ void k_post1(const float* __restrict__ g2, const float* __restrict__ b2,
                        const float* __restrict__ w_conf, const float* __restrict__ w_diff,
                        const float* __restrict__ W_aff, const float* __restrict__ cap,
                        float* __restrict__ out)
{
    const int t = blockIdx.x;
    const int tid = threadIdx.x;
    __shared__ float red[256];
    __shared__ float sh[CDIM];
    __shared__ float sconf[NEXP], saff[NEXP];
    __shared__ float sdiff;
    const float* xr = g_x2 + (size_t)t*CDIM;
    float v[4]; float s=0.f;
#pragma unroll
    for(int q=0;q<4;q++){ v[q]=xr[tid+256*q]; s+=v[q]; }
    red[tid]=s; __syncthreads();
    for(int st=128;st>0;st>>=1){ if(tid<st) red[tid]+=red[tid+st]; __syncthreads(); }
    const float m=red[0]*(1.0f/CDIM);
    __syncthreads();
    float s2=0.f;
#pragma unroll
    for(int q=0;q<4;q++){ float d=v[q]-m; s2+=d*d; }
    red[tid]=s2; __syncthreads();
    for(int st=128;st>0;st>>=1){ if(tid<st) red[tid]+=red[tid+st]; __syncthreads(); }
    const float rstd=rsqrtf(red[0]*(1.0f/CDIM)+1e-5f);
#pragma unroll
    for(int q=0;q<4;q++){
        int i=tid+256*q;
        float hv=(v[q]-m)*rstd*g2[i]+b2[i];
        sh[i]=hv;
        split_store(g_hr_h, g_hr_l, (size_t)t*2*CDIM+i, hv);
    }
    __syncthreads();
    const int w=tid>>5, lane=tid&31;
    float cd=0.f, ad=0.f, dd=0.f;
    for(int i=lane;i<CDIM;i+=32){
        float hv=sh[i];
        cd = fmaf(hv, w_conf[w*CDIM+i], cd);
        ad = fmaf(hv, W_aff[i*NEXP+w], ad);
        if(w==0) dd = fmaf(hv, w_diff[i], dd);
    }
#pragma unroll
    for(int o=16;o>0;o>>=1){
        cd += __shfl_down_sync(0xffffffffu, cd, o);
        ad += __shfl_down_sync(0xffffffffu, ad, o);
        dd += __shfl_down_sync(0xffffffffu, dd, o);
    }
    if(lane==0){ sconf[w]=cd; saff[w]=ad; if(w==0) sdiff=dd; }
    __syncthreads();
    if(tid<NEXP) out[OUT_AFF + t*NEXP + tid] = saff[tid];
    if(tid==0){
        float diff = fmaxf(sdiff,0.f) + log1pf(expf(-fabsf(sdiff)));
        float b0=-INFINITY, b1v=-INFINITY; int e0=0,e1=0;
#pragma unroll
        for(int e=0;e<NEXP;e++){
            float conf = 1.0f/(1.0f+expf(-sconf[e]));
            float bid = fmaf(conf, cap[e], saff[e]);
            if(bid>b0){ b1v=b0;e1=e0;b0=bid;e0=e; }
            else if(bid>b1v){ b1v=bid;e1=e; }
        }
        float ex = expf(b1v-b0);
        float w0 = 1.0f/(1.0f+ex);
        float w1 = ex/(1.0f+ex);
        out[OUT_WIN + 2*t]   = (float)e0;
        out[OUT_WIN + 2*t+1] = (float)e1;
        out[OUT_COST + t] = (b0*w0 + b1v*w1)*diff;
        out[OUT_DIFF + t] = diff;
        g_win[2*t]=e0; g_win[2*t+1]=e1;
        g_wt[2*t]=w0;  g_wt[2*t+1]=w1;
        atomicAdd(&g_cnt[e0],1);
        atomicAdd(&g_cnt[e1],1);
    }
}

// ---------------- routing setup/fill ----------------
__global__ void k_route_setup(){
    if(threadIdx.x==0){
        int o=0;
        for(int e=0;e<NEXP;e++){ g_off[e]=o; o+=g_cnt[e]; }
        g_off[NEXP]=o;
        int t1=0,t2=0;
        for(int e=0;e<NEXP;e++){
            g_cur[e]=g_off[e];
            int mt=(g_cnt[e]+255)>>8;
            int nt1=(e<ERWKV)?(HDIM>>7):(CDIM>>7);
            g_toff[0][e]=t1; t1+=mt*nt1;
            g_toff[1][e]=t2; t2+=mt*(CDIM>>7);
        }
        g_toff[0][NEXP]=t1; g_toff[1][NEXP]=t2;
        g_ctr[0]=0u; g_ctr[1]=0u;
    }
}
__global__ void k_route_fill(){
    int t = blockIdx.x*blockDim.x + threadIdx.x;
    if(t<BTOK){
#pragma unroll
        for(int r=0;r<2;r++){
            int e=g_win[2*t+r];
            int p=atomicAdd(&g_cur[e],1);
            g_tok[p]=t; g_gate[p]=g_wt[2*t+r]; g_rank[p]=r;
        }
    }
}

// ---------------- async chunk loader: Ah/Al 256 rows + Bh/Bl 128 rows (128B each) ----------------
__device__ __forceinline__ void issue_chunk(uint32_t su, const long long* s_aoff,
    const __nv_bfloat16* __restrict__ Ah, const __nv_bfloat16* __restrict__ Al,
    const __nv_bfloat16* __restrict__ Bh, const __nv_bfloat16* __restrict__ Bl,
    int K, int nb, int s, int c0)
{
    const int tid = threadIdx.x;
    const uint32_t stage = su + (uint32_t)s*STAGEB;
#pragma unroll
    for (int j=0; j<3; j++){
        const int r = tid + 256*j;       // 0..767
        const __nv_bfloat16* src;
        uint32_t dst;
        if (r < 512){
            const int arow = r & 255;
            src = ((r<256)? Ah : Al) + s_aoff[arow] + c0;
            dst = stage + (uint32_t)((r<256)? 0 : ABUFE*2) + (uint32_t)arow*144u;
        } else {
            const int brow = (r - 512) & 127;
            src = ((r<640)? Bh : Bl) + (long long)(nb + brow)*K + c0;
            dst = stage + (uint32_t)(2*ABUFE*2) + (uint32_t)((r<640)? 0 : BBUFE*2) + (uint32_t)brow*144u;
        }
#pragma unroll
        for (int i=0;i<8;i++){
            CP_ASYNC16(dst + i*16, src + i*8);
        }
    }
    CP_COMMIT();
}

// ---------------- wmma tile core (256x128 tile, warp 64x64, double-buffered) ----------------
template<int EPI>
__device__ void tc_tile(char* smem, uint32_t su,
    const __nv_bfloat16* __restrict__ Ah, const __nv_bfloat16* __restrict__ Al,
    int astride, int amode,
    const __nv_bfloat16* __restrict__ Bh, const __nv_bfloat16* __restrict__ Bl, int K,
    int mb, int nb, int base, int ne, int rwkv,
    const float* __restrict__ xsrc)
{
    const int tid = threadIdx.x;
    __nv_bfloat16* sbuf = (__nv_bfloat16*)smem;
    long long* s_aoff = (long long*)(smem + SM_AOFF);
    {
        int r = tid;
        long long off;
        if (amode==0)      off = (long long)(mb+r)*astride;
        else if (amode==1){ int row=mb+r; int tk = (row<ne)? g_tok[base+row] : g_tok[base]; off=(long long)tk*astride; }
        else               off = (long long)(base+mb+r)*astride;
        s_aoff[r] = off;
    }
    __syncthreads();

    const int wid = tid>>5;
    const int m0w = (wid&3)*64;        // 4 warps in M (256)
    const int n0w = (wid>>2)*64;       // 2 warps in N (128)

    wmma::fragment<wmma::accumulator,16,16,16,float> acc[4][4];
#pragma unroll
    for (int i=0;i<4;i++)
#pragma unroll
        for (int j=0;j<4;j++) wmma::fill_fragment(acc[i][j], 0.0f);

    const int nch = K >> 6;
    issue_chunk(su, s_aoff, Ah, Al, Bh, Bl, K, nb, 0, 0);

    for (int c=0; c<nch; c++){
        const int s = c & 1;
        if (c+1 < nch){
            issue_chunk(su, s_aoff, Ah, Al, Bh, Bl, K, nb, (c+1)&1, (c+1)<<6);
            CP_WAIT(1);
        } else {
            CP_WAIT(0);
        }
        __syncthreads();

        const __nv_bfloat16* sAh = sbuf + (size_t)s*(STAGEB/2);
        const __nv_bfloat16* sAl = sAh + ABUFE;
        const __nv_bfloat16* sBh = sAh + 2*ABUFE;
        const __nv_bfloat16* sBl = sBh + BBUFE;
#pragma unroll
        for (int kk=0; kk<4; kk++){
            const int k0 = kk*16;
            wmma::fragment<wmma::matrix_a,16,16,16,__nv_bfloat16,wmma::row_major> a_h[4], a_l[4];
#pragma unroll
            for (int mf=0; mf<4; mf++){
                wmma::load_matrix_sync(a_h[mf], sAh + (m0w+mf*16)*ROWE + k0, ROWE);
                wmma::load_matrix_sync(a_l[mf], sAl + (m0w+mf*16)*ROWE + k0, ROWE);
            }
#pragma unroll
            for (int nf=0; nf<4; nf++){
                wmma::fragment<wmma::matrix_b,16,16,16,__nv_bfloat16,wmma::col_major> b_h, b_l;
                wmma::load_matrix_sync(b_h, sBh + (n0w+nf*16)*ROWE + k0, ROWE);
                wmma::load_matrix_sync(b_l, sBl + (n0w+nf*16)*ROWE + k0, ROWE);
#pragma unroll
                for (int mf=0; mf<4; mf++){
                    wmma::mma_sync(acc[mf][nf], a_h[mf], b_h, acc[mf][nf]);
                    wmma::mma_sync(acc[mf][nf], a_h[mf], b_l, acc[mf][nf]);
                    wmma::mma_sync(acc[mf][nf], a_l[mf], b_h, acc[mf][nf]);
                }
            }
        }
        __syncthreads();
    }

    // epilogue: accum -> padded SMEM (256x132 f32) -> coalesced global
    float* eps = (float*)smem;
#pragma unroll
    for (int mf=0; mf<4; mf++)
#pragma unroll
        for (int nf=0; nf<4; nf++)
            wmma::store_matrix_sync(eps + (size_t)(m0w+mf*16)*132 + n0w + nf*16, acc[mf][nf], 132, wmma::mem_row_major);
    __syncthreads();
    for (int i=tid; i<32768; i+=256){
        const int row = i>>7, col = i&127;
        const float v = eps[(size_t)row*132+col];
        if (EPI==0){
            size_t o = (size_t)(mb+row)*CDIM + nb + col;
            g_x2[o] = xsrc[o] + v;
        } else if (EPI==1){
            size_t o = (size_t)(mb+row)*2*CDIM + CDIM + nb + col;
            split_store(g_hr_h, g_hr_l, o, v);
        } else if (EPI==2){
            size_t ho = (size_t)(mb+row)*2*CDIM + nb + col;
            float hrec = __bfloat162float(g_hr_h[ho]) + __bfloat162float(g_hr_l[ho]);
            split_store(g_z_h, g_z_l, (size_t)(mb+row)*CDIM + nb + col, hrec + v);
        } else if (EPI==3){
            int r2 = mb+row;
            if (r2 < ne){
                float a;
                if (rwkv){ a = fmaxf(v,0.f); a = a*a; }
                else       a = gelu_tanh(v);
                split_store(g_mid_h, g_mid_l, (size_t)(base+r2)*HDIM + nb + col, a);
            }
        } else {
            int r2 = mb+row;
            if (r2 < ne){
                int slot = base + r2;
                int tt = g_tok[slot];
                float gt = g_gate[slot];
                float* dst = g_rank[slot] ? g_slot1 : g_slot0;
                dst[(size_t)tt*CDIM + nb + col] = gt*v;
            }
        }
    }
    __syncthreads();
}

// ---------------- dense GEMM kernels ----------------
template<int EPI>
__global__ __launch_bounds__(256,1) void k_dense(
    const __nv_bfloat16* __restrict__ Ah, const __nv_bfloat16* __restrict__ Al, int astride,
    const __nv_bfloat16* __restrict__ Bh, const __nv_bfloat16* __restrict__ Bl, int K,
    const float* __restrict__ xsrc)
{
    extern __shared__ char smem[];
    uint32_t su = smem_to_u32(smem);
    tc_tile<EPI>(smem, su, Ah, Al, astride, 0, Bh, Bl, K,
                 blockIdx.y*256, blockIdx.x*128, 0, 1<<30, 0, xsrc);
}

// ---------------- routed persistent grouped GEMM ----------------
template<int STAGE>
__global__ __launch_bounds__(256,1) void k_routed(
    const __nv_bfloat16* __restrict__ hr_h, const __nv_bfloat16* __restrict__ hr_l,
    const __nv_bfloat16* __restrict__ z_h,  const __nv_bfloat16* __restrict__ z_l,
    const __nv_bfloat16* __restrict__ mid_h,const __nv_bfloat16* __restrict__ mid_l,
    const __nv_bfloat16* __restrict__ WkT_h,const __nv_bfloat16* __restrict__ WkT_l,
    const __nv_bfloat16* __restrict__ WvT_h,const __nv_bfloat16* __restrict__ WvT_l,
    const __nv_bfloat16* __restrict__ W1T_h,const __nv_bfloat16* __restrict__ W1T_l,
    const __nv_bfloat16* __restrict__ W2T_h,const __nv_bfloat16* __restrict__ W2T_l)
{
    extern __shared__ char smem[];
    __shared__ int s_idx;
    uint32_t su = smem_to_u32(smem);
    const int total = g_toff[STAGE][NEXP];
    for(;;){
        if (threadIdx.x==0) s_idx = (int)atomicAdd(&g_ctr[STAGE], 1u);
        __syncthreads();
        const int idx = s_idx;
        if (idx >= total) break;
        int e = 0;
#pragma unroll
        for (int q=1;q<NEXP;q++) if (idx >= g_toff[STAGE][q]) e = q;
        const int local = idx - g_toff[STAGE][e];
        const int base = g_off[e];
        const int ne = g_off[e+1]-base;
        const bool rwkv = (e < ERWKV);
        const int ntl = (STAGE==0) ? (rwkv ? (HDIM>>7) : (CDIM>>7)) : (CDIM>>7);
        const int mb = (local/ntl)*256;
        const int nb = (local%ntl)*128;
        if (STAGE==0){
            const __nv_bfloat16* Ah = rwkv ? hr_h : z_h;
            const __nv_bfloat16* Al = rwkv ? hr_l : z_l;
            const int astride = rwkv ? 2*CDIM : CDIM;
            const __nv_bfloat16* Bh = rwkv ? (WkT_h + (size_t)e*HDIM*CDIM) : (W1T_h + (size_t)(e-ERWKV)*CDIM*CDIM);
            const __nv_bfloat16* Bl = rwkv ? (WkT_l + (size_t)e*HDIM*CDIM) : (W1T_l + (size_t)(e-ERWKV)*CDIM*CDIM);
            tc_tile<3>(smem, su, Ah, Al, astride, 1, Bh, Bl, CDIM,
                       mb, nb, base, ne, rwkv?1:0, nullptr);
        } else {
            const int K = rwkv ? HDIM : CDIM;
            const __nv_bfloat16* Bh = rwkv ? (WvT_h + (size_t)e*CDIM*HDIM) : (W2T_h + (size_t)(e-ERWKV)*CDIM*CDIM);
            const __nv_bfloat16* Bl = rwkv ? (WvT_l + (size_t)e*CDIM*HDIM) : (W2T_l + (size_t)(e-ERWKV)*CDIM*CDIM);
            tc_tile<4>(smem, su, mid_h, mid_l, HDIM, 2, Bh, Bl, K,
                       mb, nb, base, ne, 0, nullptr);
        }
    }
}

// ---------------- epilogue combine ----------------
__global__ void k_final(const float* __restrict__ vf, float* __restrict__ out){
    const int i = blockIdx.x*256 + threadIdx.x;
    out[i]        = g_x2[i] + g_slot0[i] + g_slot1[i];
    out[OUT_VF+i] = vf[i];
}

// ---------------- launch ----------------
extern "C" void kernel_launch(void* const* d_in, const int* in_sizes, int n_in,
                              void* d_out, int out_size)
{
    const float* x     =(const float*)d_in[0];
    const float* vf    =(const float*)d_in[1];
    const float* cap   =(const float*)d_in[2];
    const float* ln1g  =(const float*)d_in[3];
    const float* ln1b  =(const float*)d_in[4];
    const float* ln2g  =(const float*)d_in[5];
    const float* ln2b  =(const float*)d_in[6];
    const float* Wa    =(const float*)d_in[7];
    const float* Ws    =(const float*)d_in[8];
    const float* wconf =(const float*)d_in[9];
    const float* wdiff =(const float*)d_in[10];
    const float* Waff  =(const float*)d_in[11];
    const float* Wbh   =(const float*)d_in[12];
    const float* Wbs   =(const float*)d_in[13];
    const float* Wk    =(const float*)d_in[14];
    const float* Wv    =(const float*)d_in[15];
    const float* W1    =(const float*)d_in[16];
    const float* W2    =(const float*)d_in[17];
    float* out=(float*)d_out;

    // resolve __device__ symbols to REAL device addresses (host-shadow trap on GB300 ATS)
    void *p_xln_h, *p_xln_l, *p_hr_h, *p_hr_l, *p_z_h, *p_z_l, *p_mid_h, *p_mid_l;
    void *p_WaT_h, *p_WaT_l, *p_WsT_h, *p_WsT_l, *p_WbT_h, *p_WbT_l;
    void *p_WkT_h, *p_WkT_l, *p_WvT_h, *p_WvT_l, *p_W1T_h, *p_W1T_l, *p_W2T_h, *p_W2T_l;
    cudaGetSymbolAddress(&p_xln_h, g_xln_h); cudaGetSymbolAddress(&p_xln_l, g_xln_l);
    cudaGetSymbolAddress(&p_hr_h,  g_hr_h);  cudaGetSymbolAddress(&p_hr_l,  g_hr_l);
    cudaGetSymbolAddress(&p_z_h,   g_z_h);   cudaGetSymbolAddress(&p_z_l,   g_z_l);
    cudaGetSymbolAddress(&p_mid_h, g_mid_h); cudaGetSymbolAddress(&p_mid_l, g_mid_l);
    cudaGetSymbolAddress(&p_WaT_h, g_WaT_h); cudaGetSymbolAddress(&p_WaT_l, g_WaT_l);
    cudaGetSymbolAddress(&p_WsT_h, g_WsT_h); cudaGetSymbolAddress(&p_WsT_l, g_WsT_l);
    cudaGetSymbolAddress(&p_WbT_h, g_WbT_h); cudaGetSymbolAddress(&p_WbT_l, g_WbT_l);
    cudaGetSymbolAddress(&p_WkT_h, g_WkT_h); cudaGetSymbolAddress(&p_WkT_l, g_WkT_l);
    cudaGetSymbolAddress(&p_WvT_h, g_WvT_h); cudaGetSymbolAddress(&p_WvT_l, g_WvT_l);
    cudaGetSymbolAddress(&p_W1T_h, g_W1T_h); cudaGetSymbolAddress(&p_W1T_l, g_W1T_l);
    cudaGetSymbolAddress(&p_W2T_h, g_W2T_h); cudaGetSymbolAddress(&p_W2T_l, g_W2T_l);

    cudaFuncSetAttribute(k_dense<0>, cudaFuncAttributeMaxDynamicSharedMemorySize, SMEM_BYTES);
    cudaFuncSetAttribute(k_dense<1>, cudaFuncAttributeMaxDynamicSharedMemorySize, SMEM_BYTES);
    cudaFuncSetAttribute(k_dense<2>, cudaFuncAttributeMaxDynamicSharedMemorySize, SMEM_BYTES);
    cudaFuncSetAttribute(k_routed<0>, cudaFuncAttributeMaxDynamicSharedMemorySize, SMEM_BYTES);
    cudaFuncSetAttribute(k_routed<1>, cudaFuncAttributeMaxDynamicSharedMemorySize, SMEM_BYTES);

    dim3 tb(32,8);
    k_transpose<<<dim3(32,32,1), tb>>>(Wa,  (__nv_bfloat16*)p_WaT_h, (__nv_bfloat16*)p_WaT_l, CDIM, CDIM, CDIM, 0, 0, 0);
    k_transpose<<<dim3(32,32,1), tb>>>(Ws,  (__nv_bfloat16*)p_WsT_h, (__nv_bfloat16*)p_WsT_l, CDIM, CDIM, CDIM, 0, 0, 0);
    k_transpose<<<dim3(32,32,1), tb>>>(Wbh, (__nv_bfloat16*)p_WbT_h, (__nv_bfloat16*)p_WbT_l, CDIM, CDIM, 2*CDIM, 0,    0, 0);
    k_transpose<<<dim3(32,32,1), tb>>>(Wbs, (__nv_bfloat16*)p_WbT_h, (__nv_bfloat16*)p_WbT_l, CDIM, CDIM, 2*CDIM, CDIM, 0, 0);
    k_transpose<<<dim3(128,32,ERWKV), tb>>>(Wk, (__nv_bfloat16*)p_WkT_h, (__nv_bfloat16*)p_WkT_l, CDIM, HDIM, CDIM, 0,
                                            (long long)CDIM*HDIM, (long long)HDIM*CDIM);
    k_transpose<<<dim3(32,128,ERWKV), tb>>>(Wv, (__nv_bfloat16*)p_WvT_h, (__nv_bfloat16*)p_WvT_l, HDIM, CDIM, HDIM, 0,
                                            (long long)HDIM*CDIM, (long long)CDIM*HDIM);
    k_transpose<<<dim3(32,32,2), tb>>>(W1, (__nv_bfloat16*)p_W1T_h, (__nv_bfloat16*)p_W1T_l, CDIM, CDIM, CDIM, 0,
                                       (long long)CDIM*CDIM, (long long)CDIM*CDIM);
    k_transpose<<<dim3(32,32,2), tb>>>(W2, (__nv_bfloat16*)p_W2T_h, (__nv_bfloat16*)p_W2T_l, CDIM, CDIM, CDIM, 0,
                                       (long long)CDIM*CDIM, (long long)CDIM*CDIM);

    k_ln1<<<BTOK,256>>>(x, ln1g, ln1b);

    dim3 gd(CDIM/128, BTOK/256);
    k_dense<0><<<gd,256,SMEM_BYTES>>>((__nv_bfloat16*)p_xln_h, (__nv_bfloat16*)p_xln_l, CDIM,
                                      (__nv_bfloat16*)p_WaT_h, (__nv_bfloat16*)p_WaT_l, CDIM, x);
    k_dense<1><<<gd,256,SMEM_BYTES>>>((__nv_bfloat16*)p_xln_h, (__nv_bfloat16*)p_xln_l, CDIM,
                                      (__nv_bfloat16*)p_WsT_h, (__nv_bfloat16*)p_WsT_l, CDIM, nullptr);

    k_post1<<<BTOK,256>>>(ln2g, ln2b, wconf, wdiff, Waff, cap, out);
    k_route_setup<<<1,32>>>();
    k_route_fill<<<(BTOK+255)/256,256>>>();

    k_dense<2><<<gd,256,SMEM_BYTES>>>((__nv_bfloat16*)p_hr_h, (__nv_bfloat16*)p_hr_l, 2*CDIM,
                                      (__nv_bfloat16*)p_WbT_h, (__nv_bfloat16*)p_WbT_l, 2*CDIM, nullptr);

    k_routed<0><<<148,256,SMEM_BYTES>>>((__nv_bfloat16*)p_hr_h,(__nv_bfloat16*)p_hr_l,
        (__nv_bfloat16*)p_z_h,(__nv_bfloat16*)p_z_l,(__nv_bfloat16*)p_mid_h,(__nv_bfloat16*)p_mid_l,
        (__nv_bfloat16*)p_WkT_h,(__nv_bfloat16*)p_WkT_l,(__nv_bfloat16*)p_WvT_h,(__nv_bfloat16*)p_WvT_l,
        (__nv_bfloat16*)p_W1T_h,(__nv_bfloat16*)p_W1T_l,(__nv_bfloat16*)p_W2T_h,(__nv_bfloat16*)p_W2T_l);
    k_routed<1><<<148,256,SMEM_BYTES>>>((__nv_bfloat16*)p_hr_h,(__nv_bfloat16*)p_hr_l,
        (__nv_bfloat16*)p_z_h,(__nv_bfloat16*)p_z_l,(__nv_bfloat16*)p_mid_h,(__nv_bfloat16*)p_mid_l,
        (__nv_bfloat16*)p_WkT_h,(__nv_bfloat16*)p_WkT_l,(__nv_bfloat16*)p_WvT_h,(__nv_bfloat16*)p_WvT_l,
        (__nv_bfloat16*)p_W1T_h,(__nv_bfloat16*)p_W1T_l,(__nv_bfloat16*)p_W2T_h,(__nv_bfloat16*)p_W2T_l);

    k_final<<<BTOK*CDIM/256,256>>>(vf, out);
}

// round 10
// speedup vs baseline: 2.2914x; 1.2895x over previous
#include <cuda_runtime.h>
#include <cuda_fp16.h>
#include <mma.h>
#include <math.h>
#include <stdint.h>

using namespace nvcuda;

#define BTOK 4096
#define CDIM 1024
#define HDIM 4096
#define NEXP 8
#define ERWKV 6
#define MAXS (2*BTOK)
#define MIDROWS (MAXS+256)

#define OUT_VF   (BTOK*CDIM)
#define OUT_WIN  (2*BTOK*CDIM)
#define OUT_COST (OUT_WIN + 2*BTOK)
#define OUT_DIFF (OUT_COST + BTOK)
#define OUT_AFF  (OUT_DIFF + BTOK)

// ---------------- SMEM layout ----------------
// stage: Ah(256 rows), Al(256), Bh(128), Bl(128); row = 64 fp16 data + 8 pad = 144B
#define ROWE   72
#define ABUFE  (256*ROWE)              // 18432 elements
#define BBUFE  (128*ROWE)              // 9216 elements
#define STAGEB ((2*ABUFE + 2*BBUFE)*2) // 110592 bytes
#define SM_AOFF  (2*STAGEB)            // 221184: 256 * 8B A-row offsets
#define SMEM_BYTES (SM_AOFF + 2048)    // 223232

// ---------------- scratch (static device memory) ----------------
__device__ __half g_xln_h[BTOK*CDIM], g_xln_l[BTOK*CDIM];
__device__ float g_x2[BTOK*CDIM];
__device__ __half g_hr_h[(size_t)BTOK*2*CDIM], g_hr_l[(size_t)BTOK*2*CDIM]; // [tok][0:1024)=h, [1024:2048)=rs
__device__ __half g_z_h[BTOK*CDIM], g_z_l[BTOK*CDIM];
__device__ __half g_mid_h[(size_t)MIDROWS*HDIM], g_mid_l[(size_t)MIDROWS*HDIM];
__device__ float g_slot0[BTOK*CDIM], g_slot1[BTOK*CDIM];

// transposed + split weights ([N][K] K-major)
__device__ __half g_WaT_h[CDIM*CDIM], g_WaT_l[CDIM*CDIM];
__device__ __half g_WsT_h[CDIM*CDIM];
__device__ __half g_WbT_h[(size_t)CDIM*2*CDIM];
__device__ __half g_WkT_h[(size_t)ERWKV*HDIM*CDIM];
__device__ __half g_WvT_h[(size_t)ERWKV*CDIM*HDIM];
__device__ __half g_W1T_h[2*CDIM*CDIM];
__device__ __half g_W2T_h[2*CDIM*CDIM];

// routing
__device__ int   g_win[2*BTOK];
__device__ float g_wt [2*BTOK];
__device__ int   g_cnt[NEXP];
__device__ int   g_off[NEXP+1];
__device__ int   g_cur[NEXP];
__device__ int   g_tok[MAXS];
__device__ float g_gate[MAXS];
__device__ int   g_rank[MAXS];
__device__ int   g_toff[2][NEXP+1];
__device__ unsigned int g_ctr[2];

// ---------------- helpers ----------------
__device__ __forceinline__ uint32_t smem_to_u32(const void* p) {
    uint32_t a;
    asm("{ .reg .u64 t; cvta.to.shared.u64 t, %1; cvt.u32.u64 %0, t; }" : "=r"(a) : "l"(p));
    return a;
}
#define CP_ASYNC16(dst, src) \
    asm volatile("cp.async.cg.shared.global [%0], [%1], 16;" :: "r"(dst), "l"(src) : "memory")
#define CP_COMMIT() asm volatile("cp.async.commit_group;" ::: "memory")
#define CP_WAIT(n)  asm volatile("cp.async.wait_group %0;" :: "n"(n) : "memory")

__device__ __forceinline__ float gelu_tanh(float x){
    float x3 = x*x*x;
    return 0.5f*x*(1.0f + tanhf(0.7978845608028654f*(x + 0.044715f*x3)));
}
__device__ __forceinline__ void split_store(__half* ph, __half* pl, size_t o, float v){
    __half hi = __float2half(v);
    ph[o] = hi;
    pl[o] = __float2half(v - __half2float(hi));
}

// ---------------- weight transpose+split: src[K][N] f32 -> dst[N][dstride] fp16 hi(+lo) ----------------
__global__ void k_transpose(const float* __restrict__ src, __half* __restrict__ dh,
                            __half* __restrict__ dl, int K, int N, int dstride, int coloff,
                            long long sBatch, long long dBatch, int writeLo)
{
    __shared__ float t[32][33];
    const int bz = blockIdx.z;
    src += (long long)bz*sBatch;
    dh  += (long long)bz*dBatch;
    if (dl) dl += (long long)bz*dBatch;
    const int k0 = blockIdx.y*32, n0 = blockIdx.x*32;
    const int tx = threadIdx.x, ty = threadIdx.y;
#pragma unroll
    for (int j=0;j<4;j++) t[ty+8*j][tx] = src[(size_t)(k0+ty+8*j)*N + n0+tx];
    __syncthreads();
#pragma unroll
    for (int j=0;j<4;j++){
        float v = t[tx][ty+8*j];
        size_t o = (size_t)(n0+ty+8*j)*dstride + coloff + k0 + tx;
        __half hi = __float2half(v);
        dh[o]=hi;
        if (writeLo) dl[o]=__float2half(v - __half2float(hi));
    }
}

// ---------------- LN1 ----------------
__global__ void k_ln1(const float* __restrict__ x, const float* __restrict__ g1,
                      const float* __restrict__ b1)
{
    const int t = blockIdx.x;
    const int tid = threadIdx.x;
    if (t == 0 && tid < NEXP) g_cnt[tid] = 0;
    __shared__ float red[256];
    const float* xr = x + (size_t)t*CDIM;
    float v[4]; float s = 0.f;
#pragma unroll
    for (int q=0;q<4;q++){ v[q]=xr[tid+256*q]; s+=v[q]; }
    red[tid]=s; __syncthreads();
    for(int st=128;st>0;st>>=1){ if(tid<st) red[tid]+=red[tid+st]; __syncthreads(); }
    const float m = red[0]*(1.0f/CDIM);
    __syncthreads();
    float s2=0.f;
#pragma unroll
    for(int q=0;q<4;q++){ float d=v[q]-m; s2+=d*d; }
    red[tid]=s2; __syncthreads();
    for(int st=128;st>0;st>>=1){ if(tid<st) red[tid]+=red[tid+st]; __syncthreads(); }
    const float rstd = rsqrtf(red[0]*(1.0f/CDIM)+1e-5f);
#pragma unroll
    for(int q=0;q<4;q++){
        int i=tid+256*q;
        float xv=(v[q]-m)*rstd*g1[i]+b1[i];
        split_store(g_xln_h, g_xln_l, (size_t)t*CDIM+i, xv);
    }
}

// ---------------- LN2 + router ----------------
__global__ void k_post1(const float* __restrict__ g2, const float* __restrict__ b2,
                        const float* __restrict__ w_conf, const float* __restrict__ w_diff,
                        const float* __restrict__ W_aff, const float* __restrict__ cap,
                        float* __restrict__ out)
{
    const int t = blockIdx.x;
    const int tid = threadIdx.x;
    __shared__ float red[256];
    __shared__ float sh[CDIM];
    __shared__ float sconf[NEXP], saff[NEXP];
    __shared__ float sdiff;
    const float* xr = g_x2 + (size_t)t*CDIM;
    float v[4]; float s=0.f;
#pragma unroll
    for(int q=0;q<4;q++){ v[q]=xr[tid+256*q]; s+=v[q]; }
    red[tid]=s; __syncthreads();
    for(int st=128;st>0;st>>=1){ if(tid<st) red[tid]+=red[tid+st]; __syncthreads(); }
    const float m=red[0]*(1.0f/CDIM);
    __syncthreads();
    float s2=0.f;
#pragma unroll
    for(int q=0;q<4;q++){ float d=v[q]-m; s2+=d*d; }
    red[tid]=s2; __syncthreads();
    for(int st=128;st>0;st>>=1){ if(tid<st) red[tid]+=red[tid+st]; __syncthreads(); }
    const float rstd=rsqrtf(red[0]*(1.0f/CDIM)+1e-5f);
#pragma unroll
    for(int q=0;q<4;q++){
        int i=tid+256*q;
        float hv=(v[q]-m)*rstd*g2[i]+b2[i];
        sh[i]=hv;
        split_store(g_hr_h, g_hr_l, (size_t)t*2*CDIM+i, hv);
    }
    __syncthreads();
    const int w=tid>>5, lane=tid&31;
    float cd=0.f, ad=0.f, dd=0.f;
    for(int i=lane;i<CDIM;i+=32){
        float hv=sh[i];
        cd = fmaf(hv, w_conf[w*CDIM+i], cd);
        ad = fmaf(hv, W_aff[i*NEXP+w], ad);
        if(w==0) dd = fmaf(hv, w_diff[i], dd);
    }
#pragma unroll
    for(int o=16;o>0;o>>=1){
        cd += __shfl_down_sync(0xffffffffu, cd, o);
        ad += __shfl_down_sync(0xffffffffu, ad, o);
        dd += __shfl_down_sync(0xffffffffu, dd, o);
    }
    if(lane==0){ sconf[w]=cd; saff[w]=ad; if(w==0) sdiff=dd; }
    __syncthreads();
    if(tid<NEXP) out[OUT_AFF + t*NEXP + tid] = saff[tid];
    if(tid==0){
        float diff = fmaxf(sdiff,0.f) + log1pf(expf(-fabsf(sdiff)));
        float b0=-INFINITY, b1v=-INFINITY; int e0=0,e1=0;
#pragma unroll
        for(int e=0;e<NEXP;e++){
            float conf = 1.0f/(1.0f+expf(-sconf[e]));
            float bid = fmaf(conf, cap[e], saff[e]);
            if(bid>b0){ b1v=b0;e1=e0;b0=bid;e0=e; }
            else if(bid>b1v){ b1v=bid;e1=e; }
        }
        float ex = expf(b1v-b0);
        float w0 = 1.0f/(1.0f+ex);
        float w1 = ex/(1.0f+ex);
        out[OUT_WIN + 2*t]   = (float)e0;
        out[OUT_WIN + 2*t+1] = (float)e1;
        out[OUT_COST + t] = (b0*w0 + b1v*w1)*diff;
        out[OUT_DIFF + t] = diff;
        g_win[2*t]=e0; g_win[2*t+1]=e1;
        g_wt[2*t]=w0;  g_wt[2*t+1]=w1;
        atomicAdd(&g_cnt[e0],1);
        atomicAdd(&g_cnt[e1],1);
    }
}

// ---------------- routing setup/fill ----------------
__global__ void k_route_setup(){
    if(threadIdx.x==0){
        int o=0;
        for(int e=0;e<NEXP;e++){ g_off[e]=o; o+=g_cnt[e]; }
        g_off[NEXP]=o;
        int t1=0,t2=0;
        for(int e=0;e<NEXP;e++){
            g_cur[e]=g_off[e];
            int mt=(g_cnt[e]+255)>>8;
            int nt1=(e<ERWKV)?(HDIM>>7):(CDIM>>7);
            g_toff[0][e]=t1; t1+=mt*nt1;
            g_toff[1][e]=t2; t2+=mt*(CDIM>>7);
        }
        g_toff[0][NEXP]=t1; g_toff[1][NEXP]=t2;
        g_ctr[0]=0u; g_ctr[1]=0u;
    }
}
__global__ void k_route_fill(){
    int t = blockIdx.x*blockDim.x + threadIdx.x;
    if(t<BTOK){
#pragma unroll
        for(int r=0;r<2;r++){
            int e=g_win[2*t+r];
            int p=atomicAdd(&g_cur[e],1);
            g_tok[p]=t; g_gate[p]=g_wt[2*t+r]; g_rank[p]=r;
        }
    }
}

// ---------------- async chunk loader ----------------
// PASSES==3: Ah,Al (256 rows each), Bh,Bl (128 rows each) = 768 rows
// PASSES==2: Ah,Al, Bh only = 640 rows
template<int PASSES>
__device__ __forceinline__ void issue_chunk(uint32_t su, const long long* s_aoff,
    const __half* __restrict__ Ah, const __half* __restrict__ Al,
    const __half* __restrict__ Bh, const __half* __restrict__ Bl,
    int K, int nb, int s, int c0)
{
    const int tid = threadIdx.x;
    const uint32_t stage = su + (uint32_t)s*STAGEB;
    const int nrows = (PASSES==3) ? 768 : 640;
#pragma unroll
    for (int j=0; j<3; j++){
        const int r = tid + 256*j;
        if (r >= nrows) break;
        const __half* src;
        uint32_t dst;
        if (r < 512){
            const int arow = r & 255;
            src = ((r<256)? Ah : Al) + s_aoff[arow] + c0;
            dst = stage + (uint32_t)((r<256)? 0 : ABUFE*2) + (uint32_t)arow*144u;
        } else {
            const int brow = (r - 512) & 127;
            src = ((r<640)? Bh : Bl) + (long long)(nb + brow)*K + c0;
            dst = stage + (uint32_t)(2*ABUFE*2) + (uint32_t)((r<640)? 0 : BBUFE*2) + (uint32_t)brow*144u;
        }
#pragma unroll
        for (int i=0;i<8;i++){
            CP_ASYNC16(dst + i*16, src + i*8);
        }
    }
    CP_COMMIT();
}

// ---------------- wmma tile core (256x128 tile, warp 64x64, double-buffered) ----------------
// EPI: 0=X2(residual add, f32), 1=RS(split to hr[:,1024:]), 2=Z(h + D, split),
//      3=MID(activation, split), 4=OUT(gate scatter)
template<int EPI, int PASSES>
__device__ void tc_tile(char* smem, uint32_t su,
    const __half* __restrict__ Ah, const __half* __restrict__ Al,
    int astride, int amode,
    const __half* __restrict__ Bh, const __half* __restrict__ Bl, int K,
    int mb, int nb, int base, int ne, int rwkv,
    const float* __restrict__ xsrc)
{
    const int tid = threadIdx.x;
    __half* sbuf = (__half*)smem;
    long long* s_aoff = (long long*)(smem + SM_AOFF);
    {
        int r = tid;
        long long off;
        if (amode==0)      off = (long long)(mb+r)*astride;
        else if (amode==1){ int row=mb+r; int tk = (row<ne)? g_tok[base+row] : g_tok[base]; off=(long long)tk*astride; }
        else               off = (long long)(base+mb+r)*astride;
        s_aoff[r] = off;
    }
    __syncthreads();

    const int wid = tid>>5;
    const int m0w = (wid&3)*64;        // 4 warps in M (256)
    const int n0w = (wid>>2)*64;       // 2 warps in N (128)

    wmma::fragment<wmma::accumulator,16,16,16,float> acc[4][4];
#pragma unroll
    for (int i=0;i<4;i++)
#pragma unroll
        for (int j=0;j<4;j++) wmma::fill_fragment(acc[i][j], 0.0f);

    const int nch = K >> 6;
    issue_chunk<PASSES>(su, s_aoff, Ah, Al, Bh, Bl, K, nb, 0, 0);

    for (int c=0; c<nch; c++){
        const int s = c & 1;
        if (c+1 < nch){
            issue_chunk<PASSES>(su, s_aoff, Ah, Al, Bh, Bl, K, nb, (c+1)&1, (c+1)<<6);
            CP_WAIT(1);
        } else {
            CP_WAIT(0);
        }
        __syncthreads();

        const __half* sAh = sbuf + (size_t)s*(STAGEB/2);
        const __half* sAl = sAh + ABUFE;
        const __half* sBh = sAh + 2*ABUFE;
        const __half* sBl = sBh + BBUFE;
#pragma unroll
        for (int kk=0; kk<4; kk++){
            const int k0 = kk*16;
            wmma::fragment<wmma::matrix_a,16,16,16,__half,wmma::row_major> a_h[4], a_l[4];
#pragma unroll
            for (int mf=0; mf<4; mf++){
                wmma::load_matrix_sync(a_h[mf], sAh + (m0w+mf*16)*ROWE + k0, ROWE);
                wmma::load_matrix_sync(a_l[mf], sAl + (m0w+mf*16)*ROWE + k0, ROWE);
            }
#pragma unroll
            for (int nf=0; nf<4; nf++){
                wmma::fragment<wmma::matrix_b,16,16,16,__half,wmma::col_major> b_h;
                wmma::load_matrix_sync(b_h, sBh + (n0w+nf*16)*ROWE + k0, ROWE);
                if (PASSES==3){
                    wmma::fragment<wmma::matrix_b,16,16,16,__half,wmma::col_major> b_l;
                    wmma::load_matrix_sync(b_l, sBl + (n0w+nf*16)*ROWE + k0, ROWE);
#pragma unroll
                    for (int mf=0; mf<4; mf++){
                        wmma::mma_sync(acc[mf][nf], a_h[mf], b_h, acc[mf][nf]);
                        wmma::mma_sync(acc[mf][nf], a_h[mf], b_l, acc[mf][nf]);
                        wmma::mma_sync(acc[mf][nf], a_l[mf], b_h, acc[mf][nf]);
                    }
                } else {
#pragma unroll
                    for (int mf=0; mf<4; mf++){
                        wmma::mma_sync(acc[mf][nf], a_h[mf], b_h, acc[mf][nf]);
                        wmma::mma_sync(acc[mf][nf], a_l[mf], b_h, acc[mf][nf]);
                    }
                }
            }
        }
        __syncthreads();
    }

    // epilogue: accum -> padded SMEM (256x132 f32) -> coalesced global
    float* eps = (float*)smem;
#pragma unroll
    for (int mf=0; mf<4; mf++)
#pragma unroll
        for (int nf=0; nf<4; nf++)
            wmma::store_matrix_sync(eps + (size_t)(m0w+mf*16)*132 + n0w + nf*16, acc[mf][nf], 132, wmma::mem_row_major);
    __syncthreads();
    for (int i=tid; i<32768; i+=256){
        const int row = i>>7, col = i&127;
        const float v = eps[(size_t)row*132+col];
        if (EPI==0){
            size_t o = (size_t)(mb+row)*CDIM + nb + col;
            g_x2[o] = xsrc[o] + v;
        } else if (EPI==1){
            size_t o = (size_t)(mb+row)*2*CDIM + CDIM + nb + col;
            split_store(g_hr_h, g_hr_l, o, v);
        } else if (EPI==2){
            size_t ho = (size_t)(mb+row)*2*CDIM + nb + col;
            float hrec = __half2float(g_hr_h[ho]) + __half2float(g_hr_l[ho]);
            split_store(g_z_h, g_z_l, (size_t)(mb+row)*CDIM + nb + col, hrec + v);
        } else if (EPI==3){
            int r2 = mb+row;
            if (r2 < ne){
                float a;
                if (rwkv){ a = fmaxf(v,0.f); a = a*a; }
                else       a = gelu_tanh(v);
                split_store(g_mid_h, g_mid_l, (size_t)(base+r2)*HDIM + nb + col, a);
            }
        } else {
            int r2 = mb+row;
            if (r2 < ne){
                int slot = base + r2;
                int tt = g_tok[slot];
                float gt = g_gate[slot];
                float* dst = g_rank[slot] ? g_slot1 : g_slot0;
                dst[(size_t)tt*CDIM + nb + col] = gt*v;
            }
        }
    }
    __syncthreads();
}

// ---------------- dense GEMM kernels ----------------
template<int EPI, int PASSES>
__global__ __launch_bounds__(256,1) void k_dense(
    const __half* __restrict__ Ah, const __half* __restrict__ Al, int astride,
    const __half* __restrict__ Bh, const __half* __restrict__ Bl, int K,
    const float* __restrict__ xsrc)
{
    extern __shared__ char smem[];
    uint32_t su = smem_to_u32(smem);
    tc_tile<EPI,PASSES>(smem, su, Ah, Al, astride, 0, Bh, Bl, K,
                 blockIdx.y*256, blockIdx.x*128, 0, 1<<30, 0, xsrc);
}

// ---------------- routed persistent grouped GEMM (2-pass fp16) ----------------
template<int STAGE>
__global__ __launch_bounds__(256,1) void k_routed(
    const __half* __restrict__ hr_h, const __half* __restrict__ hr_l,
    const __half* __restrict__ z_h,  const __half* __restrict__ z_l,
    const __half* __restrict__ mid_h,const __half* __restrict__ mid_l,
    const __half* __restrict__ WkT_h,
    const __half* __restrict__ WvT_h,
    const __half* __restrict__ W1T_h,
    const __half* __restrict__ W2T_h)
{
    extern __shared__ char smem[];
    __shared__ int s_idx;
    uint32_t su = smem_to_u32(smem);
    const int total = g_toff[STAGE][NEXP];
    for(;;){
        if (threadIdx.x==0) s_idx = (int)atomicAdd(&g_ctr[STAGE], 1u);
        __syncthreads();
        const int idx = s_idx;
        if (idx >= total) break;
        int e = 0;
#pragma unroll
        for (int q=1;q<NEXP;q++) if (idx >= g_toff[STAGE][q]) e = q;
        const int local = idx - g_toff[STAGE][e];
        const int base = g_off[e];
        const int ne = g_off[e+1]-base;
        const bool rwkv = (e < ERWKV);
        const int ntl = (STAGE==0) ? (rwkv ? (HDIM>>7) : (CDIM>>7)) : (CDIM>>7);
        const int mb = (local/ntl)*256;
        const int nb = (local%ntl)*128;
        if (STAGE==0){
            const __half* Ah = rwkv ? hr_h : z_h;
            const __half* Al = rwkv ? hr_l : z_l;
            const int astride = rwkv ? 2*CDIM : CDIM;
            const __half* Bh = rwkv ? (WkT_h + (size_t)e*HDIM*CDIM) : (W1T_h + (size_t)(e-ERWKV)*CDIM*CDIM);
            tc_tile<3,2>(smem, su, Ah, Al, astride, 1, Bh, nullptr, CDIM,
                       mb, nb, base, ne, rwkv?1:0, nullptr);
        } else {
            const int K = rwkv ? HDIM : CDIM;
            const __half* Bh = rwkv ? (WvT_h + (size_t)e*CDIM*HDIM) : (W2T_h + (size_t)(e-ERWKV)*CDIM*CDIM);
            tc_tile<4,2>(smem, su, mid_h, mid_l, HDIM, 2, Bh, nullptr, K,
                       mb, nb, base, ne, 0, nullptr);
        }
    }
}

// ---------------- epilogue combine ----------------
__global__ void k_final(const float* __restrict__ vf, float* __restrict__ out){
    const int i = blockIdx.x*256 + threadIdx.x;
    out[i]        = g_x2[i] + g_slot0[i] + g_slot1[i];
    out[OUT_VF+i] = vf[i];
}

// ---------------- launch ----------------
extern "C" void kernel_launch(void* const* d_in, const int* in_sizes, int n_in,
                              void* d_out, int out_size)
{
    const float* x     =(const float*)d_in[0];
    const float* vf    =(const float*)d_in[1];
    const float* cap   =(const float*)d_in[2];
    const float* ln1g  =(const float*)d_in[3];
    const float* ln1b  =(const float*)d_in[4];
    const float* ln2g  =(const float*)d_in[5];
    const float* ln2b  =(const float*)d_in[6];
    const float* Wa    =(const float*)d_in[7];
    const float* Ws    =(const float*)d_in[8];
    const float* wconf =(const float*)d_in[9];
    const float* wdiff =(const float*)d_in[10];
    const float* Waff  =(const float*)d_in[11];
    const float* Wbh   =(const float*)d_in[12];
    const float* Wbs   =(const float*)d_in[13];
    const float* Wk    =(const float*)d_in[14];
    const float* Wv    =(const float*)d_in[15];
    const float* W1    =(const float*)d_in[16];
    const float* W2    =(const float*)d_in[17];
    float* out=(float*)d_out;

    // resolve __device__ symbols to REAL device addresses (host-shadow trap on GB300 ATS)
    void *p_xln_h, *p_xln_l, *p_hr_h, *p_hr_l, *p_z_h, *p_z_l, *p_mid_h, *p_mid_l;
    void *p_WaT_h, *p_WaT_l, *p_WsT_h, *p_WbT_h;
    void *p_WkT_h, *p_WvT_h, *p_W1T_h, *p_W2T_h;
    cudaGetSymbolAddress(&p_xln_h, g_xln_h); cudaGetSymbolAddress(&p_xln_l, g_xln_l);
    cudaGetSymbolAddress(&p_hr_h,  g_hr_h);  cudaGetSymbolAddress(&p_hr_l,  g_hr_l);
    cudaGetSymbolAddress(&p_z_h,   g_z_h);   cudaGetSymbolAddress(&p_z_l,   g_z_l);
    cudaGetSymbolAddress(&p_mid_h, g_mid_h); cudaGetSymbolAddress(&p_mid_l, g_mid_l);
    cudaGetSymbolAddress(&p_WaT_h, g_WaT_h); cudaGetSymbolAddress(&p_WaT_l, g_WaT_l);
    cudaGetSymbolAddress(&p_WsT_h, g_WsT_h);
    cudaGetSymbolAddress(&p_WbT_h, g_WbT_h);
    cudaGetSymbolAddress(&p_WkT_h, g_WkT_h);
    cudaGetSymbolAddress(&p_WvT_h, g_WvT_h);
    cudaGetSymbolAddress(&p_W1T_h, g_W1T_h);
    cudaGetSymbolAddress(&p_W2T_h, g_W2T_h);

    cudaFuncSetAttribute((k_dense<0,3>), cudaFuncAttributeMaxDynamicSharedMemorySize, SMEM_BYTES);
    cudaFuncSetAttribute((k_dense<1,2>), cudaFuncAttributeMaxDynamicSharedMemorySize, SMEM_BYTES);
    cudaFuncSetAttribute((k_dense<2,2>), cudaFuncAttributeMaxDynamicSharedMemorySize, SMEM_BYTES);
    cudaFuncSetAttribute(k_routed<0>, cudaFuncAttributeMaxDynamicSharedMemorySize, SMEM_BYTES);
    cudaFuncSetAttribute(k_routed<1>, cudaFuncAttributeMaxDynamicSharedMemorySize, SMEM_BYTES);

    dim3 tb(32,8);
    k_transpose<<<dim3(32,32,1), tb>>>(Wa,  (__half*)p_WaT_h, (__half*)p_WaT_l, CDIM, CDIM, CDIM, 0, 0, 0, 1);
    k_transpose<<<dim3(32,32,1), tb>>>(Ws,  (__half*)p_WsT_h, nullptr, CDIM, CDIM, CDIM, 0, 0, 0, 0);
    k_transpose<<<dim3(32,32,1), tb>>>(Wbh, (__half*)p_WbT_h, nullptr, CDIM, CDIM, 2*CDIM, 0,    0, 0, 0);
    k_transpose<<<dim3(32,32,1), tb>>>(Wbs, (__half*)p_WbT_h, nullptr, CDIM, CDIM, 2*CDIM, CDIM, 0, 0, 0);
    k_transpose<<<dim3(128,32,ERWKV), tb>>>(Wk, (__half*)p_WkT_h, nullptr, CDIM, HDIM, CDIM, 0,
                                            (long long)CDIM*HDIM, (long long)HDIM*CDIM, 0);
    k_transpose<<<dim3(32,128,ERWKV), tb>>>(Wv, (__half*)p_WvT_h, nullptr, HDIM, CDIM, HDIM, 0,
                                            (long long)HDIM*CDIM, (long long)CDIM*HDIM, 0);
    k_transpose<<<dim3(32,32,2), tb>>>(W1, (__half*)p_W1T_h, nullptr, CDIM, CDIM, CDIM, 0,
                                       (long long)CDIM*CDIM, (long long)CDIM*CDIM, 0);
    k_transpose<<<dim3(32,32,2), tb>>>(W2, (__half*)p_W2T_h, nullptr, CDIM, CDIM, CDIM, 0,
                                       (long long)CDIM*CDIM, (long long)CDIM*CDIM, 0);

    k_ln1<<<BTOK,256>>>(x, ln1g, ln1b);

    dim3 gd(CDIM/128, BTOK/256);
    k_dense<0,3><<<gd,256,SMEM_BYTES>>>((__half*)p_xln_h, (__half*)p_xln_l, CDIM,
                                      (__half*)p_WaT_h, (__half*)p_WaT_l, CDIM, x);
    k_dense<1,2><<<gd,256,SMEM_BYTES>>>((__half*)p_xln_h, (__half*)p_xln_l, CDIM,
                                      (__half*)p_WsT_h, nullptr, CDIM, nullptr);

    k_post1<<<BTOK,256>>>(ln2g, ln2b, wconf, wdiff, Waff, cap, out);
    k_route_setup<<<1,32>>>();
    k_route_fill<<<(BTOK+255)/256,256>>>();

    k_dense<2,2><<<gd,256,SMEM_BYTES>>>((__half*)p_hr_h, (__half*)p_hr_l, 2*CDIM,
                                      (__half*)p_WbT_h, nullptr, 2*CDIM, nullptr);

    k_routed<0><<<148,256,SMEM_BYTES>>>((__half*)p_hr_h,(__half*)p_hr_l,
        (__half*)p_z_h,(__half*)p_z_l,(__half*)p_mid_h,(__half*)p_mid_l,
        (__half*)p_WkT_h,(__half*)p_WvT_h,(__half*)p_W1T_h,(__half*)p_W2T_h);
    k_routed<1><<<148,256,SMEM_BYTES>>>((__half*)p_hr_h,(__half*)p_hr_l,
        (__half*)p_z_h,(__half*)p_z_l,(__half*)p_mid_h,(__half*)p_mid_l,
        (__half*)p_WkT_h,(__half*)p_WvT_h,(__half*)p_W1T_h,(__half*)p_W2T_h);

    k_final<<<BTOK*CDIM/256,256>>>(vf, out);
}

// round 11
// speedup vs baseline: 2.3204x; 1.0126x over previous
#include <cuda_runtime.h>
#include <cuda_fp16.h>
#include <mma.h>
#include <math.h>
#include <stdint.h>

using namespace nvcuda;

#define BTOK 4096
#define CDIM 1024
#define HDIM 4096
#define NEXP 8
#define ERWKV 6
#define MAXS (2*BTOK)
#define MIDROWS (MAXS+256)

#define OUT_VF   (BTOK*CDIM)
#define OUT_WIN  (2*BTOK*CDIM)
#define OUT_COST (OUT_WIN + 2*BTOK)
#define OUT_DIFF (OUT_COST + BTOK)
#define OUT_AFF  (OUT_DIFF + BTOK)

// ---------------- SMEM layout ----------------
// stage: Ah(256 rows x 144B), Al(256 x 144B), Bh(64 K-rows x 272B), [Bl(64 x 272B) for 3-pass]
#define ROWE   72                      // A row elements (144B)
#define ABUFE  (256*ROWE)              // 18432 elements per A buffer
#define BBUFB  (64*272)                // 17408 bytes per B buffer
#define STAGEB (4*ABUFE + 2*BBUFB)     // 73728 + 34816 = 108544 bytes
#define SM_AOFF  (2*STAGEB)            // 217088
#define SMEM_BYTES (SM_AOFF + 2048)    // 219136

// ---------------- scratch (static device memory) ----------------
__device__ __half g_xln_h[BTOK*CDIM], g_xln_l[BTOK*CDIM];
__device__ float g_x2[BTOK*CDIM];
__device__ __half g_hr_h[(size_t)BTOK*2*CDIM], g_hr_l[(size_t)BTOK*2*CDIM]; // [tok][0:1024)=h, [1024:2048)=rs
__device__ __half g_z_h[BTOK*CDIM], g_z_l[BTOK*CDIM];
__device__ __half g_mid_h[(size_t)MIDROWS*HDIM], g_mid_l[(size_t)MIDROWS*HDIM];
__device__ float g_slot0[BTOK*CDIM], g_slot1[BTOK*CDIM];

// fp16 weights in ORIGINAL [K][N] layout (no transpose)
__device__ __half g_Wa_h[CDIM*CDIM], g_Wa_l[CDIM*CDIM];
__device__ __half g_Ws_h[CDIM*CDIM];
__device__ __half g_Wb_h[(size_t)2*CDIM*CDIM];             // rows 0-1023 Wbh, 1024-2047 Wbs
__device__ __half g_Wk_h[(size_t)ERWKV*CDIM*HDIM];
__device__ __half g_Wv_h[(size_t)ERWKV*HDIM*CDIM];
__device__ __half g_W1_h[2*CDIM*CDIM];
__device__ __half g_W2_h[2*CDIM*CDIM];

// routing
__device__ int   g_win[2*BTOK];
__device__ float g_wt [2*BTOK];
__device__ int   g_cnt[NEXP];
__device__ int   g_off[NEXP+1];
__device__ int   g_cur[NEXP];
__device__ int   g_tok[MAXS];
__device__ float g_gate[MAXS];
__device__ int   g_rank[MAXS];
__device__ int   g_toff[2][NEXP+1];
__device__ unsigned int g_ctr[2];

// ---------------- helpers ----------------
__device__ __forceinline__ uint32_t smem_to_u32(const void* p) {
    uint32_t a;
    asm("{ .reg .u64 t; cvta.to.shared.u64 t, %1; cvt.u32.u64 %0, t; }" : "=r"(a) : "l"(p));
    return a;
}
#define CP_ASYNC16(dst, src) \
    asm volatile("cp.async.cg.shared.global [%0], [%1], 16;" :: "r"(dst), "l"(src) : "memory")
#define CP_COMMIT() asm volatile("cp.async.commit_group;" ::: "memory")
#define CP_WAIT(n)  asm volatile("cp.async.wait_group %0;" :: "n"(n) : "memory")

__device__ __forceinline__ float gelu_tanh(float x){
    float x3 = x*x*x;
    return 0.5f*x*(1.0f + tanhf(0.7978845608028654f*(x + 0.044715f*x3)));
}
__device__ __forceinline__ void split_store(__half* ph, __half* pl, size_t o, float v){
    __half hi = __float2half(v);
    ph[o] = hi;
    pl[o] = __float2half(v - __half2float(hi));
}

// ---------------- elementwise f32 -> fp16 convert (hi, optional lo) ----------------
__global__ void k_convert(const float* __restrict__ src, __half* __restrict__ dh,
                          __half* __restrict__ dl, long long n)
{
    long long i = ((long long)blockIdx.x*256 + threadIdx.x)*8;
    if (i >= n) return;
    float4 v0 = *(const float4*)(src+i);
    float4 v1 = *(const float4*)(src+i+4);
    __half2 a = __floats2half2_rn(v0.x, v0.y);
    __half2 b = __floats2half2_rn(v0.z, v0.w);
    __half2 c = __floats2half2_rn(v1.x, v1.y);
    __half2 d = __floats2half2_rn(v1.z, v1.w);
    uint4 o;
    o.x = *reinterpret_cast<unsigned*>(&a);
    o.y = *reinterpret_cast<unsigned*>(&b);
    o.z = *reinterpret_cast<unsigned*>(&c);
    o.w = *reinterpret_cast<unsigned*>(&d);
    *(uint4*)(dh+i) = o;
    if (dl){
        __half2 la = __floats2half2_rn(v0.x-__low2float(a), v0.y-__high2float(a));
        __half2 lb = __floats2half2_rn(v0.z-__low2float(b), v0.w-__high2float(b));
        __half2 lc = __floats2half2_rn(v1.x-__low2float(c), v1.y-__high2float(c));
        __half2 ld = __floats2half2_rn(v1.z-__low2float(d), v1.w-__high2float(d));
        uint4 ol;
        ol.x = *reinterpret_cast<unsigned*>(&la);
        ol.y = *reinterpret_cast<unsigned*>(&lb);
        ol.z = *reinterpret_cast<unsigned*>(&lc);
        ol.w = *reinterpret_cast<unsigned*>(&ld);
        *(uint4*)(dl+i) = ol;
    }
}

// ---------------- LN1 ----------------
__global__ void k_ln1(const float* __restrict__ x, const float* __restrict__ g1,
                      const float* __restrict__ b1)
{
    const int t = blockIdx.x;
    const int tid = threadIdx.x;
    if (t == 0 && tid < NEXP) g_cnt[tid] = 0;
    __shared__ float red[256];
    const float* xr = x + (size_t)t*CDIM;
    float v[4]; float s = 0.f;
#pragma unroll
    for (int q=0;q<4;q++){ v[q]=xr[tid+256*q]; s+=v[q]; }
    red[tid]=s; __syncthreads();
    for(int st=128;st>0;st>>=1){ if(tid<st) red[tid]+=red[tid+st]; __syncthreads(); }
    const float m = red[0]*(1.0f/CDIM);
    __syncthreads();
    float s2=0.f;
#pragma unroll
    for(int q=0;q<4;q++){ float d=v[q]-m; s2+=d*d; }
    red[tid]=s2; __syncthreads();
    for(int st=128;st>0;st>>=1){ if(tid<st) red[tid]+=red[tid+st]; __syncthreads(); }
    const float rstd = rsqrtf(red[0]*(1.0f/CDIM)+1e-5f);
#pragma unroll
    for(int q=0;q<4;q++){
        int i=tid+256*q;
        float xv=(v[q]-m)*rstd*g1[i]+b1[i];
        split_store(g_xln_h, g_xln_l, (size_t)t*CDIM+i, xv);
    }
}

// ---------------- LN2 + router ----------------
__global__ void k_post1(const float* __restrict__ g2, const float* __restrict__ b2,
                        const float* __restrict__ w_conf, const float* __restrict__ w_diff,
                        const float* __restrict__ W_aff, const float* __restrict__ cap,
                        float* __restrict__ out)
{
    const int t = blockIdx.x;
    const int tid = threadIdx.x;
    __shared__ float red[256];
    __shared__ float sh[CDIM];
    __shared__ float sconf[NEXP], saff[NEXP];
    __shared__ float sdiff;
    const float* xr = g_x2 + (size_t)t*CDIM;
    float v[4]; float s=0.f;
#pragma unroll
    for(int q=0;q<4;q++){ v[q]=xr[tid+256*q]; s+=v[q]; }
    red[tid]=s; __syncthreads();
    for(int st=128;st>0;st>>=1){ if(tid<st) red[tid]+=red[tid+st]; __syncthreads(); }
    const float m=red[0]*(1.0f/CDIM);
    __syncthreads();
    float s2=0.f;
#pragma unroll
    for(int q=0;q<4;q++){ float d=v[q]-m; s2+=d*d; }
    red[tid]=s2; __syncthreads();
    for(int st=128;st>0;st>>=1){ if(tid<st) red[tid]+=red[tid+st]; __syncthreads(); }
    const float rstd=rsqrtf(red[0]*(1.0f/CDIM)+1e-5f);
#pragma unroll
    for(int q=0;q<4;q++){
        int i=tid+256*q;
        float hv=(v[q]-m)*rstd*g2[i]+b2[i];
        sh[i]=hv;
        split_store(g_hr_h, g_hr_l, (size_t)t*2*CDIM+i, hv);
    }
    __syncthreads();
    const int w=tid>>5, lane=tid&31;
    float cd=0.f, ad=0.f, dd=0.f;
    for(int i=lane;i<CDIM;i+=32){
        float hv=sh[i];
        cd = fmaf(hv, w_conf[w*CDIM+i], cd);
        ad = fmaf(hv, W_aff[i*NEXP+w], ad);
        if(w==0) dd = fmaf(hv, w_diff[i], dd);
    }
#pragma unroll
    for(int o=16;o>0;o>>=1){
        cd += __shfl_down_sync(0xffffffffu, cd, o);
        ad += __shfl_down_sync(0xffffffffu, ad, o);
        dd += __shfl_down_sync(0xffffffffu, dd, o);
    }
    if(lane==0){ sconf[w]=cd; saff[w]=ad; if(w==0) sdiff=dd; }
    __syncthreads();
    if(tid<NEXP) out[OUT_AFF + t*NEXP + tid] = saff[tid];
    if(tid==0){
        float diff = fmaxf(sdiff,0.f) + log1pf(expf(-fabsf(sdiff)));
        float b0=-INFINITY, b1v=-INFINITY; int e0=0,e1=0;
#pragma unroll
        for(int e=0;e<NEXP;e++){
            float conf = 1.0f/(1.0f+expf(-sconf[e]));
            float bid = fmaf(conf, cap[e], saff[e]);
            if(bid>b0){ b1v=b0;e1=e0;b0=bid;e0=e; }
            else if(bid>b1v){ b1v=bid;e1=e; }
        }
        float ex = expf(b1v-b0);
        float w0 = 1.0f/(1.0f+ex);
        float w1 = ex/(1.0f+ex);
        out[OUT_WIN + 2*t]   = (float)e0;
        out[OUT_WIN + 2*t+1] = (float)e1;
        out[OUT_COST + t] = (b0*w0 + b1v*w1)*diff;
        out[OUT_DIFF + t] = diff;
        g_win[2*t]=e0; g_win[2*t+1]=e1;
        g_wt[2*t]=w0;  g_wt[2*t+1]=w1;
        atomicAdd(&g_cnt[e0],1);
        atomicAdd(&g_cnt[e1],1);
    }
}

// ---------------- routing setup/fill ----------------
__global__ void k_route_setup(){
    if(threadIdx.x==0){
        int o=0;
        for(int e=0;e<NEXP;e++){ g_off[e]=o; o+=g_cnt[e]; }
        g_off[NEXP]=o;
        int t1=0,t2=0;
        for(int e=0;e<NEXP;e++){
            g_cur[e]=g_off[e];
            int mt=(g_cnt[e]+255)>>8;
            int nt1=(e<ERWKV)?(HDIM>>7):(CDIM>>7);
            g_toff[0][e]=t1; t1+=mt*nt1;
            g_toff[1][e]=t2; t2+=mt*(CDIM>>7);
        }
        g_toff[0][NEXP]=t1; g_toff[1][NEXP]=t2;
        g_ctr[0]=0u; g_ctr[1]=0u;
    }
}
__global__ void k_route_fill(){
    int t = blockIdx.x*blockDim.x + threadIdx.x;
    if(t<BTOK){
#pragma unroll
        for(int r=0;r<2;r++){
            int e=g_win[2*t+r];
            int p=atomicAdd(&g_cur[e],1);
            g_tok[p]=t; g_gate[p]=g_wt[2*t+r]; g_rank[p]=r;
        }
    }
}

// ---------------- async chunk loader ----------------
// A: 512 rows (Ah 256, Al 256) x 128B.  B: [K][N] layout, 64 K-rows x 256B as 128 half-rows.
// PASSES==3 adds Bl (128 more half-rows).
template<int PASSES>
__device__ __forceinline__ void issue_chunk(uint32_t su, const long long* s_aoff,
    const __half* __restrict__ Ah, const __half* __restrict__ Al,
    const __half* __restrict__ Bh, const __half* __restrict__ Bl,
    int Nstride, int nb, int s, int c0)
{
    const int tid = threadIdx.x;
    const uint32_t stage = su + (uint32_t)s*STAGEB;
    const int nrows = (PASSES==3) ? 768 : 640;
#pragma unroll
    for (int j=0; j<3; j++){
        const int r = tid + 256*j;
        if (r >= nrows) break;
        const __half* src;
        uint32_t dst;
        if (r < 512){
            const int arow = r & 255;
            src = ((r<256)? Ah : Al) + s_aoff[arow] + c0;
            dst = stage + (uint32_t)((r<256)? 0 : 2*ABUFE) + (uint32_t)arow*144u;
        } else {
            const int brow = (r - 512) & 127;
            const int k = brow>>1, hf = brow&1;
            src = ((r<640)? Bh : Bl) + (long long)(c0+k)*Nstride + nb + hf*64;
            dst = stage + (uint32_t)(4*ABUFE) + (uint32_t)((r<640)? 0 : BBUFB)
                  + (uint32_t)(k*272 + hf*128);
        }
#pragma unroll
        for (int i=0;i<8;i++){
            CP_ASYNC16(dst + i*16, src + i*8);
        }
    }
    CP_COMMIT();
}

// ---------------- wmma tile core (256x128 tile, warp 64x64, double-buffered) ----------------
// EPI: 0=X2(residual add, f32), 1=RS(split to hr[:,1024:]), 2=Z(h + D, split),
//      3=MID(activation, split), 4=OUT(gate scatter)
template<int EPI, int PASSES>
__device__ void tc_tile(char* smem, uint32_t su,
    const __half* __restrict__ Ah, const __half* __restrict__ Al,
    int astride, int amode,
    const __half* __restrict__ Bh, const __half* __restrict__ Bl, int K, int Nstride,
    int mb, int nb, int base, int ne, int rwkv,
    const float* __restrict__ xsrc)
{
    const int tid = threadIdx.x;
    __half* sbuf = (__half*)smem;
    long long* s_aoff = (long long*)(smem + SM_AOFF);
    {
        int r = tid;
        long long off;
        if (amode==0)      off = (long long)(mb+r)*astride;
        else if (amode==1){ int row=mb+r; int tk = (row<ne)? g_tok[base+row] : g_tok[base]; off=(long long)tk*astride; }
        else               off = (long long)(base+mb+r)*astride;
        s_aoff[r] = off;
    }
    __syncthreads();

    const int wid = tid>>5;
    const int m0w = (wid&3)*64;        // 4 warps in M (256)
    const int n0w = (wid>>2)*64;       // 2 warps in N (128)

    wmma::fragment<wmma::accumulator,16,16,16,float> acc[4][4];
#pragma unroll
    for (int i=0;i<4;i++)
#pragma unroll
        for (int j=0;j<4;j++) wmma::fill_fragment(acc[i][j], 0.0f);

    const int nch = K >> 6;
    issue_chunk<PASSES>(su, s_aoff, Ah, Al, Bh, Bl, Nstride, nb, 0, 0);

    for (int c=0; c<nch; c++){
        const int s = c & 1;
        if (c+1 < nch){
            issue_chunk<PASSES>(su, s_aoff, Ah, Al, Bh, Bl, Nstride, nb, (c+1)&1, (c+1)<<6);
            CP_WAIT(1);
        } else {
            CP_WAIT(0);
        }
        __syncthreads();

        const __half* sAh = sbuf + (size_t)s*(STAGEB/2);
        const __half* sAl = sAh + ABUFE;
        const __half* sBh = sAh + 2*ABUFE;       // B rows: 136-element stride
        const __half* sBl = sBh + BBUFB/2;
#pragma unroll
        for (int kk=0; kk<4; kk++){
            const int k0 = kk*16;
            wmma::fragment<wmma::matrix_a,16,16,16,__half,wmma::row_major> a_h[4], a_l[4];
#pragma unroll
            for (int mf=0; mf<4; mf++){
                wmma::load_matrix_sync(a_h[mf], sAh + (m0w+mf*16)*ROWE + k0, ROWE);
                wmma::load_matrix_sync(a_l[mf], sAl + (m0w+mf*16)*ROWE + k0, ROWE);
            }
#pragma unroll
            for (int nf=0; nf<4; nf++){
                wmma::fragment<wmma::matrix_b,16,16,16,__half,wmma::row_major> b_h;
                wmma::load_matrix_sync(b_h, sBh + k0*136 + n0w + nf*16, 136);
                if (PASSES==3){
                    wmma::fragment<wmma::matrix_b,16,16,16,__half,wmma::row_major> b_l;
                    wmma::load_matrix_sync(b_l, sBl + k0*136 + n0w + nf*16, 136);
#pragma unroll
                    for (int mf=0; mf<4; mf++){
                        wmma::mma_sync(acc[mf][nf], a_h[mf], b_h, acc[mf][nf]);
                        wmma::mma_sync(acc[mf][nf], a_h[mf], b_l, acc[mf][nf]);
                        wmma::mma_sync(acc[mf][nf], a_l[mf], b_h, acc[mf][nf]);
                    }
                } else {
#pragma unroll
                    for (int mf=0; mf<4; mf++){
                        wmma::mma_sync(acc[mf][nf], a_h[mf], b_h, acc[mf][nf]);
                        wmma::mma_sync(acc[mf][nf], a_l[mf], b_h, acc[mf][nf]);
                    }
                }
            }
        }
        __syncthreads();
    }

    // epilogue: accum -> padded SMEM (256x132 f32) -> coalesced global
    float* eps = (float*)smem;
#pragma unroll
    for (int mf=0; mf<4; mf++)
#pragma unroll
        for (int nf=0; nf<4; nf++)
            wmma::store_matrix_sync(eps + (size_t)(m0w+mf*16)*132 + n0w + nf*16, acc[mf][nf], 132, wmma::mem_row_major);
    __syncthreads();
    for (int i=tid; i<32768; i+=256){
        const int row = i>>7, col = i&127;
        const float v = eps[(size_t)row*132+col];
        if (EPI==0){
            size_t o = (size_t)(mb+row)*CDIM + nb + col;
            g_x2[o] = xsrc[o] + v;
        } else if (EPI==1){
            size_t o = (size_t)(mb+row)*2*CDIM + CDIM + nb + col;
            split_store(g_hr_h, g_hr_l, o, v);
        } else if (EPI==2){
            size_t ho = (size_t)(mb+row)*2*CDIM + nb + col;
            float hrec = __half2float(g_hr_h[ho]) + __half2float(g_hr_l[ho]);
            split_store(g_z_h, g_z_l, (size_t)(mb+row)*CDIM + nb + col, hrec + v);
        } else if (EPI==3){
            int r2 = mb+row;
            if (r2 < ne){
                float a;
                if (rwkv){ a = fmaxf(v,0.f); a = a*a; }
                else       a = gelu_tanh(v);
                split_store(g_mid_h, g_mid_l, (size_t)(base+r2)*HDIM + nb + col, a);
            }
        } else {
            int r2 = mb+row;
            if (r2 < ne){
                int slot = base + r2;
                int tt = g_tok[slot];
                float gt = g_gate[slot];
                float* dst = g_rank[slot] ? g_slot1 : g_slot0;
                dst[(size_t)tt*CDIM + nb + col] = gt*v;
            }
        }
    }
    __syncthreads();
}

// ---------------- dense GEMM kernels ----------------
template<int EPI, int PASSES>
__global__ __launch_bounds__(256,1) void k_dense(
    const __half* __restrict__ Ah, const __half* __restrict__ Al, int astride,
    const __half* __restrict__ Bh, const __half* __restrict__ Bl, int K, int Nstride,
    const float* __restrict__ xsrc)
{
    extern __shared__ char smem[];
    uint32_t su = smem_to_u32(smem);
    tc_tile<EPI,PASSES>(smem, su, Ah, Al, astride, 0, Bh, Bl, K, Nstride,
                 blockIdx.y*256, blockIdx.x*128, 0, 1<<30, 0, xsrc);
}

// ---------------- routed persistent grouped GEMM (2-pass fp16) ----------------
template<int STAGE>
__global__ __launch_bounds__(256,1) void k_routed(
    const __half* __restrict__ hr_h, const __half* __restrict__ hr_l,
    const __half* __restrict__ z_h,  const __half* __restrict__ z_l,
    const __half* __restrict__ mid_h,const __half* __restrict__ mid_l,
    const __half* __restrict__ Wk_h,
    const __half* __restrict__ Wv_h,
    const __half* __restrict__ W1_h,
    const __half* __restrict__ W2_h)
{
    extern __shared__ char smem[];
    __shared__ int s_idx;
    uint32_t su = smem_to_u32(smem);
    const int total = g_toff[STAGE][NEXP];
    for(;;){
        if (threadIdx.x==0) s_idx = (int)atomicAdd(&g_ctr[STAGE], 1u);
        __syncthreads();
        const int idx = s_idx;
        if (idx >= total) break;
        int e = 0;
#pragma unroll
        for (int q=1;q<NEXP;q++) if (idx >= g_toff[STAGE][q]) e = q;
        const int local = idx - g_toff[STAGE][e];
        const int base = g_off[e];
        const int ne = g_off[e+1]-base;
        const bool rwkv = (e < ERWKV);
        const int ntl = (STAGE==0) ? (rwkv ? (HDIM>>7) : (CDIM>>7)) : (CDIM>>7);
        const int mb = (local/ntl)*256;
        const int nb = (local%ntl)*128;
        if (STAGE==0){
            const __half* Ah = rwkv ? hr_h : z_h;
            const __half* Al = rwkv ? hr_l : z_l;
            const int astride = rwkv ? 2*CDIM : CDIM;
            const __half* Bh = rwkv ? (Wk_h + (size_t)e*CDIM*HDIM) : (W1_h + (size_t)(e-ERWKV)*CDIM*CDIM);
            const int Nstride = rwkv ? HDIM : CDIM;
            tc_tile<3,2>(smem, su, Ah, Al, astride, 1, Bh, nullptr, CDIM, Nstride,
                       mb, nb, base, ne, rwkv?1:0, nullptr);
        } else {
            const int K = rwkv ? HDIM : CDIM;
            const __half* Bh = rwkv ? (Wv_h + (size_t)e*HDIM*CDIM) : (W2_h + (size_t)(e-ERWKV)*CDIM*CDIM);
            tc_tile<4,2>(smem, su, mid_h, mid_l, HDIM, 2, Bh, nullptr, K, CDIM,
                       mb, nb, base, ne, 0, nullptr);
        }
    }
}

// ---------------- epilogue combine ----------------
__global__ void k_final(const float* __restrict__ vf, float* __restrict__ out){
    const int i = blockIdx.x*256 + threadIdx.x;
    out[i]        = g_x2[i] + g_slot0[i] + g_slot1[i];
    out[OUT_VF+i] = vf[i];
}

// ---------------- launch ----------------
extern "C" void kernel_launch(void* const* d_in, const int* in_sizes, int n_in,
                              void* d_out, int out_size)
{
    const float* x     =(const float*)d_in[0];
    const float* vf    =(const float*)d_in[1];
    const float* cap   =(const float*)d_in[2];
    const float* ln1g  =(const float*)d_in[3];
    const float* ln1b  =(const float*)d_in[4];
    const float* ln2g  =(const float*)d_in[5];
    const float* ln2b  =(const float*)d_in[6];
    const float* Wa    =(const float*)d_in[7];
    const float* Ws    =(const float*)d_in[8];
    const float* wconf =(const float*)d_in[9];
    const float* wdiff =(const float*)d_in[10];
    const float* Waff  =(const float*)d_in[11];
    const float* Wbh   =(const float*)d_in[12];
    const float* Wbs   =(const float*)d_in[13];
    const float* Wk    =(const float*)d_in[14];
    const float* Wv    =(const float*)d_in[15];
    const float* W1    =(const float*)d_in[16];
    const float* W2    =(const float*)d_in[17];
    float* out=(float*)d_out;

    // resolve __device__ symbols to REAL device addresses (host-shadow trap on GB300 ATS)
    void *p_xln_h, *p_xln_l, *p_hr_h, *p_hr_l, *p_z_h, *p_z_l, *p_mid_h, *p_mid_l;
    void *p_Wa_h, *p_Wa_l, *p_Ws_h, *p_Wb_h;
    void *p_Wk_h, *p_Wv_h, *p_W1_h, *p_W2_h;
    cudaGetSymbolAddress(&p_xln_h, g_xln_h); cudaGetSymbolAddress(&p_xln_l, g_xln_l);
    cudaGetSymbolAddress(&p_hr_h,  g_hr_h);  cudaGetSymbolAddress(&p_hr_l,  g_hr_l);
    cudaGetSymbolAddress(&p_z_h,   g_z_h);   cudaGetSymbolAddress(&p_z_l,   g_z_l);
    cudaGetSymbolAddress(&p_mid_h, g_mid_h); cudaGetSymbolAddress(&p_mid_l, g_mid_l);
    cudaGetSymbolAddress(&p_Wa_h, g_Wa_h);   cudaGetSymbolAddress(&p_Wa_l, g_Wa_l);
    cudaGetSymbolAddress(&p_Ws_h, g_Ws_h);
    cudaGetSymbolAddress(&p_Wb_h, g_Wb_h);
    cudaGetSymbolAddress(&p_Wk_h, g_Wk_h);
    cudaGetSymbolAddress(&p_Wv_h, g_Wv_h);
    cudaGetSymbolAddress(&p_W1_h, g_W1_h);
    cudaGetSymbolAddress(&p_W2_h, g_W2_h);

    cudaFuncSetAttribute((k_dense<0,3>), cudaFuncAttributeMaxDynamicSharedMemorySize, SMEM_BYTES);
    cudaFuncSetAttribute((k_dense<1,2>), cudaFuncAttributeMaxDynamicSharedMemorySize, SMEM_BYTES);
    cudaFuncSetAttribute((k_dense<2,2>), cudaFuncAttributeMaxDynamicSharedMemorySize, SMEM_BYTES);
    cudaFuncSetAttribute(k_routed<0>, cudaFuncAttributeMaxDynamicSharedMemorySize, SMEM_BYTES);
    cudaFuncSetAttribute(k_routed<1>, cudaFuncAttributeMaxDynamicSharedMemorySize, SMEM_BYTES);

    // weight converts (pure elementwise, no transpose)
    const long long nC2  = (long long)CDIM*CDIM;
    const long long nKH  = (long long)ERWKV*CDIM*HDIM;
    auto blocks = [](long long n){ return (unsigned)((n + 2047)/2048); };
    k_convert<<<blocks(nC2),256>>>(Wa,  (__half*)p_Wa_h, (__half*)p_Wa_l, nC2);
    k_convert<<<blocks(nC2),256>>>(Ws,  (__half*)p_Ws_h, nullptr, nC2);
    k_convert<<<blocks(nC2),256>>>(Wbh, (__half*)p_Wb_h, nullptr, nC2);
    k_convert<<<blocks(nC2),256>>>(Wbs, (__half*)p_Wb_h + nC2, nullptr, nC2);
    k_convert<<<blocks(nKH),256>>>(Wk,  (__half*)p_Wk_h, nullptr, nKH);
    k_convert<<<blocks(nKH),256>>>(Wv,  (__half*)p_Wv_h, nullptr, nKH);
    k_convert<<<blocks(2*nC2),256>>>(W1, (__half*)p_W1_h, nullptr, 2*nC2);
    k_convert<<<blocks(2*nC2),256>>>(W2, (__half*)p_W2_h, nullptr, 2*nC2);

    k_ln1<<<BTOK,256>>>(x, ln1g, ln1b);

    dim3 gd(CDIM/128, BTOK/256);
    k_dense<0,3><<<gd,256,SMEM_BYTES>>>((__half*)p_xln_h, (__half*)p_xln_l, CDIM,
                                      (__half*)p_Wa_h, (__half*)p_Wa_l, CDIM, CDIM, x);
    k_dense<1,2><<<gd,256,SMEM_BYTES>>>((__half*)p_xln_h, (__half*)p_xln_l, CDIM,
                                      (__half*)p_Ws_h, nullptr, CDIM, CDIM, nullptr);

    k_post1<<<BTOK,256>>>(ln2g, ln2b, wconf, wdiff, Waff, cap, out);
    k_route_setup<<<1,32>>>();
    k_route_fill<<<(BTOK+255)/256,256>>>();

    k_dense<2,2><<<gd,256,SMEM_BYTES>>>((__half*)p_hr_h, (__half*)p_hr_l, 2*CDIM,
                                      (__half*)p_Wb_h, nullptr, 2*CDIM, CDIM, nullptr);

    k_routed<0><<<148,256,SMEM_BYTES>>>((__half*)p_hr_h,(__half*)p_hr_l,
        (__half*)p_z_h,(__half*)p_z_l,(__half*)p_mid_h,(__half*)p_mid_l,
        (__half*)p_Wk_h,(__half*)p_Wv_h,(__half*)p_W1_h,(__half*)p_W2_h);
    k_routed<1><<<148,256,SMEM_BYTES>>>((__half*)p_hr_h,(__half*)p_hr_l,
        (__half*)p_z_h,(__half*)p_z_l,(__half*)p_mid_h,(__half*)p_mid_l,
        (__half*)p_Wk_h,(__half*)p_Wv_h,(__half*)p_W1_h,(__half*)p_W2_h);

    k_final<<<BTOK*CDIM/256,256>>>(vf, out);
}

// round 12
// speedup vs baseline: 3.4078x; 1.4686x over previous
#include <cuda_runtime.h>
#include <cuda_fp16.h>
#include <mma.h>
#include <math.h>
#include <stdint.h>

using namespace nvcuda;

#define BTOK 4096
#define CDIM 1024
#define HDIM 4096
#define NEXP 8
#define ERWKV 6
#define MAXS (2*BTOK)
#define MIDROWS (MAXS+256)

#define OUT_VF   (BTOK*CDIM)
#define OUT_WIN  (2*BTOK*CDIM)
#define OUT_COST (OUT_WIN + 2*BTOK)
#define OUT_DIFF (OUT_COST + BTOK)
#define OUT_AFF  (OUT_DIFF + BTOK)

// ---------------- SMEM layout ----------------
// stage: Ah(256 rows x 144B), Al(256 x 144B, 3-pass only), Bh(64 K-rows x 272B), Bl(3-pass only)
#define ROWE   72                      // A row elements (144B)
#define ABUFE  (256*ROWE)              // 18432 elements per A buffer
#define BBUFB  (64*272)                // 17408 bytes per B buffer
#define STAGEB (4*ABUFE + 2*BBUFB)     // 108544 bytes
#define SM_AOFF  (2*STAGEB)            // 217088
#define SMEM_BYTES (SM_AOFF + 2048)    // 219136

// ---------------- scratch (static device memory) ----------------
__device__ __half g_xln_h[BTOK*CDIM], g_xln_l[BTOK*CDIM];
__device__ float g_x2[BTOK*CDIM];
__device__ __half g_hr_h[(size_t)BTOK*2*CDIM];   // [tok][0:1024)=h, [1024:2048)=rs (hi only)
__device__ __half g_z_h[BTOK*CDIM];
__device__ __half g_mid_h[(size_t)MIDROWS*HDIM];
__device__ float g_slot0[BTOK*CDIM], g_slot1[BTOK*CDIM];

// fp16 weights in ORIGINAL [K][N] layout (no transpose)
__device__ __half g_Wa_h[CDIM*CDIM], g_Wa_l[CDIM*CDIM];
__device__ __half g_Ws_h[CDIM*CDIM];
__device__ __half g_Wb_h[(size_t)2*CDIM*CDIM];             // rows 0-1023 Wbh, 1024-2047 Wbs
__device__ __half g_Wk_h[(size_t)ERWKV*CDIM*HDIM];
__device__ __half g_Wv_h[(size_t)ERWKV*HDIM*CDIM];
__device__ __half g_W1_h[2*CDIM*CDIM];
__device__ __half g_W2_h[2*CDIM*CDIM];

// routing
__device__ int   g_win[2*BTOK];
__device__ float g_wt [2*BTOK];
__device__ int   g_cnt[NEXP];
__device__ int   g_off[NEXP+1];
__device__ int   g_cur[NEXP];
__device__ int   g_tok[MAXS];
__device__ float g_gate[MAXS];
__device__ int   g_rank[MAXS];
__device__ int   g_toff[2][NEXP+1];
__device__ unsigned int g_ctr[2];

// ---------------- helpers ----------------
__device__ __forceinline__ uint32_t smem_to_u32(const void* p) {
    uint32_t a;
    asm("{ .reg .u64 t; cvta.to.shared.u64 t, %1; cvt.u32.u64 %0, t; }" : "=r"(a) : "l"(p));
    return a;
}
#define CP_ASYNC16(dst, src) \
    asm volatile("cp.async.cg.shared.global [%0], [%1], 16;" :: "r"(dst), "l"(src) : "memory")
#define CP_COMMIT() asm volatile("cp.async.commit_group;" ::: "memory")
#define CP_WAIT(n)  asm volatile("cp.async.wait_group %0;" :: "n"(n) : "memory")

__device__ __forceinline__ float gelu_tanh(float x){
    float x3 = x*x*x;
    return 0.5f*x*(1.0f + tanhf(0.7978845608028654f*(x + 0.044715f*x3)));
}
__device__ __forceinline__ void split_store(__half* ph, __half* pl, size_t o, float v){
    __half hi = __float2half(v);
    ph[o] = hi;
    pl[o] = __float2half(v - __half2float(hi));
}

// ---------------- elementwise f32 -> fp16 convert (hi, optional lo) ----------------
__global__ void k_convert(const float* __restrict__ src, __half* __restrict__ dh,
                          __half* __restrict__ dl, long long n)
{
    long long i = ((long long)blockIdx.x*256 + threadIdx.x)*8;
    if (i >= n) return;
    float4 v0 = *(const float4*)(src+i);
    float4 v1 = *(const float4*)(src+i+4);
    __half2 a = __floats2half2_rn(v0.x, v0.y);
    __half2 b = __floats2half2_rn(v0.z, v0.w);
    __half2 c = __floats2half2_rn(v1.x, v1.y);
    __half2 d = __floats2half2_rn(v1.z, v1.w);
    uint4 o;
    o.x = *reinterpret_cast<unsigned*>(&a);
    o.y = *reinterpret_cast<unsigned*>(&b);
    o.z = *reinterpret_cast<unsigned*>(&c);
    o.w = *reinterpret_cast<unsigned*>(&d);
    *(uint4*)(dh+i) = o;
    if (dl){
        __half2 la = __floats2half2_rn(v0.x-__low2float(a), v0.y-__high2float(a));
        __half2 lb = __floats2half2_rn(v0.z-__low2float(b), v0.w-__high2float(b));
        __half2 lc = __floats2half2_rn(v1.x-__low2float(c), v1.y-__high2float(c));
        __half2 ld = __floats2half2_rn(v1.z-__low2float(d), v1.w-__high2float(d));
        uint4 ol;
        ol.x = *reinterpret_cast<unsigned*>(&la);
        ol.y = *reinterpret_cast<unsigned*>(&lb);
        ol.z = *reinterpret_cast<unsigned*>(&lc);
        ol.w = *reinterpret_cast<unsigned*>(&ld);
        *(uint4*)(dl+i) = ol;
    }
}

// ---------------- LN1 ----------------
__global__ void k_ln1(const float* __restrict__ x, const float* __restrict__ g1,
                      const float* __restrict__ b1)
{
    const int t = blockIdx.x;
    const int tid = threadIdx.x;
    if (t == 0 && tid < NEXP) g_cnt[tid] = 0;
    __shared__ float red[256];
    const float* xr = x + (size_t)t*CDIM;
    float v[4]; float s = 0.f;
#pragma unroll
    for (int q=0;q<4;q++){ v[q]=xr[tid+256*q]; s+=v[q]; }
    red[tid]=s; __syncthreads();
    for(int st=128;st>0;st>>=1){ if(tid<st) red[tid]+=red[tid+st]; __syncthreads(); }
    const float m = red[0]*(1.0f/CDIM);
    __syncthreads();
    float s2=0.f;
#pragma unroll
    for(int q=0;q<4;q++){ float d=v[q]-m; s2+=d*d; }
    red[tid]=s2; __syncthreads();
    for(int st=128;st>0;st>>=1){ if(tid<st) red[tid]+=red[tid+st]; __syncthreads(); }
    const float rstd = rsqrtf(red[0]*(1.0f/CDIM)+1e-5f);
#pragma unroll
    for(int q=0;q<4;q++){
        int i=tid+256*q;
        float xv=(v[q]-m)*rstd*g1[i]+b1[i];
        split_store(g_xln_h, g_xln_l, (size_t)t*CDIM+i, xv);
    }
}

// ---------------- LN2 + router (h stored hi-only) ----------------
__global__ void k_post1(const float* __restrict__ g2, const float* __restrict__ b2,
                        const float* __restrict__ w_conf, const float* __restrict__ w_diff,
                        const float* __restrict__ W_aff, const float* __restrict__ cap,
                        float* __restrict__ out)
{
    const int t = blockIdx.x;
    const int tid = threadIdx.x;
    __shared__ float red[256];
    __shared__ float sh[CDIM];
    __shared__ float sconf[NEXP], saff[NEXP];
    __shared__ float sdiff;
    const float* xr = g_x2 + (size_t)t*CDIM;
    float v[4]; float s=0.f;
#pragma unroll
    for(int q=0;q<4;q++){ v[q]=xr[tid+256*q]; s+=v[q]; }
    red[tid]=s; __syncthreads();
    for(int st=128;st>0;st>>=1){ if(tid<st) red[tid]+=red[tid+st]; __syncthreads(); }
    const float m=red[0]*(1.0f/CDIM);
    __syncthreads();
    float s2=0.f;
#pragma unroll
    for(int q=0;q<4;q++){ float d=v[q]-m; s2+=d*d; }
    red[tid]=s2; __syncthreads();
    for(int st=128;st>0;st>>=1){ if(tid<st) red[tid]+=red[tid+st]; __syncthreads(); }
    const float rstd=rsqrtf(red[0]*(1.0f/CDIM)+1e-5f);
#pragma unroll
    for(int q=0;q<4;q++){
        int i=tid+256*q;
        float hv=(v[q]-m)*rstd*g2[i]+b2[i];
        sh[i]=hv;
        g_hr_h[(size_t)t*2*CDIM+i] = __float2half(hv);
    }
    __syncthreads();
    const int w=tid>>5, lane=tid&31;
    float cd=0.f, ad=0.f, dd=0.f;
    for(int i=lane;i<CDIM;i+=32){
        float hv=sh[i];
        cd = fmaf(hv, w_conf[w*CDIM+i], cd);
        ad = fmaf(hv, W_aff[i*NEXP+w], ad);
        if(w==0) dd = fmaf(hv, w_diff[i], dd);
    }
#pragma unroll
    for(int o=16;o>0;o>>=1){
        cd += __shfl_down_sync(0xffffffffu, cd, o);
        ad += __shfl_down_sync(0xffffffffu, ad, o);
        dd += __shfl_down_sync(0xffffffffu, dd, o);
    }
    if(lane==0){ sconf[w]=cd; saff[w]=ad; if(w==0) sdiff=dd; }
    __syncthreads();
    if(tid<NEXP) out[OUT_AFF + t*NEXP + tid] = saff[tid];
    if(tid==0){
        float diff = fmaxf(sdiff,0.f) + log1pf(expf(-fabsf(sdiff)));
        float b0=-INFINITY, b1v=-INFINITY; int e0=0,e1=0;
#pragma unroll
        for(int e=0;e<NEXP;e++){
            float conf = 1.0f/(1.0f+expf(-sconf[e]));
            float bid = fmaf(conf, cap[e], saff[e]);
            if(bid>b0){ b1v=b0;e1=e0;b0=bid;e0=e; }
            else if(bid>b1v){ b1v=bid;e1=e; }
        }
        float ex = expf(b1v-b0);
        float w0 = 1.0f/(1.0f+ex);
        float w1 = ex/(1.0f+ex);
        out[OUT_WIN + 2*t]   = (float)e0;
        out[OUT_WIN + 2*t+1] = (float)e1;
        out[OUT_COST + t] = (b0*w0 + b1v*w1)*diff;
        out[OUT_DIFF + t] = diff;
        g_win[2*t]=e0; g_win[2*t+1]=e1;
        g_wt[2*t]=w0;  g_wt[2*t+1]=w1;
        atomicAdd(&g_cnt[e0],1);
        atomicAdd(&g_cnt[e1],1);
    }
}

// ---------------- routing setup/fill ----------------
__global__ void k_route_setup(){
    if(threadIdx.x==0){
        int o=0;
        for(int e=0;e<NEXP;e++){ g_off[e]=o; o+=g_cnt[e]; }
        g_off[NEXP]=o;
        int t1=0,t2=0;
        for(int e=0;e<NEXP;e++){
            g_cur[e]=g_off[e];
            int mt=(g_cnt[e]+255)>>8;
            int nt1=(e<ERWKV)?(HDIM>>7):(CDIM>>7);
            g_toff[0][e]=t1; t1+=mt*nt1;
            g_toff[1][e]=t2; t2+=mt*(CDIM>>7);
        }
        g_toff[0][NEXP]=t1; g_toff[1][NEXP]=t2;
        g_ctr[0]=0u; g_ctr[1]=0u;
    }
}
__global__ void k_route_fill(){
    int t = blockIdx.x*blockDim.x + threadIdx.x;
    if(t<BTOK){
#pragma unroll
        for(int r=0;r<2;r++){
            int e=g_win[2*t+r];
            int p=atomicAdd(&g_cur[e],1);
            g_tok[p]=t; g_gate[p]=g_wt[2*t+r]; g_rank[p]=r;
        }
    }
}

// ---------------- async chunk loader ----------------
// Layout (bytes from stage base): Ah@0, Al@2*ABUFE, Bh@4*ABUFE, Bl@4*ABUFE+BBUFB
// PASSES==3: rows [0,256)Ah [256,512)Al [512,640)Bh [640,768)Bl
// PASSES==1: rows [0,256)Ah [256,384)Bh
template<int PASSES>
__device__ __forceinline__ void issue_chunk(uint32_t su, const long long* s_aoff,
    const __half* __restrict__ Ah, const __half* __restrict__ Al,
    const __half* __restrict__ Bh, const __half* __restrict__ Bl,
    int Nstride, int nb, int s, int c0)
{
    const int tid = threadIdx.x;
    const uint32_t stage = su + (uint32_t)s*STAGEB;
    const int nrows = (PASSES==3) ? 768 : 384;
    const int bstart = (PASSES==3) ? 512 : 256;
#pragma unroll
    for (int j=0; j<3; j++){
        const int r = tid + 256*j;
        if (r >= nrows) break;
        const __half* src;
        uint32_t dst;
        if (r < 256){
            src = Ah + s_aoff[r] + c0;
            dst = stage + (uint32_t)r*144u;
        } else if (PASSES==3 && r < 512){
            const int arow = r & 255;
            src = Al + s_aoff[arow] + c0;
            dst = stage + (uint32_t)(2*ABUFE) + (uint32_t)arow*144u;
        } else {
            const int br = r - bstart;             // 0..255 (3-pass) or 0..127 (1-pass)
            const int brow = br & 127;
            const int k = brow>>1, hf = brow&1;
            const bool isBl = (PASSES==3) && (br >= 128);
            src = (isBl? Bl : Bh) + (long long)(c0+k)*Nstride + nb + hf*64;
            dst = stage + (uint32_t)(4*ABUFE) + (isBl? (uint32_t)BBUFB : 0u)
                  + (uint32_t)(k*272 + hf*128);
        }
#pragma unroll
        for (int i=0;i<8;i++){
            CP_ASYNC16(dst + i*16, src + i*8);
        }
    }
    CP_COMMIT();
}

// ---------------- wmma tile core (256x128 tile, warp 64x64, double-buffered) ----------------
// EPI: 0=X2(residual add, f32), 1=RS(hi to hr[:,1024:]), 2=Z(h + D, hi), 3=MID(activation, hi), 4=OUT(gate scatter)
template<int EPI, int PASSES>
__device__ void tc_tile(char* smem, uint32_t su,
    const __half* __restrict__ Ah, const __half* __restrict__ Al,
    int astride, int amode,
    const __half* __restrict__ Bh, const __half* __restrict__ Bl, int K, int Nstride,
    int mb, int nb, int base, int ne, int rwkv,
    const float* __restrict__ xsrc)
{
    const int tid = threadIdx.x;
    __half* sbuf = (__half*)smem;
    long long* s_aoff = (long long*)(smem + SM_AOFF);
    {
        int r = tid;
        long long off;
        if (amode==0)      off = (long long)(mb+r)*astride;
        else if (amode==1){ int row=mb+r; int tk = (row<ne)? g_tok[base+row] : g_tok[base]; off=(long long)tk*astride; }
        else               off = (long long)(base+mb+r)*astride;
        s_aoff[r] = off;
    }
    __syncthreads();

    const int wid = tid>>5;
    const int m0w = (wid&3)*64;        // 4 warps in M (256)
    const int n0w = (wid>>2)*64;       // 2 warps in N (128)

    wmma::fragment<wmma::accumulator,16,16,16,float> acc[4][4];
#pragma unroll
    for (int i=0;i<4;i++)
#pragma unroll
        for (int j=0;j<4;j++) wmma::fill_fragment(acc[i][j], 0.0f);

    const int nch = K >> 6;
    issue_chunk<PASSES>(su, s_aoff, Ah, Al, Bh, Bl, Nstride, nb, 0, 0);

    for (int c=0; c<nch; c++){
        const int s = c & 1;
        if (c+1 < nch){
            issue_chunk<PASSES>(su, s_aoff, Ah, Al, Bh, Bl, Nstride, nb, (c+1)&1, (c+1)<<6);
            CP_WAIT(1);
        } else {
            CP_WAIT(0);
        }
        __syncthreads();

        const __half* sAh = sbuf + (size_t)s*(STAGEB/2);
        const __half* sAl = sAh + ABUFE;
        const __half* sBh = sAh + 2*ABUFE;       // B rows: 136-element stride
        const __half* sBl = sBh + BBUFB/2;
#pragma unroll
        for (int kk=0; kk<4; kk++){
            const int k0 = kk*16;
            wmma::fragment<wmma::matrix_a,16,16,16,__half,wmma::row_major> a_h[4], a_l[4];
#pragma unroll
            for (int mf=0; mf<4; mf++){
                wmma::load_matrix_sync(a_h[mf], sAh + (m0w+mf*16)*ROWE + k0, ROWE);
                if (PASSES==3)
                    wmma::load_matrix_sync(a_l[mf], sAl + (m0w+mf*16)*ROWE + k0, ROWE);
            }
#pragma unroll
            for (int nf=0; nf<4; nf++){
                wmma::fragment<wmma::matrix_b,16,16,16,__half,wmma::row_major> b_h;
                wmma::load_matrix_sync(b_h, sBh + k0*136 + n0w + nf*16, 136);
                if (PASSES==3){
                    wmma::fragment<wmma::matrix_b,16,16,16,__half,wmma::row_major> b_l;
                    wmma::load_matrix_sync(b_l, sBl + k0*136 + n0w + nf*16, 136);
#pragma unroll
                    for (int mf=0; mf<4; mf++){
                        wmma::mma_sync(acc[mf][nf], a_h[mf], b_h, acc[mf][nf]);
                        wmma::mma_sync(acc[mf][nf], a_h[mf], b_l, acc[mf][nf]);
                        wmma::mma_sync(acc[mf][nf], a_l[mf], b_h, acc[mf][nf]);
                    }
                } else {
#pragma unroll
                    for (int mf=0; mf<4; mf++){
                        wmma::mma_sync(acc[mf][nf], a_h[mf], b_h, acc[mf][nf]);
                    }
                }
            }
        }
        __syncthreads();
    }

    // epilogue: accum -> padded SMEM (256x132 f32) -> coalesced global
    float* eps = (float*)smem;
#pragma unroll
    for (int mf=0; mf<4; mf++)
#pragma unroll
        for (int nf=0; nf<4; nf++)
            wmma::store_matrix_sync(eps + (size_t)(m0w+mf*16)*132 + n0w + nf*16, acc[mf][nf], 132, wmma::mem_row_major);
    __syncthreads();
    for (int i=tid; i<32768; i+=256){
        const int row = i>>7, col = i&127;
        const float v = eps[(size_t)row*132+col];
        if (EPI==0){
            size_t o = (size_t)(mb+row)*CDIM + nb + col;
            g_x2[o] = xsrc[o] + v;
        } else if (EPI==1){
            size_t o = (size_t)(mb+row)*2*CDIM + CDIM + nb + col;
            g_hr_h[o] = __float2half(v);
        } else if (EPI==2){
            size_t ho = (size_t)(mb+row)*2*CDIM + nb + col;
            float hrec = __half2float(g_hr_h[ho]);
            g_z_h[(size_t)(mb+row)*CDIM + nb + col] = __float2half(hrec + v);
        } else if (EPI==3){
            int r2 = mb+row;
            if (r2 < ne){
                float a;
                if (rwkv){ a = fmaxf(v,0.f); a = a*a; }
                else       a = gelu_tanh(v);
                g_mid_h[(size_t)(base+r2)*HDIM + nb + col] = __float2half(a);
            }
        } else {
            int r2 = mb+row;
            if (r2 < ne){
                int slot = base + r2;
                int tt = g_tok[slot];
                float gt = g_gate[slot];
                float* dst = g_rank[slot] ? g_slot1 : g_slot0;
                dst[(size_t)tt*CDIM + nb + col] = gt*v;
            }
        }
    }
    __syncthreads();
}

// ---------------- dense GEMM kernels ----------------
template<int EPI, int PASSES>
__global__ __launch_bounds__(256,1) void k_dense(
    const __half* __restrict__ Ah, const __half* __restrict__ Al, int astride,
    const __half* __restrict__ Bh, const __half* __restrict__ Bl, int K, int Nstride,
    const float* __restrict__ xsrc)
{
    extern __shared__ char smem[];
    uint32_t su = smem_to_u32(smem);
    tc_tile<EPI,PASSES>(smem, su, Ah, Al, astride, 0, Bh, Bl, K, Nstride,
                 blockIdx.y*256, blockIdx.x*128, 0, 1<<30, 0, xsrc);
}

// ---------------- routed persistent grouped GEMM (1-pass fp16) ----------------
template<int STAGE>
__global__ __launch_bounds__(256,1) void k_routed(
    const __half* __restrict__ hr_h,
    const __half* __restrict__ z_h,
    const __half* __restrict__ mid_h,
    const __half* __restrict__ Wk_h,
    const __half* __restrict__ Wv_h,
    const __half* __restrict__ W1_h,
    const __half* __restrict__ W2_h)
{
    extern __shared__ char smem[];
    __shared__ int s_idx;
    uint32_t su = smem_to_u32(smem);
    const int total = g_toff[STAGE][NEXP];
    for(;;){
        if (threadIdx.x==0) s_idx = (int)atomicAdd(&g_ctr[STAGE], 1u);
        __syncthreads();
        const int idx = s_idx;
        if (idx >= total) break;
        int e = 0;
#pragma unroll
        for (int q=1;q<NEXP;q++) if (idx >= g_toff[STAGE][q]) e = q;
        const int local = idx - g_toff[STAGE][e];
        const int base = g_off[e];
        const int ne = g_off[e+1]-base;
        const bool rwkv = (e < ERWKV);
        const int ntl = (STAGE==0) ? (rwkv ? (HDIM>>7) : (CDIM>>7)) : (CDIM>>7);
        const int mb = (local/ntl)*256;
        const int nb = (local%ntl)*128;
        if (STAGE==0){
            const __half* Ah = rwkv ? hr_h : z_h;
            const int astride = rwkv ? 2*CDIM : CDIM;
            const __half* Bh = rwkv ? (Wk_h + (size_t)e*CDIM*HDIM) : (W1_h + (size_t)(e-ERWKV)*CDIM*CDIM);
            const int Nstride = rwkv ? HDIM : CDIM;
            tc_tile<3,1>(smem, su, Ah, nullptr, astride, 1, Bh, nullptr, CDIM, Nstride,
                       mb, nb, base, ne, rwkv?1:0, nullptr);
        } else {
            const int K = rwkv ? HDIM : CDIM;
            const __half* Bh = rwkv ? (Wv_h + (size_t)e*HDIM*CDIM) : (W2_h + (size_t)(e-ERWKV)*CDIM*CDIM);
            tc_tile<4,1>(smem, su, mid_h, nullptr, HDIM, 2, Bh, nullptr, K, CDIM,
                       mb, nb, base, ne, 0, nullptr);
        }
    }
}

// ---------------- epilogue combine ----------------
__global__ void k_final(const float* __restrict__ vf, float* __restrict__ out){
    const int i = blockIdx.x*256 + threadIdx.x;
    out[i]        = g_x2[i] + g_slot0[i] + g_slot1[i];
    out[OUT_VF+i] = vf[i];
}

// ---------------- launch ----------------
extern "C" void kernel_launch(void* const* d_in, const int* in_sizes, int n_in,
                              void* d_out, int out_size)
{
    const float* x     =(const float*)d_in[0];
    const float* vf    =(const float*)d_in[1];
    const float* cap   =(const float*)d_in[2];
    const float* ln1g  =(const float*)d_in[3];
    const float* ln1b  =(const float*)d_in[4];
    const float* ln2g  =(const float*)d_in[5];
    const float* ln2b  =(const float*)d_in[6];
    const float* Wa    =(const float*)d_in[7];
    const float* Ws    =(const float*)d_in[8];
    const float* wconf =(const float*)d_in[9];
    const float* wdiff =(const float*)d_in[10];
    const float* Waff  =(const float*)d_in[11];
    const float* Wbh   =(const float*)d_in[12];
    const float* Wbs   =(const float*)d_in[13];
    const float* Wk    =(const float*)d_in[14];
    const float* Wv    =(const float*)d_in[15];
    const float* W1    =(const float*)d_in[16];
    const float* W2    =(const float*)d_in[17];
    float* out=(float*)d_out;

    // resolve __device__ symbols to REAL device addresses (host-shadow trap on GB300 ATS)
    void *p_xln_h, *p_xln_l, *p_hr_h, *p_z_h, *p_mid_h;
    void *p_Wa_h, *p_Wa_l, *p_Ws_h, *p_Wb_h;
    void *p_Wk_h, *p_Wv_h, *p_W1_h, *p_W2_h;
    cudaGetSymbolAddress(&p_xln_h, g_xln_h); cudaGetSymbolAddress(&p_xln_l, g_xln_l);
    cudaGetSymbolAddress(&p_hr_h,  g_hr_h);
    cudaGetSymbolAddress(&p_z_h,   g_z_h);
    cudaGetSymbolAddress(&p_mid_h, g_mid_h);
    cudaGetSymbolAddress(&p_Wa_h, g_Wa_h);   cudaGetSymbolAddress(&p_Wa_l, g_Wa_l);
    cudaGetSymbolAddress(&p_Ws_h, g_Ws_h);
    cudaGetSymbolAddress(&p_Wb_h, g_Wb_h);
    cudaGetSymbolAddress(&p_Wk_h, g_Wk_h);
    cudaGetSymbolAddress(&p_Wv_h, g_Wv_h);
    cudaGetSymbolAddress(&p_W1_h, g_W1_h);
    cudaGetSymbolAddress(&p_W2_h, g_W2_h);

    cudaFuncSetAttribute((k_dense<0,3>), cudaFuncAttributeMaxDynamicSharedMemorySize, SMEM_BYTES);
    cudaFuncSetAttribute((k_dense<1,1>), cudaFuncAttributeMaxDynamicSharedMemorySize, SMEM_BYTES);
    cudaFuncSetAttribute((k_dense<2,1>), cudaFuncAttributeMaxDynamicSharedMemorySize, SMEM_BYTES);
    cudaFuncSetAttribute(k_routed<0>, cudaFuncAttributeMaxDynamicSharedMemorySize, SMEM_BYTES);
    cudaFuncSetAttribute(k_routed<1>, cudaFuncAttributeMaxDynamicSharedMemorySize, SMEM_BYTES);

    // weight converts (pure elementwise, no transpose)
    const long long nC2  = (long long)CDIM*CDIM;
    const long long nKH  = (long long)ERWKV*CDIM*HDIM;
    auto blocks = [](long long n){ return (unsigned)((n + 2047)/2048); };
    k_convert<<<blocks(nC2),256>>>(Wa,  (__half*)p_Wa_h, (__half*)p_Wa_l, nC2);
    k_convert<<<blocks(nC2),256>>>(Ws,  (__half*)p_Ws_h, nullptr, nC2);
    k_convert<<<blocks(nC2),256>>>(Wbh, (__half*)p_Wb_h, nullptr, nC2);
    k_convert<<<blocks(nC2),256>>>(Wbs, (__half*)p_Wb_h + nC2, nullptr, nC2);
    k_convert<<<blocks(nKH),256>>>(Wk,  (__half*)p_Wk_h, nullptr, nKH);
    k_convert<<<blocks(nKH),256>>>(Wv,  (__half*)p_Wv_h, nullptr, nKH);
    k_convert<<<blocks(2*nC2),256>>>(W1, (__half*)p_W1_h, nullptr, 2*nC2);
    k_convert<<<blocks(2*nC2),256>>>(W2, (__half*)p_W2_h, nullptr, 2*nC2);

    k_ln1<<<BTOK,256>>>(x, ln1g, ln1b);

    dim3 gd(CDIM/128, BTOK/256);
    k_dense<0,3><<<gd,256,SMEM_BYTES>>>((__half*)p_xln_h, (__half*)p_xln_l, CDIM,
                                      (__half*)p_Wa_h, (__half*)p_Wa_l, CDIM, CDIM, x);
    k_dense<1,1><<<gd,256,SMEM_BYTES>>>((__half*)p_xln_h, nullptr, CDIM,
                                      (__half*)p_Ws_h, nullptr, CDIM, CDIM, nullptr);

    k_post1<<<BTOK,256>>>(ln2g, ln2b, wconf, wdiff, Waff, cap, out);
    k_route_setup<<<1,32>>>();
    k_route_fill<<<(BTOK+255)/256,256>>>();

    k_dense<2,1><<<gd,256,SMEM_BYTES>>>((__half*)p_hr_h, nullptr, 2*CDIM,
                                      (__half*)p_Wb_h, nullptr, 2*CDIM, CDIM, nullptr);

    k_routed<0><<<148,256,SMEM_BYTES>>>((__half*)p_hr_h, (__half*)p_z_h, (__half*)p_mid_h,
        (__half*)p_Wk_h,(__half*)p_Wv_h,(__half*)p_W1_h,(__half*)p_W2_h);
    k_routed<1><<<148,256,SMEM_BYTES>>>((__half*)p_hr_h, (__half*)p_z_h, (__half*)p_mid_h,
        (__half*)p_Wk_h,(__half*)p_Wv_h,(__half*)p_W1_h,(__half*)p_W2_h);

    k_final<<<BTOK*CDIM/256,256>>>(vf, out);
}